// round 10
// baseline (speedup 1.0000x reference)
#include <cuda_runtime.h>
#include <cuda_bf16.h>
#include <math.h>
#include <stdint.h>

#define BN   256
#define PN   32768
#define DN   256
#define CN   8
#define KSCALE 20.0f
#define BGK  50
#define PKK  3
#define BALW 0.15f
#define CAP  768

#define NEG_INF (__int_as_float(0xff800000))

// ---------------- scratch ----------------
__device__ int   g_pseudo[BN];
__device__ __nv_bfloat16 g_Ahi[2 * BN * DN];   // rows 0..255 features, 256..511 blended
__device__ __nv_bfloat16 g_Alo[2 * BN * DN];
__device__ __nv_bfloat16 g_Bhi[(size_t)PN * DN];
__device__ __nv_bfloat16 g_Blo[(size_t)PN * DN];
// A in mma fragment layout: [rb(32)][ks16(16)][lane(32)] uint4
__device__ uint4 g_AfragHi[32 * 16 * 32];
__device__ uint4 g_AfragLo[32 * 16 * 32];
__device__ float g_score[(size_t)BN * PN];
__device__ float g_sims [(size_t)BN * PN];
__device__ float g_loss[3 * BN];

// ---------------- PTX helpers ----------------
__device__ __forceinline__ uint32_t smem_u32(const void* p) {
    uint32_t a;
    asm("{ .reg .u64 t; cvta.to.shared.u64 t, %1; cvt.u32.u64 %0, t; }" : "=r"(a) : "l"(p));
    return a;
}
#define SW128(off) ((off) ^ (((off) >> 3) & 0x70))
__device__ __forceinline__ void cp16(uint32_t dst, const void* src) {
    asm volatile("cp.async.cg.shared.global [%0], [%1], 16;" :: "r"(dst), "l"(src));
}
__device__ __forceinline__ void cp_commit() { asm volatile("cp.async.commit_group;"); }
template <int N>
__device__ __forceinline__ void cp_wait() { asm volatile("cp.async.wait_group %0;" :: "n"(N)); }

__device__ __forceinline__ void ldsm_x4(uint32_t addr, uint32_t& r0, uint32_t& r1,
                                        uint32_t& r2, uint32_t& r3) {
    asm volatile("ldmatrix.sync.aligned.m8n8.x4.shared.b16 {%0,%1,%2,%3}, [%4];"
        : "=r"(r0), "=r"(r1), "=r"(r2), "=r"(r3) : "r"(addr));
}
__device__ __forceinline__ void mma_bf16(float& c0, float& c1, float& c2, float& c3,
                                         uint32_t a0, uint32_t a1, uint32_t a2, uint32_t a3,
                                         uint32_t b0, uint32_t b1) {
    asm volatile("mma.sync.aligned.m16n8k16.row.col.f32.bf16.bf16.f32 "
        "{%0,%1,%2,%3}, {%4,%5,%6,%7}, {%8,%9}, {%0,%1,%2,%3};"
        : "+f"(c0), "+f"(c1), "+f"(c2), "+f"(c3)
        : "r"(a0), "r"(a1), "r"(a2), "r"(a3), "r"(b0), "r"(b1));
}

// ---------------- selection helpers ----------------
__device__ __forceinline__ unsigned fkey(float v) {
    unsigned u = __float_as_uint(v);
    return (u & 0x80000000u) ? ~u : (u | 0x80000000u);
}
__device__ __forceinline__ float unfkey(unsigned k) {
    unsigned u = (k & 0x80000000u) ? (k ^ 0x80000000u) : ~k;
    return __uint_as_float(u);
}
__device__ __forceinline__ float blockMaxF(float x, float* s16, int t) {
    int lane = t & 31, wid = t >> 5;
    for (int o = 16; o > 0; o >>= 1) x = fmaxf(x, __shfl_xor_sync(0xffffffffu, x, o));
    __syncthreads();
    if (lane == 0) s16[wid] = x;
    __syncthreads();
    if (t == 0) { float y = s16[0]; for (int w = 1; w < 16; w++) y = fmaxf(y, s16[w]); s16[0] = y; }
    __syncthreads();
    return s16[0];
}
__device__ __forceinline__ float blockSumF(float x, float* s16, int t) {
    int lane = t & 31, wid = t >> 5;
    for (int o = 16; o > 0; o >>= 1) x += __shfl_xor_sync(0xffffffffu, x, o);
    __syncthreads();
    if (lane == 0) s16[wid] = x;
    __syncthreads();
    if (t == 0) { float y = 0.f; for (int w = 0; w < 16; w++) y += s16[w]; s16[0] = y; }
    __syncthreads();
    return s16[0];
}
__device__ __forceinline__ int blockSumI(int x, int* s16, int t) {
    int lane = t & 31, wid = t >> 5;
    for (int o = 16; o > 0; o >>= 1) x += __shfl_xor_sync(0xffffffffu, x, o);
    __syncthreads();
    if (lane == 0) s16[wid] = x;
    __syncthreads();
    if (t == 0) { int y = 0; for (int w = 0; w < 16; w++) y += s16[w]; s16[0] = y; }
    __syncthreads();
    return s16[0];
}

// ---------------- K1: merged prep (A blend + hi/lo) and B conversion -------
__global__ __launch_bounds__(256) void k_prep(const float* __restrict__ features,
                                              const int* __restrict__ targets,
                                              const int* __restrict__ all_proxy_label,
                                              const float* __restrict__ mem) {
    int blk = blockIdx.x;
    int t = threadIdx.x;
    if (blk < 1024) {
        size_t base = (size_t)blk * 8192;
#pragma unroll
        for (int i = 0; i < 8; i++) {
            size_t off = base + (size_t)i * 1024 + t * 4;
            float4 f = *(const float4*)(mem + off);
            __nv_bfloat162 h01 = __floats2bfloat162_rn(f.x, f.y);
            __nv_bfloat162 h23 = __floats2bfloat162_rn(f.z, f.w);
            float lx = f.x - __bfloat162float(__low2bfloat16(h01));
            float ly = f.y - __bfloat162float(__high2bfloat16(h01));
            float lz = f.z - __bfloat162float(__low2bfloat16(h23));
            float lw = f.w - __bfloat162float(__high2bfloat16(h23));
            __nv_bfloat162 l01 = __floats2bfloat162_rn(lx, ly);
            __nv_bfloat162 l23 = __floats2bfloat162_rn(lz, lw);
            ((__nv_bfloat162*)(g_Bhi + off))[0] = h01;
            ((__nv_bfloat162*)(g_Bhi + off))[1] = h23;
            ((__nv_bfloat162*)(g_Blo + off))[0] = l01;
            ((__nv_bfloat162*)(g_Blo + off))[1] = l23;
        }
    } else {
        int b = blk - 1024;
        int tgt = targets[b];
        int prx = all_proxy_label[tgt];
        if (t == 0) g_pseudo[b] = prx / CN;
        float f = features[b * DN + t];
        __nv_bfloat16 fh = __float2bfloat16_rn(f);
        g_Ahi[b * DN + t] = fh;
        g_Alo[b * DN + t] = __float2bfloat16_rn(f - __bfloat162float(fh));
        float m = mem[(size_t)prx * DN + t];
        float bl = BALW * f + (1.0f - BALW) * m;
        __nv_bfloat16 bh = __float2bfloat16_rn(bl);
        g_Ahi[(BN + b) * DN + t] = bh;
        g_Alo[(BN + b) * DN + t] = __float2bfloat16_rn(bl - __bfloat162float(bh));
    }
}

// ---------------- K1c: pack A into mma fragment layout ----------------
// blk = rb*16 + ks16; 32 lanes; frag rows R0=rb*16, cols K0=ks16*16.
__global__ __launch_bounds__(32) void k_frag() {
    int blk = blockIdx.x;
    int l = threadIdx.x;
    int rb = blk >> 4, ks16 = blk & 15;
    int r0 = rb * 16 + (l >> 2);
    int c0 = ks16 * 16 + 2 * (l & 3);
    const unsigned short* H = (const unsigned short*)g_Ahi;
    const unsigned short* L = (const unsigned short*)g_Alo;
    uint4 h, w;
    h.x = (unsigned)H[r0 * DN + c0]       | ((unsigned)H[r0 * DN + c0 + 1] << 16);
    h.y = (unsigned)H[(r0+8) * DN + c0]   | ((unsigned)H[(r0+8) * DN + c0 + 1] << 16);
    h.z = (unsigned)H[r0 * DN + c0 + 8]   | ((unsigned)H[r0 * DN + c0 + 9] << 16);
    h.w = (unsigned)H[(r0+8) * DN + c0+8] | ((unsigned)H[(r0+8) * DN + c0 + 9] << 16);
    w.x = (unsigned)L[r0 * DN + c0]       | ((unsigned)L[r0 * DN + c0 + 1] << 16);
    w.y = (unsigned)L[(r0+8) * DN + c0]   | ((unsigned)L[(r0+8) * DN + c0 + 1] << 16);
    w.z = (unsigned)L[r0 * DN + c0 + 8]   | ((unsigned)L[r0 * DN + c0 + 9] << 16);
    w.w = (unsigned)L[(r0+8) * DN + c0+8] | ((unsigned)L[(r0+8) * DN + c0 + 9] << 16);
    g_AfragHi[blk * 32 + l] = h;
    g_AfragLo[blk * 32 + l] = w;
}

// ---------------- K2: mma.sync GEMM, B-only smem, all-K resident -----------
// grid (256 ntiles, 2 mtiles), 512 threads, 4x4 warp grid, warp tile 32x32 (x2 z).
// 4 K-chunks of 64, each a 32KB stage (Bhi 16KB + Blo 16KB), all resident.
#define STAGE_B 32768
#define SMEM_GEMM (4 * STAGE_B)

__global__ __launch_bounds__(512, 1) void k_gemm_mma() {
    extern __shared__ char smem[];
    const uint32_t sb = smem_u32(smem);
    const int t = threadIdx.x;
    const int lane = t & 31, w = t >> 5;
    const int warp_m = w >> 2, warp_n = w & 3;
    const int n0 = blockIdx.x * 128;
    const int m0 = blockIdx.y * 128;
    const int rbm = (m0 >> 4) + warp_m * 2;   // row-block base for z=0

    float acc[2][2][4][4];
#pragma unroll
    for (int z = 0; z < 2; z++)
#pragma unroll
        for (int i = 0; i < 2; i++)
#pragma unroll
            for (int j = 0; j < 4; j++)
#pragma unroll
                for (int q = 0; q < 4; q++) acc[z][i][j][q] = 0.f;

    // ---- issue all 4 B chunks ----
    const int cprow = t >> 3;   // idx = t + 512*j -> row = cprow + 64*j
    const int cpkc  = t & 7;
#pragma unroll
    for (int c = 0; c < 4; c++) {
        uint32_t st = sb + c * STAGE_B;
        int k0 = c * 64;
#pragma unroll
        for (int j = 0; j < 2; j++) {
            int row = cprow + 64 * j;
            uint32_t d = SW128((uint32_t)(row * 128 + cpkc * 16));
            cp16(st + d,         g_Bhi + (size_t)(n0 + row) * DN + k0 + cpkc * 8);
            cp16(st + 16384 + d, g_Blo + (size_t)(n0 + row) * DN + k0 + cpkc * 8);
        }
        cp_commit();
    }

    const int brow = warp_n * 32 + (lane & 7) + ((lane >> 4) << 3);
    const int bcolb = ((lane >> 3) & 1) << 4;

#define COMPUTE(c)                                                                     \
    {                                                                                  \
        uint32_t stBh = sb + (c) * STAGE_B;                                            \
        uint32_t stBl = stBh + 16384;                                                  \
        _Pragma("unroll")                                                              \
        for (int ks = 0; ks < 4; ks++) {                                               \
            int ks16 = (c) * 4 + ks;                                                   \
            uint32_t bh[4][2], bl[4][2];                                               \
            _Pragma("unroll")                                                          \
            for (int h = 0; h < 2; h++) {                                              \
                uint32_t off = SW128((uint32_t)((brow + h * 16) * 128 + ks * 32 + bcolb)); \
                uint32_t r0, r1, r2, r3;                                               \
                ldsm_x4(stBh + off, r0, r1, r2, r3);                                   \
                bh[h*2][0] = r0; bh[h*2][1] = r1; bh[h*2+1][0] = r2; bh[h*2+1][1] = r3;\
                ldsm_x4(stBl + off, r0, r1, r2, r3);                                   \
                bl[h*2][0] = r0; bl[h*2][1] = r1; bl[h*2+1][0] = r2; bl[h*2+1][1] = r3;\
            }                                                                          \
            _Pragma("unroll")                                                          \
            for (int z = 0; z < 2; z++) {                                              \
                _Pragma("unroll")                                                      \
                for (int mf = 0; mf < 2; mf++) {                                       \
                    int rb = z * 16 + rbm + mf;                                        \
                    uint4 ah = g_AfragHi[(rb * 16 + ks16) * 32 + lane];                \
                    uint4 al = g_AfragLo[(rb * 16 + ks16) * 32 + lane];                \
                    _Pragma("unroll")                                                  \
                    for (int nf = 0; nf < 4; nf++) {                                   \
                        mma_bf16(acc[z][mf][nf][0], acc[z][mf][nf][1], acc[z][mf][nf][2], acc[z][mf][nf][3], \
                                 ah.x, ah.y, ah.z, ah.w, bh[nf][0], bh[nf][1]);        \
                        mma_bf16(acc[z][mf][nf][0], acc[z][mf][nf][1], acc[z][mf][nf][2], acc[z][mf][nf][3], \
                                 ah.x, ah.y, ah.z, ah.w, bl[nf][0], bl[nf][1]);        \
                        mma_bf16(acc[z][mf][nf][0], acc[z][mf][nf][1], acc[z][mf][nf][2], acc[z][mf][nf][3], \
                                 al.x, al.y, al.z, al.w, bh[nf][0], bh[nf][1]);        \
                    }                                                                  \
                }                                                                      \
            }                                                                          \
        }                                                                              \
    }

    cp_wait<3>(); __syncthreads(); COMPUTE(0);
    cp_wait<2>(); __syncthreads(); COMPUTE(1);
    cp_wait<1>(); __syncthreads(); COMPUTE(2);
    cp_wait<0>(); __syncthreads(); COMPUTE(3);

    const int gr = lane >> 2;
    const int gc = (lane & 3) * 2;
#pragma unroll
    for (int z = 0; z < 2; z++) {
        float* outp = (z == 0) ? g_score : g_sims;
#pragma unroll
        for (int mf = 0; mf < 2; mf++) {
#pragma unroll
            for (int nf = 0; nf < 4; nf++) {
                int r0 = m0 + warp_m * 32 + mf * 16 + gr;
                int col = n0 + warp_n * 32 + nf * 8 + gc;
                float2 v0 = make_float2(acc[z][mf][nf][0], acc[z][mf][nf][1]);
                float2 v1 = make_float2(acc[z][mf][nf][2], acc[z][mf][nf][3]);
                *(float2*)(outp + (size_t)r0 * PN + col)       = v0;
                *(float2*)(outp + (size_t)(r0 + 8) * PN + col) = v1;
            }
        }
    }
}

// warp0-only: exact 50th-largest of 512 shared values via key bisection.
__device__ __forceinline__ void warp0_pivot(const float* tmax, int t,
                                            unsigned* sh_pk, float* sh_gm) {
    if (t < 32) {
        float m16[16];
#pragma unroll
        for (int k = 0; k < 16; k++) m16[k] = tmax[t + 32 * k];
        float gm = m16[0];
#pragma unroll
        for (int k = 1; k < 16; k++) gm = fmaxf(gm, m16[k]);
        for (int o = 16; o > 0; o >>= 1) gm = fmaxf(gm, __shfl_xor_sync(0xffffffffu, gm, o));
        unsigned klo = 0u, khi = fkey(gm);
#pragma unroll 1
        for (int it = 0; it < 32; it++) {
            if (khi - klo <= 1u) break;
            unsigned mid = klo + ((khi - klo) >> 1);
            float pm = unfkey(mid);
            int c = 0;
#pragma unroll
            for (int k = 0; k < 16; k++) c += (m16[k] > pm);
            for (int o = 16; o > 0; o >>= 1) c += __shfl_xor_sync(0xffffffffu, c, o);
            if (c >= BGK) klo = mid; else khi = mid;
        }
        if (t == 0) { *sh_pk = klo; *sh_gm = gm; }
    }
    __syncthreads();
}

// ---------------- merged loss kernel: blocks [0,256) = B (heavier first) ----
__global__ __launch_bounds__(512) void k_loss(const int* __restrict__ cams) {
    __shared__ float s16[16];
    __shared__ int   si16[16];
    __shared__ float tmax[512];
    __shared__ float candv[CAP];
    __shared__ int   candi[CAP];
    __shared__ float sposv[8];
    __shared__ float s_cv[8][16];
    __shared__ int   s_ci[8][16];
    __shared__ int   chos[3];
    __shared__ int   fin[64];
    __shared__ unsigned sh_pk;
    __shared__ float sh_gm;
    __shared__ unsigned sh_cnt, sh_nf;

    const int t = threadIdx.x;
    const int lane = t & 31, wid = t >> 5;

    if (blockIdx.x >= BN) {
        // ================= lossA: intra + cross on score =================
        const int b = blockIdx.x - BN;
        const float* ri = g_score + (size_t)b * PN;
        const int pseudo = g_pseudo[b];
        const int cam = cams[b];

        if (t == 0) sh_cnt = 0;
        if (t < 8) sposv[t] = KSCALE * ri[pseudo * 8 + t];

        float v[64];
        float vcam[8];
#pragma unroll
        for (int i = 0; i < 8; i++) {
            int chunk = t + 512 * i;
            const float4* p4 = (const float4*)(ri + 8 * chunk);
            float4 a = p4[0], c = p4[1];
            a.x *= KSCALE; a.y *= KSCALE; a.z *= KSCALE; a.w *= KSCALE;
            c.x *= KSCALE; c.y *= KSCALE; c.z *= KSCALE; c.w *= KSCALE;
            float sel = (cam < 4) ? ((cam < 2) ? (cam == 0 ? a.x : a.y)
                                               : (cam == 2 ? a.z : a.w))
                                  : ((cam < 6) ? (cam == 4 ? c.x : c.y)
                                               : (cam == 6 ? c.z : c.w));
            vcam[i] = sel;
            bool grp = (chunk == pseudo);
            float ninf = NEG_INF;
            v[i*8+0] = grp ? ninf : a.x; v[i*8+1] = grp ? ninf : a.y;
            v[i*8+2] = grp ? ninf : a.z; v[i*8+3] = grp ? ninf : a.w;
            v[i*8+4] = grp ? ninf : c.x; v[i*8+5] = grp ? ninf : c.y;
            v[i*8+6] = grp ? ninf : c.z; v[i*8+7] = grp ? ninf : c.w;
        }

        float m = v[0];
#pragma unroll
        for (int s = 1; s < 64; s++) m = fmaxf(m, v[s]);
        tmax[t] = m;
        float mi = vcam[0];
#pragma unroll
        for (int i = 1; i < 8; i++) mi = fmaxf(mi, vcam[i]);
        float Mi = blockMaxF(mi, s16, t);
        __syncthreads();

        warp0_pivot(tmax, t, &sh_pk, &sh_gm);
        unsigned pk = sh_pk;
        float Mex = sh_gm;
        float M = Mex;
#pragma unroll
        for (int k = 0; k < 8; k++) M = fmaxf(M, sposv[k]);

        float pf = unfkey(pk);
        {
            int c = 0;
#pragma unroll
            for (int s = 0; s < 64; s++) c += (v[s] > pf);
            int tot = blockSumI(c, si16, t);
            unsigned pkhi = fkey(Mex);
#pragma unroll 1
            while (tot > CAP && pkhi - pk > 1u) {
                unsigned mid = pk + ((pkhi - pk) >> 1);
                float pm = unfkey(mid);
                int c2 = 0;
#pragma unroll
                for (int s = 0; s < 64; s++) c2 += (v[s] > pm);
                int t2 = blockSumI(c2, si16, t);
                if (t2 >= BGK) { pk = mid; tot = t2; }
                else pkhi = mid;
            }
            pf = unfkey(pk);
        }

#pragma unroll
        for (int s = 0; s < 64; s++) {
            if (v[s] > pf) {
                unsigned k = atomicAdd(&sh_cnt, 1u);
                if (k < (unsigned)CAP) candv[k] = v[s];
            }
        }
        __syncthreads();
        int nc = (int)min(sh_cnt, (unsigned)CAP);

        float seC = 0.f;
        for (int i = t; i < nc; i += 512) {
            float x = candv[i];
            int r = 0;
            for (int j = 0; j < nc; j++) {
                float w2 = candv[j];
                r += (w2 > x) || (w2 == x && j < i);
            }
            if (r < BGK) seC += __expf(x - M);
        }
        if (t < 8) seC += __expf(sposv[t] - M);
        float sumC = blockSumF(seC, s16, t);

        float seI = 0.f;
#pragma unroll
        for (int i = 0; i < 8; i++) seI += __expf(vcam[i] - Mi);
        float sumI = blockSumF(seI, s16, t);

        if (t == 0) {
            float psum = 0.f;
            for (int k = 0; k < 8; k++) psum += sposv[k];
            g_loss[b]      = Mi + logf(sumI) - sposv[cam];
            g_loss[BN + b] = M  + logf(sumC) - psum * 0.125f;
        }
    } else {
        // ================= lossB: online on sims =================
        const int b = blockIdx.x;
        const float* rsm = g_sims  + (size_t)b * PN;
        const float* rsc = g_score + (size_t)b * PN;

        if (t == 0) { sh_cnt = 0; sh_nf = 3; }

        float v[64];
        float bv[8]; int bi[8];
#pragma unroll
        for (int j = 0; j < 8; j++) { bv[j] = NEG_INF; bi[j] = 0x7fffffff; }
#pragma unroll
        for (int i = 0; i < 8; i++) {
            int chunk = t + 512 * i;
            const float4* p4 = (const float4*)(rsm + 8 * chunk);
            float4 a = p4[0], c = p4[1];
            v[i*8+0]=a.x; v[i*8+1]=a.y; v[i*8+2]=a.z; v[i*8+3]=a.w;
            v[i*8+4]=c.x; v[i*8+5]=c.y; v[i*8+6]=c.z; v[i*8+7]=c.w;
#pragma unroll
            for (int j = 0; j < 8; j++) {
                float x = v[i*8+j];
                if (x > bv[j]) { bv[j] = x; bi[j] = 8 * chunk + j; }
            }
        }

#pragma unroll
        for (int j = 0; j < 8; j++) {
            float x = bv[j]; int idx = bi[j];
            for (int o = 16; o > 0; o >>= 1) {
                float ov = __shfl_down_sync(0xffffffffu, x, o);
                int   oi = __shfl_down_sync(0xffffffffu, idx, o);
                if (ov > x || (ov == x && oi < idx)) { x = ov; idx = oi; }
            }
            if (lane == 0) { s_cv[j][wid] = x; s_ci[j][wid] = idx; }
        }
        __syncthreads();
        if (t == 0) {
            float cv[8]; int ci[8];
            for (int c = 0; c < 8; c++) {
                float bvv = NEG_INF; int bii = 0x7fffffff;
                for (int w2 = 0; w2 < 16; w2++) {
                    float x = s_cv[c][w2]; int idx = s_ci[c][w2];
                    if (x > bvv || (x == bvv && idx < bii)) { bvv = x; bii = idx; }
                }
                cv[c] = bvv; ci[c] = bii;
            }
            bool used[8] = {false,false,false,false,false,false,false,false};
            for (int k = 0; k < PKK; k++) {
                int bc = -1; float bvv = NEG_INF;
                for (int c = 0; c < 8; c++)
                    if (!used[c] && cv[c] > bvv) { bvv = cv[c]; bc = c; }
                used[bc] = true;
                chos[k] = ci[bc];
            }
            fin[0] = chos[0]; fin[1] = chos[1]; fin[2] = chos[2];
        }
        __syncthreads();
        int c0 = chos[0], c1 = chos[1], c2 = chos[2];

#pragma unroll 1
        for (int k = 0; k < 3; k++) {
            int ck = (k == 0) ? c0 : (k == 1 ? c1 : c2);
            if (((ck >> 3) & 511) == t) {
                int slot = ((ck >> 3) >> 9) * 8 + (ck & 7);
#pragma unroll
                for (int s = 0; s < 64; s++)
                    if (s == slot) v[s] = NEG_INF;
            }
        }

        float m = v[0];
#pragma unroll
        for (int s = 1; s < 64; s++) m = fmaxf(m, v[s]);
        tmax[t] = m;
        __syncthreads();
        warp0_pivot(tmax, t, &sh_pk, &sh_gm);
        unsigned pk = sh_pk;
        float pf = unfkey(pk);
        {
            int c = 0;
#pragma unroll
            for (int s = 0; s < 64; s++) c += (v[s] > pf);
            int tot = blockSumI(c, si16, t);
            unsigned pkhi = fkey(sh_gm);
#pragma unroll 1
            while (tot > CAP && pkhi - pk > 1u) {
                unsigned mid = pk + ((pkhi - pk) >> 1);
                float pm = unfkey(mid);
                int c2 = 0;
#pragma unroll
                for (int s = 0; s < 64; s++) c2 += (v[s] > pm);
                int t2 = blockSumI(c2, si16, t);
                if (t2 >= BGK) { pk = mid; tot = t2; }
                else pkhi = mid;
            }
            pf = unfkey(pk);
        }
#pragma unroll
        for (int s = 0; s < 64; s++) {
            if (v[s] > pf) {
                unsigned k = atomicAdd(&sh_cnt, 1u);
                if (k < (unsigned)CAP) {
                    candv[k] = v[s];
                    candi[k] = 8 * (t + 512 * (s >> 3)) + (s & 7);
                }
            }
        }
        __syncthreads();
        int nc = (int)min(sh_cnt, (unsigned)CAP);

        for (int i = t; i < nc; i += 512) {
            float x = candv[i]; int pi = candi[i];
            int r = 0;
            for (int j = 0; j < nc; j++) {
                float w2 = candv[j];
                r += (w2 > x) || (w2 == x && candi[j] < pi);
            }
            if (r < BGK) {
                unsigned k = atomicAdd(&sh_nf, 1u);
                if (k < 64u) fin[k] = pi;
            }
        }
        __syncthreads();
        int nf = (int)min(sh_nf, 64u);   // 53

        float val = (t < nf) ? KSCALE * rsc[fin[t]] : NEG_INF;
        float mo = blockMaxF(val, s16, t);
        float e  = (t < nf) ? __expf(val - mo) : 0.f;
        float se = blockSumF(e, s16, t);
        if (t == 0) {
            float csum = KSCALE * rsc[c0] + KSCALE * rsc[c1] + KSCALE * rsc[c2];
            g_loss[2 * BN + b] = mo + logf(se) - csum * (1.0f / 3.0f);
        }
    }
}

// ---------------- final reduction (warp per camera) ----------------
__global__ void k_final(const int* __restrict__ cams, float* __restrict__ out) {
    __shared__ float sv[256];
    __shared__ int   sc[256];
    __shared__ float s8[8];
    int t = threadIdx.x;
    int w = t >> 5, l = t & 31;
    sv[t] = g_loss[t] + g_loss[BN + t] + g_loss[2 * BN + t];
    sc[t] = cams[t];
    __syncthreads();
    {
        float acc = 0.f; int n = 0;
        for (int b = l; b < BN; b += 32) {
            if (sc[b] == w) { acc += sv[b]; n++; }
        }
        for (int o = 16; o > 0; o >>= 1) {
            acc += __shfl_xor_sync(0xffffffffu, acc, o);
            n   += __shfl_xor_sync(0xffffffffu, n, o);
        }
        if (l == 0) s8[w] = (n > 0) ? acc / (float)n : 0.f;
    }
    __syncthreads();
    if (t == 0) {
        float tot = 0.f;
        for (int c = 0; c < 8; c++) tot += s8[c];
        out[0] = tot;
    }
}

// ---------------- launch ----------------
extern "C" void kernel_launch(void* const* d_in, const int* in_sizes, int n_in,
                              void* d_out, int out_size) {
    const float* features        = (const float*)d_in[0];
    const int*   targets         = (const int*)d_in[1];
    const int*   cams            = (const int*)d_in[2];
    const float* global_memory   = (const float*)d_in[4];
    const int*   all_proxy_label = (const int*)d_in[6];
    float* out = (float*)d_out;

    cudaFuncSetAttribute(k_gemm_mma, cudaFuncAttributeMaxDynamicSharedMemorySize, SMEM_GEMM);

    k_prep<<<1024 + BN, 256>>>(features, targets, all_proxy_label, global_memory);
    k_frag<<<512, 32>>>();
    dim3 gg(PN / 128, 2);
    k_gemm_mma<<<gg, 512, SMEM_GEMM>>>();
    k_loss<<<2 * BN, 512>>>(cams);
    k_final<<<1, 256>>>(cams, out);
}

// round 11
// speedup vs baseline: 1.2024x; 1.2024x over previous
#include <cuda_runtime.h>
#include <cuda_bf16.h>
#include <math.h>
#include <stdint.h>

#define BN   256
#define PN   32768
#define DN   256
#define CN   8
#define KSCALE 20.0f
#define BGK  50
#define PKK  3
#define BALW 0.15f
#define CAP  768

#define NEG_INF (__int_as_float(0xff800000))

// ---------------- scratch ----------------
__device__ int   g_pseudo[BN];
__device__ __nv_bfloat16 g_Ahi[2 * BN * DN];   // rows 0..255 features, 256..511 blended
__device__ __nv_bfloat16 g_Alo[2 * BN * DN];
__device__ __nv_bfloat16 g_Bhi[(size_t)PN * DN];
__device__ __nv_bfloat16 g_Blo[(size_t)PN * DN];
__device__ float g_score[(size_t)BN * PN];
__device__ float g_sims [(size_t)BN * PN];
__device__ float g_loss[3 * BN];

// ---------------- PTX helpers ----------------
__device__ __forceinline__ uint32_t smem_u32(const void* p) {
    uint32_t a;
    asm("{ .reg .u64 t; cvta.to.shared.u64 t, %1; cvt.u32.u64 %0, t; }" : "=r"(a) : "l"(p));
    return a;
}
#define SW128(off) ((off) ^ (((off) >> 3) & 0x70))
__device__ __forceinline__ void cp16(uint32_t dst, const void* src) {
    asm volatile("cp.async.cg.shared.global [%0], [%1], 16;" :: "r"(dst), "l"(src));
}
__device__ __forceinline__ void cp_commit() { asm volatile("cp.async.commit_group;"); }
template <int N>
__device__ __forceinline__ void cp_wait() { asm volatile("cp.async.wait_group %0;" :: "n"(N)); }

__device__ __forceinline__ void ldsm_x4(uint32_t addr, uint32_t& r0, uint32_t& r1,
                                        uint32_t& r2, uint32_t& r3) {
    asm volatile("ldmatrix.sync.aligned.m8n8.x4.shared.b16 {%0,%1,%2,%3}, [%4];"
        : "=r"(r0), "=r"(r1), "=r"(r2), "=r"(r3) : "r"(addr));
}
__device__ __forceinline__ void mma_bf16(float& c0, float& c1, float& c2, float& c3,
                                         uint32_t a0, uint32_t a1, uint32_t a2, uint32_t a3,
                                         uint32_t b0, uint32_t b1) {
    asm volatile("mma.sync.aligned.m16n8k16.row.col.f32.bf16.bf16.f32 "
        "{%0,%1,%2,%3}, {%4,%5,%6,%7}, {%8,%9}, {%0,%1,%2,%3};"
        : "+f"(c0), "+f"(c1), "+f"(c2), "+f"(c3)
        : "r"(a0), "r"(a1), "r"(a2), "r"(a3), "r"(b0), "r"(b1));
}

// ---------------- selection helpers ----------------
__device__ __forceinline__ unsigned fkey(float v) {
    unsigned u = __float_as_uint(v);
    return (u & 0x80000000u) ? ~u : (u | 0x80000000u);
}
__device__ __forceinline__ float unfkey(unsigned k) {
    unsigned u = (k & 0x80000000u) ? (k ^ 0x80000000u) : ~k;
    return __uint_as_float(u);
}
__device__ __forceinline__ float blockMaxF(float x, float* s16, int t) {
    int lane = t & 31, wid = t >> 5;
    for (int o = 16; o > 0; o >>= 1) x = fmaxf(x, __shfl_xor_sync(0xffffffffu, x, o));
    __syncthreads();
    if (lane == 0) s16[wid] = x;
    __syncthreads();
    if (t == 0) { float y = s16[0]; for (int w = 1; w < 16; w++) y = fmaxf(y, s16[w]); s16[0] = y; }
    __syncthreads();
    return s16[0];
}
__device__ __forceinline__ float blockSumF(float x, float* s16, int t) {
    int lane = t & 31, wid = t >> 5;
    for (int o = 16; o > 0; o >>= 1) x += __shfl_xor_sync(0xffffffffu, x, o);
    __syncthreads();
    if (lane == 0) s16[wid] = x;
    __syncthreads();
    if (t == 0) { float y = 0.f; for (int w = 0; w < 16; w++) y += s16[w]; s16[0] = y; }
    __syncthreads();
    return s16[0];
}
__device__ __forceinline__ int blockSumI(int x, int* s16, int t) {
    int lane = t & 31, wid = t >> 5;
    for (int o = 16; o > 0; o >>= 1) x += __shfl_xor_sync(0xffffffffu, x, o);
    __syncthreads();
    if (lane == 0) s16[wid] = x;
    __syncthreads();
    if (t == 0) { int y = 0; for (int w = 0; w < 16; w++) y += s16[w]; s16[0] = y; }
    __syncthreads();
    return s16[0];
}

// ---------------- K1: merged prep ----------------
__global__ __launch_bounds__(256) void k_prep(const float* __restrict__ features,
                                              const int* __restrict__ targets,
                                              const int* __restrict__ all_proxy_label,
                                              const float* __restrict__ mem) {
    int blk = blockIdx.x;
    int t = threadIdx.x;
    if (blk < 1024) {
        size_t base = (size_t)blk * 8192;
#pragma unroll
        for (int i = 0; i < 8; i++) {
            size_t off = base + (size_t)i * 1024 + t * 4;
            float4 f = *(const float4*)(mem + off);
            __nv_bfloat162 h01 = __floats2bfloat162_rn(f.x, f.y);
            __nv_bfloat162 h23 = __floats2bfloat162_rn(f.z, f.w);
            float lx = f.x - __bfloat162float(__low2bfloat16(h01));
            float ly = f.y - __bfloat162float(__high2bfloat16(h01));
            float lz = f.z - __bfloat162float(__low2bfloat16(h23));
            float lw = f.w - __bfloat162float(__high2bfloat16(h23));
            __nv_bfloat162 l01 = __floats2bfloat162_rn(lx, ly);
            __nv_bfloat162 l23 = __floats2bfloat162_rn(lz, lw);
            ((__nv_bfloat162*)(g_Bhi + off))[0] = h01;
            ((__nv_bfloat162*)(g_Bhi + off))[1] = h23;
            ((__nv_bfloat162*)(g_Blo + off))[0] = l01;
            ((__nv_bfloat162*)(g_Blo + off))[1] = l23;
        }
    } else {
        int b = blk - 1024;
        int tgt = targets[b];
        int prx = all_proxy_label[tgt];
        if (t == 0) g_pseudo[b] = prx / CN;
        float f = features[b * DN + t];
        __nv_bfloat16 fh = __float2bfloat16_rn(f);
        g_Ahi[b * DN + t] = fh;
        g_Alo[b * DN + t] = __float2bfloat16_rn(f - __bfloat162float(fh));
        float m = mem[(size_t)prx * DN + t];
        float bl = BALW * f + (1.0f - BALW) * m;
        __nv_bfloat16 bh = __float2bfloat16_rn(bl);
        g_Ahi[(BN + b) * DN + t] = bh;
        g_Alo[(BN + b) * DN + t] = __float2bfloat16_rn(bl - __bfloat162float(bh));
    }
}

// ---------------- K2: mma.sync bf16 3-term GEMM (R9 version) ---------------
#define KCH 64
#define STAGE_STRIDE 98304
#define SMEM_GEMM (2 * STAGE_STRIDE)

__global__ __launch_bounds__(512, 1) void k_gemm_mma() {
    extern __shared__ char smem[];
    const uint32_t sb = smem_u32(smem);
    const int t = threadIdx.x;
    const int lane = t & 31, w = t >> 5;
    const int warp_m = w >> 2, warp_n = w & 3;
    const int n0 = blockIdx.x * 128;
    const int m0 = blockIdx.y * 128;

    float acc[2][2][4][4];
#pragma unroll
    for (int z = 0; z < 2; z++)
#pragma unroll
        for (int i = 0; i < 2; i++)
#pragma unroll
            for (int j = 0; j < 4; j++)
#pragma unroll
                for (int q = 0; q < 4; q++) acc[z][i][j][q] = 0.f;

    const int cprow = t >> 3;
    const int cpkc  = t & 7;

#define ISSUE(c, s)                                                                    \
    {                                                                                  \
        int k0 = (c) * KCH;                                                            \
        uint32_t st = sb + (s) * STAGE_STRIDE;                                         \
        _Pragma("unroll")                                                              \
        for (int j = 0; j < 2; j++) {                                                  \
            int row = cprow + 64 * j;                                                  \
            uint32_t d = SW128((uint32_t)(row * 128 + cpkc * 16));                     \
            const __nv_bfloat16* ahs = g_Ahi + (size_t)(m0 + row) * DN + k0 + cpkc * 8;       \
            const __nv_bfloat16* als = g_Alo + (size_t)(m0 + row) * DN + k0 + cpkc * 8;       \
            const __nv_bfloat16* ahb = g_Ahi + (size_t)(BN + m0 + row) * DN + k0 + cpkc * 8;  \
            const __nv_bfloat16* alb = g_Alo + (size_t)(BN + m0 + row) * DN + k0 + cpkc * 8;  \
            const __nv_bfloat16* bh  = g_Bhi + (size_t)(n0 + row) * DN + k0 + cpkc * 8;       \
            const __nv_bfloat16* bl  = g_Blo + (size_t)(n0 + row) * DN + k0 + cpkc * 8;       \
            cp16(st + d, ahs);                                                         \
            cp16(st + 16384 + d, als);                                                 \
            cp16(st + 32768 + d, ahb);                                                 \
            cp16(st + 49152 + d, alb);                                                 \
            cp16(st + 65536 + d, bh);                                                  \
            cp16(st + 81920 + d, bl);                                                  \
        }                                                                              \
        cp_commit();                                                                   \
    }

#define COMPUTE(s)                                                                     \
    {                                                                                  \
        uint32_t st = sb + (s) * STAGE_STRIDE;                                         \
        uint32_t stBh = st + 65536;                                                    \
        uint32_t stBl = st + 81920;                                                    \
        const int arow = warp_m * 32 + (lane & 15);                                    \
        const int acolb = (lane >> 4) << 4;                                            \
        const int brow = warp_n * 32 + (lane & 7) + ((lane >> 4) << 3);                \
        const int bcolb = ((lane >> 3) & 1) << 4;                                      \
        _Pragma("unroll")                                                              \
        for (int ks = 0; ks < 4; ks++) {                                               \
            uint32_t bh[4][2], bl[4][2];                                               \
            _Pragma("unroll")                                                          \
            for (int h = 0; h < 2; h++) {                                              \
                uint32_t off = SW128((uint32_t)((brow + h * 16) * 128 + ks * 32 + bcolb)); \
                uint32_t r0, r1, r2, r3;                                               \
                ldsm_x4(stBh + off, r0, r1, r2, r3);                                   \
                bh[h*2][0] = r0; bh[h*2][1] = r1; bh[h*2+1][0] = r2; bh[h*2+1][1] = r3;\
                ldsm_x4(stBl + off, r0, r1, r2, r3);                                   \
                bl[h*2][0] = r0; bl[h*2][1] = r1; bl[h*2+1][0] = r2; bl[h*2+1][1] = r3;\
            }                                                                          \
            _Pragma("unroll")                                                          \
            for (int z = 0; z < 2; z++) {                                              \
                uint32_t stAh = st + z * 32768;                                        \
                uint32_t stAl = stAh + 16384;                                          \
                _Pragma("unroll")                                                      \
                for (int mf = 0; mf < 2; mf++) {                                       \
                    uint32_t ah0, ah1, ah2, ah3, al0, al1, al2, al3;                   \
                    uint32_t off = SW128((uint32_t)((arow + mf * 16) * 128 + ks * 32 + acolb)); \
                    ldsm_x4(stAh + off, ah0, ah1, ah2, ah3);                           \
                    ldsm_x4(stAl + off, al0, al1, al2, al3);                           \
                    _Pragma("unroll")                                                  \
                    for (int nf = 0; nf < 4; nf++) {                                   \
                        mma_bf16(acc[z][mf][nf][0], acc[z][mf][nf][1], acc[z][mf][nf][2], acc[z][mf][nf][3], \
                                 ah0, ah1, ah2, ah3, bh[nf][0], bh[nf][1]);            \
                        mma_bf16(acc[z][mf][nf][0], acc[z][mf][nf][1], acc[z][mf][nf][2], acc[z][mf][nf][3], \
                                 ah0, ah1, ah2, ah3, bl[nf][0], bl[nf][1]);            \
                        mma_bf16(acc[z][mf][nf][0], acc[z][mf][nf][1], acc[z][mf][nf][2], acc[z][mf][nf][3], \
                                 al0, al1, al2, al3, bh[nf][0], bh[nf][1]);            \
                    }                                                                  \
                }                                                                      \
            }                                                                          \
        }                                                                              \
    }

    ISSUE(0, 0);
    ISSUE(1, 1);

    cp_wait<1>(); __syncthreads();
    COMPUTE(0);  __syncthreads();
    ISSUE(2, 0);

    cp_wait<1>(); __syncthreads();
    COMPUTE(1);  __syncthreads();
    ISSUE(3, 1);

    cp_wait<1>(); __syncthreads();
    COMPUTE(0);  __syncthreads();

    cp_wait<0>(); __syncthreads();
    COMPUTE(1);

    const int gr = lane >> 2;
    const int gc = (lane & 3) * 2;
#pragma unroll
    for (int z = 0; z < 2; z++) {
        float* outp = (z == 0) ? g_score : g_sims;
#pragma unroll
        for (int mf = 0; mf < 2; mf++) {
#pragma unroll
            for (int nf = 0; nf < 4; nf++) {
                int r0 = m0 + warp_m * 32 + mf * 16 + gr;
                int col = n0 + warp_n * 32 + nf * 8 + gc;
                float2 v0 = make_float2(acc[z][mf][nf][0], acc[z][mf][nf][1]);
                float2 v1 = make_float2(acc[z][mf][nf][2], acc[z][mf][nf][3]);
                *(float2*)(outp + (size_t)r0 * PN + col)       = v0;
                *(float2*)(outp + (size_t)(r0 + 8) * PN + col) = v1;
            }
        }
    }
}

// warp0-only: exact kth-largest of 512 shared values via key bisection.
__device__ __forceinline__ void warp0_pivot(const float* tmax, int t, int kth,
                                            unsigned* sh_pk, float* sh_gm) {
    if (t < 32) {
        float m16[16];
#pragma unroll
        for (int k = 0; k < 16; k++) m16[k] = tmax[t + 32 * k];
        float gm = m16[0];
#pragma unroll
        for (int k = 1; k < 16; k++) gm = fmaxf(gm, m16[k]);
        for (int o = 16; o > 0; o >>= 1) gm = fmaxf(gm, __shfl_xor_sync(0xffffffffu, gm, o));
        unsigned klo = 0u, khi = fkey(gm);
#pragma unroll 1
        for (int it = 0; it < 32; it++) {
            if (khi - klo <= 1u) break;
            unsigned mid = klo + ((khi - klo) >> 1);
            float pm = unfkey(mid);
            int c = 0;
#pragma unroll
            for (int k = 0; k < 16; k++) c += (m16[k] > pm);
            for (int o = 16; o > 0; o >>= 1) c += __shfl_xor_sync(0xffffffffu, c, o);
            if (c >= kth) klo = mid; else khi = mid;
        }
        if (t == 0) { *sh_pk = klo; *sh_gm = gm; }
    }
    __syncthreads();
}

// ---------------- merged loss kernel: streaming 2-pass, low regs -----------
__global__ __launch_bounds__(512, 2) void k_loss(const int* __restrict__ cams) {
    __shared__ float s16[16];
    __shared__ int   si16[16];
    __shared__ float tmax[512];
    __shared__ float candv[CAP];
    __shared__ int   candi[CAP];
    __shared__ float sposv[8];
    __shared__ float s_cv[8][16];
    __shared__ int   s_ci[8][16];
    __shared__ int   chos[3];
    __shared__ int   fin[64];
    __shared__ unsigned sh_pk;
    __shared__ float sh_gm;
    __shared__ unsigned sh_cnt, sh_nf;

    const int t = threadIdx.x;
    const int lane = t & 31, wid = t >> 5;

    if (blockIdx.x >= BN) {
        // ================= lossA: intra + cross on score =================
        const int b = blockIdx.x - BN;
        const float* ri = g_score + (size_t)b * PN;
        const int pseudo = g_pseudo[b];
        const int cam = cams[b];

        if (t == 0) sh_cnt = 0;
        if (t < 8) sposv[t] = KSCALE * ri[pseudo * 8 + t];

        // pass 1: thread max (excl pseudo chunk) + vcam
        float vcam[8];
        float m = NEG_INF;
#pragma unroll
        for (int i = 0; i < 8; i++) {
            int chunk = t + 512 * i;
            const float4* p4 = (const float4*)(ri + 8 * chunk);
            float4 a = p4[0], c = p4[1];
            a.x *= KSCALE; a.y *= KSCALE; a.z *= KSCALE; a.w *= KSCALE;
            c.x *= KSCALE; c.y *= KSCALE; c.z *= KSCALE; c.w *= KSCALE;
            float sel = (cam < 4) ? ((cam < 2) ? (cam == 0 ? a.x : a.y)
                                               : (cam == 2 ? a.z : a.w))
                                  : ((cam < 6) ? (cam == 4 ? c.x : c.y)
                                               : (cam == 6 ? c.z : c.w));
            vcam[i] = sel;
            if (chunk != pseudo) {
                m = fmaxf(m, fmaxf(fmaxf(a.x, a.y), fmaxf(a.z, a.w)));
                m = fmaxf(m, fmaxf(fmaxf(c.x, c.y), fmaxf(c.z, c.w)));
            }
        }
        tmax[t] = m;
        float mi = vcam[0];
#pragma unroll
        for (int i = 1; i < 8; i++) mi = fmaxf(mi, vcam[i]);
        float Mi = blockMaxF(mi, s16, t);   // barrier makes tmax/sposv visible

        warp0_pivot(tmax, t, BGK, &sh_pk, &sh_gm);
        float M = sh_gm;
#pragma unroll
        for (int k = 0; k < 8; k++) M = fmaxf(M, sposv[k]);
        float pf = unfkey(sh_pk);

        // pass 2: gather candidates
#pragma unroll
        for (int i = 0; i < 8; i++) {
            int chunk = t + 512 * i;
            if (chunk == pseudo) continue;
            const float4* p4 = (const float4*)(ri + 8 * chunk);
            float4 a = p4[0], c = p4[1];
            float vv[8] = {KSCALE*a.x, KSCALE*a.y, KSCALE*a.z, KSCALE*a.w,
                           KSCALE*c.x, KSCALE*c.y, KSCALE*c.z, KSCALE*c.w};
#pragma unroll
            for (int j = 0; j < 8; j++) {
                if (vv[j] > pf) {
                    unsigned k = atomicAdd(&sh_cnt, 1u);
                    if (k < (unsigned)CAP) candv[k] = vv[j];
                }
            }
        }
        __syncthreads();
        if (sh_cnt > (unsigned)CAP) {
            // fallback (statistically never): raise pivot by streaming bisection
            unsigned pk = sh_pk, pkhi = fkey(sh_gm);
            int cnt = (int)sh_cnt;
#pragma unroll 1
            while (cnt > CAP && pkhi - pk > 1u) {
                unsigned mid = pk + ((pkhi - pk) >> 1);
                float pm = unfkey(mid);
                int c2 = 0;
                for (int i = 0; i < 8; i++) {
                    int chunk = t + 512 * i;
                    if (chunk == pseudo) continue;
                    const float4* p4 = (const float4*)(ri + 8 * chunk);
                    float4 a = p4[0], c = p4[1];
                    c2 += (KSCALE*a.x > pm) + (KSCALE*a.y > pm) + (KSCALE*a.z > pm) + (KSCALE*a.w > pm)
                        + (KSCALE*c.x > pm) + (KSCALE*c.y > pm) + (KSCALE*c.z > pm) + (KSCALE*c.w > pm);
                }
                int t2 = blockSumI(c2, si16, t);
                if (t2 >= BGK) { pk = mid; cnt = t2; }
                else pkhi = mid;
            }
            pf = unfkey(pk);
            __syncthreads();
            if (t == 0) sh_cnt = 0;
            __syncthreads();
            for (int i = 0; i < 8; i++) {
                int chunk = t + 512 * i;
                if (chunk == pseudo) continue;
                const float4* p4 = (const float4*)(ri + 8 * chunk);
                float4 a = p4[0], c = p4[1];
                float vv[8] = {KSCALE*a.x, KSCALE*a.y, KSCALE*a.z, KSCALE*a.w,
                               KSCALE*c.x, KSCALE*c.y, KSCALE*c.z, KSCALE*c.w};
                for (int j = 0; j < 8; j++) {
                    if (vv[j] > pf) {
                        unsigned k = atomicAdd(&sh_cnt, 1u);
                        if (k < (unsigned)CAP) candv[k] = vv[j];
                    }
                }
            }
            __syncthreads();
        }
        int nc = (int)min(sh_cnt, (unsigned)CAP);

        float seC = 0.f;
        for (int i = t; i < nc; i += 512) {
            float x = candv[i];
            int r = 0;
            for (int j = 0; j < nc; j++) {
                float w2 = candv[j];
                r += (w2 > x) || (w2 == x && j < i);
            }
            if (r < BGK) seC += __expf(x - M);
        }
        if (t < 8) seC += __expf(sposv[t] - M);
        float sumC = blockSumF(seC, s16, t);

        float seI = 0.f;
#pragma unroll
        for (int i = 0; i < 8; i++) seI += __expf(vcam[i] - Mi);
        float sumI = blockSumF(seI, s16, t);

        if (t == 0) {
            float psum = 0.f;
            for (int k = 0; k < 8; k++) psum += sposv[k];
            g_loss[b]      = Mi + logf(sumI) - sposv[cam];
            g_loss[BN + b] = M  + logf(sumC) - psum * 0.125f;
        }
    } else {
        // ================= lossB: online on sims =================
        const int b = blockIdx.x;
        const float* rsm = g_sims  + (size_t)b * PN;
        const float* rsc = g_score + (size_t)b * PN;

        if (t == 0) { sh_cnt = 0; sh_nf = 3; }

        // pass 1: per-camera argmax + thread max (all values)
        float bv[8]; int bi[8];
#pragma unroll
        for (int j = 0; j < 8; j++) { bv[j] = NEG_INF; bi[j] = 0x7fffffff; }
        float m = NEG_INF;
#pragma unroll
        for (int i = 0; i < 8; i++) {
            int chunk = t + 512 * i;
            const float4* p4 = (const float4*)(rsm + 8 * chunk);
            float4 a = p4[0], c = p4[1];
            float vv[8] = {a.x, a.y, a.z, a.w, c.x, c.y, c.z, c.w};
#pragma unroll
            for (int j = 0; j < 8; j++) {
                float x = vv[j];
                if (x > bv[j]) { bv[j] = x; bi[j] = 8 * chunk + j; }
                m = fmaxf(m, x);
            }
        }
        tmax[t] = m;

#pragma unroll
        for (int j = 0; j < 8; j++) {
            float x = bv[j]; int idx = bi[j];
            for (int o = 16; o > 0; o >>= 1) {
                float ov = __shfl_down_sync(0xffffffffu, x, o);
                int   oi = __shfl_down_sync(0xffffffffu, idx, o);
                if (ov > x || (ov == x && oi < idx)) { x = ov; idx = oi; }
            }
            if (lane == 0) { s_cv[j][wid] = x; s_ci[j][wid] = idx; }
        }
        __syncthreads();
        if (t == 0) {
            float cv[8]; int ci[8];
            for (int c = 0; c < 8; c++) {
                float bvv = NEG_INF; int bii = 0x7fffffff;
                for (int w2 = 0; w2 < 16; w2++) {
                    float x = s_cv[c][w2]; int idx = s_ci[c][w2];
                    if (x > bvv || (x == bvv && idx < bii)) { bvv = x; bii = idx; }
                }
                cv[c] = bvv; ci[c] = bii;
            }
            bool used[8] = {false,false,false,false,false,false,false,false};
            for (int k = 0; k < PKK; k++) {
                int bc = -1; float bvv = NEG_INF;
                for (int c = 0; c < 8; c++)
                    if (!used[c] && cv[c] > bvv) { bvv = cv[c]; bc = c; }
                used[bc] = true;
                chos[k] = ci[bc];
            }
            fin[0] = chos[0]; fin[1] = chos[1]; fin[2] = chos[2];
        }
        __syncthreads();
        int c0 = chos[0], c1 = chos[1], c2 = chos[2];

        // pivot = 53rd-largest thread max (>=53 above => >=50 valid above)
        warp0_pivot(tmax, t, BGK + PKK, &sh_pk, &sh_gm);
        float pf = unfkey(sh_pk);

        // pass 2: gather (value, index) excluding chosen
#pragma unroll
        for (int i = 0; i < 8; i++) {
            int chunk = t + 512 * i;
            const float4* p4 = (const float4*)(rsm + 8 * chunk);
            float4 a = p4[0], c = p4[1];
            float vv[8] = {a.x, a.y, a.z, a.w, c.x, c.y, c.z, c.w};
#pragma unroll
            for (int j = 0; j < 8; j++) {
                int p = 8 * chunk + j;
                if (vv[j] > pf && p != c0 && p != c1 && p != c2) {
                    unsigned k = atomicAdd(&sh_cnt, 1u);
                    if (k < (unsigned)CAP) { candv[k] = vv[j]; candi[k] = p; }
                }
            }
        }
        __syncthreads();
        if (sh_cnt > (unsigned)CAP) {
            unsigned pk = sh_pk, pkhi = fkey(sh_gm);
            int cnt = (int)sh_cnt;
#pragma unroll 1
            while (cnt > CAP && pkhi - pk > 1u) {
                unsigned mid = pk + ((pkhi - pk) >> 1);
                float pm = unfkey(mid);
                int cacc = 0;
                for (int i = 0; i < 8; i++) {
                    int chunk = t + 512 * i;
                    const float4* p4 = (const float4*)(rsm + 8 * chunk);
                    float4 a = p4[0], c = p4[1];
                    float vv[8] = {a.x, a.y, a.z, a.w, c.x, c.y, c.z, c.w};
                    for (int j = 0; j < 8; j++) {
                        int p = 8 * chunk + j;
                        cacc += (vv[j] > pm && p != c0 && p != c1 && p != c2);
                    }
                }
                int t2 = blockSumI(cacc, si16, t);
                if (t2 >= BGK) { pk = mid; cnt = t2; }
                else pkhi = mid;
            }
            pf = unfkey(pk);
            __syncthreads();
            if (t == 0) sh_cnt = 0;
            __syncthreads();
            for (int i = 0; i < 8; i++) {
                int chunk = t + 512 * i;
                const float4* p4 = (const float4*)(rsm + 8 * chunk);
                float4 a = p4[0], c = p4[1];
                float vv[8] = {a.x, a.y, a.z, a.w, c.x, c.y, c.z, c.w};
                for (int j = 0; j < 8; j++) {
                    int p = 8 * chunk + j;
                    if (vv[j] > pf && p != c0 && p != c1 && p != c2) {
                        unsigned k = atomicAdd(&sh_cnt, 1u);
                        if (k < (unsigned)CAP) { candv[k] = vv[j]; candi[k] = p; }
                    }
                }
            }
            __syncthreads();
        }
        int nc = (int)min(sh_cnt, (unsigned)CAP);

        for (int i = t; i < nc; i += 512) {
            float x = candv[i]; int pi = candi[i];
            int r = 0;
            for (int j = 0; j < nc; j++) {
                float w2 = candv[j];
                r += (w2 > x) || (w2 == x && candi[j] < pi);
            }
            if (r < BGK) {
                unsigned k = atomicAdd(&sh_nf, 1u);
                if (k < 64u) fin[k] = pi;
            }
        }
        __syncthreads();
        int nf = (int)min(sh_nf, 64u);   // 53

        float val = (t < nf) ? KSCALE * rsc[fin[t]] : NEG_INF;
        float mo = blockMaxF(val, s16, t);
        float e  = (t < nf) ? __expf(val - mo) : 0.f;
        float se = blockSumF(e, s16, t);
        if (t == 0) {
            float csum = KSCALE * rsc[c0] + KSCALE * rsc[c1] + KSCALE * rsc[c2];
            g_loss[2 * BN + b] = mo + logf(se) - csum * (1.0f / 3.0f);
        }
    }
}

// ---------------- final reduction (warp per camera) ----------------
__global__ void k_final(const int* __restrict__ cams, float* __restrict__ out) {
    __shared__ float sv[256];
    __shared__ int   sc[256];
    __shared__ float s8[8];
    int t = threadIdx.x;
    int w = t >> 5, l = t & 31;
    sv[t] = g_loss[t] + g_loss[BN + t] + g_loss[2 * BN + t];
    sc[t] = cams[t];
    __syncthreads();
    {
        float acc = 0.f; int n = 0;
        for (int b = l; b < BN; b += 32) {
            if (sc[b] == w) { acc += sv[b]; n++; }
        }
        for (int o = 16; o > 0; o >>= 1) {
            acc += __shfl_xor_sync(0xffffffffu, acc, o);
            n   += __shfl_xor_sync(0xffffffffu, n, o);
        }
        if (l == 0) s8[w] = (n > 0) ? acc / (float)n : 0.f;
    }
    __syncthreads();
    if (t == 0) {
        float tot = 0.f;
        for (int c = 0; c < 8; c++) tot += s8[c];
        out[0] = tot;
    }
}

// ---------------- launch ----------------
extern "C" void kernel_launch(void* const* d_in, const int* in_sizes, int n_in,
                              void* d_out, int out_size) {
    const float* features        = (const float*)d_in[0];
    const int*   targets         = (const int*)d_in[1];
    const int*   cams            = (const int*)d_in[2];
    const float* global_memory   = (const float*)d_in[4];
    const int*   all_proxy_label = (const int*)d_in[6];
    float* out = (float*)d_out;

    cudaFuncSetAttribute(k_gemm_mma, cudaFuncAttributeMaxDynamicSharedMemorySize, SMEM_GEMM);

    k_prep<<<1024 + BN, 256>>>(features, targets, all_proxy_label, global_memory);
    dim3 gg(PN / 128, 2);
    k_gemm_mma<<<gg, 512, SMEM_GEMM>>>();
    k_loss<<<2 * BN, 512>>>(cams);
    k_final<<<1, 256>>>(cams, out);
}

// round 12
// speedup vs baseline: 1.2762x; 1.0613x over previous
#include <cuda_runtime.h>
#include <cuda_bf16.h>
#include <math.h>
#include <stdint.h>

#define BN   256
#define PN   32768
#define DN   256
#define CN   8
#define KSCALE 20.0f
#define BGK  50
#define PKK  3
#define BALW 0.15f
#define CAP  768

#define NEG_INF (__int_as_float(0xff800000))

// ---------------- scratch ----------------
__device__ int   g_pseudo[BN];
__device__ __nv_bfloat16 g_Ahi[2 * BN * DN];   // rows 0..255 features, 256..511 blended
__device__ __nv_bfloat16 g_Alo[2 * BN * DN];
__device__ __nv_bfloat16 g_Bhi[(size_t)PN * DN];
__device__ __nv_bfloat16 g_Blo[(size_t)PN * DN];
__device__ float g_score[(size_t)BN * PN];
__device__ float g_sims [(size_t)BN * PN];
__device__ float g_loss[3 * BN];

// ---------------- PTX helpers ----------------
__device__ __forceinline__ uint32_t smem_u32(const void* p) {
    uint32_t a;
    asm("{ .reg .u64 t; cvta.to.shared.u64 t, %1; cvt.u32.u64 %0, t; }" : "=r"(a) : "l"(p));
    return a;
}
// 64B-row swizzle: u' = u ^ ((r>>1)&3) for off = r*64 + u*16
#define SW64(off) ((off) ^ (((off) >> 3) & 0x30))
__device__ __forceinline__ void cp16(uint32_t dst, const void* src) {
    asm volatile("cp.async.cg.shared.global [%0], [%1], 16;" :: "r"(dst), "l"(src));
}
__device__ __forceinline__ void cp_commit() { asm volatile("cp.async.commit_group;"); }
template <int N>
__device__ __forceinline__ void cp_wait() { asm volatile("cp.async.wait_group %0;" :: "n"(N)); }

__device__ __forceinline__ void ldsm_x4(uint32_t addr, uint32_t& r0, uint32_t& r1,
                                        uint32_t& r2, uint32_t& r3) {
    asm volatile("ldmatrix.sync.aligned.m8n8.x4.shared.b16 {%0,%1,%2,%3}, [%4];"
        : "=r"(r0), "=r"(r1), "=r"(r2), "=r"(r3) : "r"(addr));
}
__device__ __forceinline__ void mma_bf16(float& c0, float& c1, float& c2, float& c3,
                                         uint32_t a0, uint32_t a1, uint32_t a2, uint32_t a3,
                                         uint32_t b0, uint32_t b1) {
    asm volatile("mma.sync.aligned.m16n8k16.row.col.f32.bf16.bf16.f32 "
        "{%0,%1,%2,%3}, {%4,%5,%6,%7}, {%8,%9}, {%0,%1,%2,%3};"
        : "+f"(c0), "+f"(c1), "+f"(c2), "+f"(c3)
        : "r"(a0), "r"(a1), "r"(a2), "r"(a3), "r"(b0), "r"(b1));
}

// ---------------- selection helpers ----------------
__device__ __forceinline__ unsigned fkey(float v) {
    unsigned u = __float_as_uint(v);
    return (u & 0x80000000u) ? ~u : (u | 0x80000000u);
}
__device__ __forceinline__ float unfkey(unsigned k) {
    unsigned u = (k & 0x80000000u) ? (k ^ 0x80000000u) : ~k;
    return __uint_as_float(u);
}
__device__ __forceinline__ float blockMaxF(float x, float* s16, int t) {
    int lane = t & 31, wid = t >> 5;
    for (int o = 16; o > 0; o >>= 1) x = fmaxf(x, __shfl_xor_sync(0xffffffffu, x, o));
    __syncthreads();
    if (lane == 0) s16[wid] = x;
    __syncthreads();
    if (t == 0) { float y = s16[0]; for (int w = 1; w < 16; w++) y = fmaxf(y, s16[w]); s16[0] = y; }
    __syncthreads();
    return s16[0];
}
__device__ __forceinline__ float blockSumF(float x, float* s16, int t) {
    int lane = t & 31, wid = t >> 5;
    for (int o = 16; o > 0; o >>= 1) x += __shfl_xor_sync(0xffffffffu, x, o);
    __syncthreads();
    if (lane == 0) s16[wid] = x;
    __syncthreads();
    if (t == 0) { float y = 0.f; for (int w = 0; w < 16; w++) y += s16[w]; s16[0] = y; }
    __syncthreads();
    return s16[0];
}
__device__ __forceinline__ int blockSumI(int x, int* s16, int t) {
    int lane = t & 31, wid = t >> 5;
    for (int o = 16; o > 0; o >>= 1) x += __shfl_xor_sync(0xffffffffu, x, o);
    __syncthreads();
    if (lane == 0) s16[wid] = x;
    __syncthreads();
    if (t == 0) { int y = 0; for (int w = 0; w < 16; w++) y += s16[w]; s16[0] = y; }
    __syncthreads();
    return s16[0];
}

// ---------------- K1: merged prep ----------------
__global__ __launch_bounds__(256) void k_prep(const float* __restrict__ features,
                                              const int* __restrict__ targets,
                                              const int* __restrict__ all_proxy_label,
                                              const float* __restrict__ mem) {
    int blk = blockIdx.x;
    int t = threadIdx.x;
    if (blk < 1024) {
        size_t base = (size_t)blk * 8192;
#pragma unroll
        for (int i = 0; i < 8; i++) {
            size_t off = base + (size_t)i * 1024 + t * 4;
            float4 f = *(const float4*)(mem + off);
            __nv_bfloat162 h01 = __floats2bfloat162_rn(f.x, f.y);
            __nv_bfloat162 h23 = __floats2bfloat162_rn(f.z, f.w);
            float lx = f.x - __bfloat162float(__low2bfloat16(h01));
            float ly = f.y - __bfloat162float(__high2bfloat16(h01));
            float lz = f.z - __bfloat162float(__low2bfloat16(h23));
            float lw = f.w - __bfloat162float(__high2bfloat16(h23));
            __nv_bfloat162 l01 = __floats2bfloat162_rn(lx, ly);
            __nv_bfloat162 l23 = __floats2bfloat162_rn(lz, lw);
            ((__nv_bfloat162*)(g_Bhi + off))[0] = h01;
            ((__nv_bfloat162*)(g_Bhi + off))[1] = h23;
            ((__nv_bfloat162*)(g_Blo + off))[0] = l01;
            ((__nv_bfloat162*)(g_Blo + off))[1] = l23;
        }
    } else {
        int b = blk - 1024;
        int tgt = targets[b];
        int prx = all_proxy_label[tgt];
        if (t == 0) g_pseudo[b] = prx / CN;
        float f = features[b * DN + t];
        __nv_bfloat16 fh = __float2bfloat16_rn(f);
        g_Ahi[b * DN + t] = fh;
        g_Alo[b * DN + t] = __float2bfloat16_rn(f - __bfloat162float(fh));
        float m = mem[(size_t)prx * DN + t];
        float bl = BALW * f + (1.0f - BALW) * m;
        __nv_bfloat16 bh = __float2bfloat16_rn(bl);
        g_Ahi[(BN + b) * DN + t] = bh;
        g_Alo[(BN + b) * DN + t] = __float2bfloat16_rn(bl - __bfloat162float(bh));
    }
}

// ---------------- K2: mma.sync bf16 3-term GEMM, 256 thr, 2 CTAs/SM --------
// grid (256 ntiles, 2 mtiles, 2 z), 256 threads, 8 warps as 2(m)x4(n),
// warp tile 64x32, K = 256 in 8 chunks of 32, 3-stage pipeline, SW64 rows.
#define KCH 32
#define STAGE_SZ 32768     // Ahi 8K, Alo 8K, Bhi 8K, Blo 8K
#define SMEM_GEMM (3 * STAGE_SZ)

__global__ __launch_bounds__(256, 2) void k_gemm_mma() {
    extern __shared__ char smem[];
    const uint32_t sb = smem_u32(smem);
    const int t = threadIdx.x;
    const int lane = t & 31, w = t >> 5;
    const int warp_m = w >> 2, warp_n = w & 3;
    const int n0 = blockIdx.x * 128;
    const int m0 = blockIdx.y * 128;
    const int z  = blockIdx.z;               // 0 = score, 1 = sims
    const int arow_base = (z ? BN : 0) + m0;

    float acc[4][4][4];
#pragma unroll
    for (int i = 0; i < 4; i++)
#pragma unroll
        for (int j = 0; j < 4; j++)
#pragma unroll
            for (int q = 0; q < 4; q++) acc[i][j][q] = 0.f;

    const int cprow = t >> 2;     // 0..63; rows r = cprow + 64*j
    const int cpu   = t & 3;      // 16B unit within 64B row

#define ISSUE(c, s)                                                                    \
    {                                                                                  \
        int k0 = (c) * KCH;                                                            \
        uint32_t st = sb + (s) * STAGE_SZ;                                             \
        _Pragma("unroll")                                                              \
        for (int j = 0; j < 2; j++) {                                                  \
            int row = cprow + 64 * j;                                                  \
            uint32_t d = SW64((uint32_t)(row * 64 + cpu * 16));                        \
            cp16(st + d,         g_Ahi + (size_t)(arow_base + row) * DN + k0 + cpu * 8); \
            cp16(st + 8192 + d,  g_Alo + (size_t)(arow_base + row) * DN + k0 + cpu * 8); \
            cp16(st + 16384 + d, g_Bhi + (size_t)(n0 + row) * DN + k0 + cpu * 8);      \
            cp16(st + 24576 + d, g_Blo + (size_t)(n0 + row) * DN + k0 + cpu * 8);      \
        }                                                                              \
        cp_commit();                                                                   \
    }

#define COMPUTE(s)                                                                     \
    {                                                                                  \
        uint32_t stAh = sb + (s) * STAGE_SZ;                                           \
        uint32_t stAl = stAh + 8192;                                                   \
        uint32_t stBh = stAh + 16384;                                                  \
        uint32_t stBl = stAh + 24576;                                                  \
        const int arow = warp_m * 64 + (lane & 15);                                    \
        const int acolb = (lane >> 4) << 4;                                            \
        const int brow = warp_n * 32 + (lane & 7) + ((lane >> 4) << 3);                \
        const int bcolb = ((lane >> 3) & 1) << 4;                                      \
        _Pragma("unroll")                                                              \
        for (int ks = 0; ks < 2; ks++) {                                               \
            uint32_t bh[4][2], bl[4][2];                                               \
            _Pragma("unroll")                                                          \
            for (int h = 0; h < 2; h++) {                                              \
                uint32_t off = SW64((uint32_t)((brow + h * 16) * 64 + ks * 32 + bcolb)); \
                uint32_t r0, r1, r2, r3;                                               \
                ldsm_x4(stBh + off, r0, r1, r2, r3);                                   \
                bh[h*2][0] = r0; bh[h*2][1] = r1; bh[h*2+1][0] = r2; bh[h*2+1][1] = r3;\
                ldsm_x4(stBl + off, r0, r1, r2, r3);                                   \
                bl[h*2][0] = r0; bl[h*2][1] = r1; bl[h*2+1][0] = r2; bl[h*2+1][1] = r3;\
            }                                                                          \
            _Pragma("unroll")                                                          \
            for (int mf = 0; mf < 4; mf++) {                                           \
                uint32_t ah0, ah1, ah2, ah3, al0, al1, al2, al3;                       \
                uint32_t off = SW64((uint32_t)((arow + mf * 16) * 64 + ks * 32 + acolb)); \
                ldsm_x4(stAh + off, ah0, ah1, ah2, ah3);                               \
                ldsm_x4(stAl + off, al0, al1, al2, al3);                               \
                _Pragma("unroll")                                                      \
                for (int nf = 0; nf < 4; nf++) {                                       \
                    mma_bf16(acc[mf][nf][0], acc[mf][nf][1], acc[mf][nf][2], acc[mf][nf][3], \
                             ah0, ah1, ah2, ah3, bh[nf][0], bh[nf][1]);                \
                    mma_bf16(acc[mf][nf][0], acc[mf][nf][1], acc[mf][nf][2], acc[mf][nf][3], \
                             ah0, ah1, ah2, ah3, bl[nf][0], bl[nf][1]);                \
                    mma_bf16(acc[mf][nf][0], acc[mf][nf][1], acc[mf][nf][2], acc[mf][nf][3], \
                             al0, al1, al2, al3, bh[nf][0], bh[nf][1]);                \
                }                                                                      \
            }                                                                          \
        }                                                                              \
    }

    ISSUE(0, 0); ISSUE(1, 1); ISSUE(2, 2);

    cp_wait<2>(); __syncthreads(); COMPUTE(0); __syncthreads(); ISSUE(3, 0);
    cp_wait<2>(); __syncthreads(); COMPUTE(1); __syncthreads(); ISSUE(4, 1);
    cp_wait<2>(); __syncthreads(); COMPUTE(2); __syncthreads(); ISSUE(5, 2);
    cp_wait<2>(); __syncthreads(); COMPUTE(0); __syncthreads(); ISSUE(6, 0);
    cp_wait<2>(); __syncthreads(); COMPUTE(1); __syncthreads(); ISSUE(7, 1);
    cp_wait<2>(); __syncthreads(); COMPUTE(2);
    cp_wait<1>(); __syncthreads(); COMPUTE(0);
    cp_wait<0>(); __syncthreads(); COMPUTE(1);

    float* outp = (z == 0) ? g_score : g_sims;
    const int gr = lane >> 2;
    const int gc = (lane & 3) * 2;
#pragma unroll
    for (int mf = 0; mf < 4; mf++) {
#pragma unroll
        for (int nf = 0; nf < 4; nf++) {
            int r0 = m0 + warp_m * 64 + mf * 16 + gr;
            int col = n0 + warp_n * 32 + nf * 8 + gc;
            float2 v0 = make_float2(acc[mf][nf][0], acc[mf][nf][1]);
            float2 v1 = make_float2(acc[mf][nf][2], acc[mf][nf][3]);
            *(float2*)(outp + (size_t)r0 * PN + col)       = v0;
            *(float2*)(outp + (size_t)(r0 + 8) * PN + col) = v1;
        }
    }
}

// warp0-only: exact kth-largest of 512 shared values via key bisection.
__device__ __forceinline__ void warp0_pivot(const float* tmax, int t, int kth,
                                            unsigned* sh_pk, float* sh_gm) {
    if (t < 32) {
        float m16[16];
#pragma unroll
        for (int k = 0; k < 16; k++) m16[k] = tmax[t + 32 * k];
        float gm = m16[0];
#pragma unroll
        for (int k = 1; k < 16; k++) gm = fmaxf(gm, m16[k]);
        for (int o = 16; o > 0; o >>= 1) gm = fmaxf(gm, __shfl_xor_sync(0xffffffffu, gm, o));
        unsigned klo = 0u, khi = fkey(gm);
#pragma unroll 1
        for (int it = 0; it < 32; it++) {
            if (khi - klo <= 1u) break;
            unsigned mid = klo + ((khi - klo) >> 1);
            float pm = unfkey(mid);
            int c = 0;
#pragma unroll
            for (int k = 0; k < 16; k++) c += (m16[k] > pm);
            for (int o = 16; o > 0; o >>= 1) c += __shfl_xor_sync(0xffffffffu, c, o);
            if (c >= kth) klo = mid; else khi = mid;
        }
        if (t == 0) { *sh_pk = klo; *sh_gm = gm; }
    }
    __syncthreads();
}

// ---------------- merged loss kernel: streaming 2-pass (R11, proven) -------
__global__ __launch_bounds__(512, 2) void k_loss(const int* __restrict__ cams) {
    __shared__ float s16[16];
    __shared__ int   si16[16];
    __shared__ float tmax[512];
    __shared__ float candv[CAP];
    __shared__ int   candi[CAP];
    __shared__ float sposv[8];
    __shared__ float s_cv[8][16];
    __shared__ int   s_ci[8][16];
    __shared__ int   chos[3];
    __shared__ int   fin[64];
    __shared__ unsigned sh_pk;
    __shared__ float sh_gm;
    __shared__ unsigned sh_cnt, sh_nf;

    const int t = threadIdx.x;
    const int lane = t & 31, wid = t >> 5;

    if (blockIdx.x >= BN) {
        // ================= lossA: intra + cross on score =================
        const int b = blockIdx.x - BN;
        const float* ri = g_score + (size_t)b * PN;
        const int pseudo = g_pseudo[b];
        const int cam = cams[b];

        if (t == 0) sh_cnt = 0;
        if (t < 8) sposv[t] = KSCALE * ri[pseudo * 8 + t];

        float vcam[8];
        float m = NEG_INF;
#pragma unroll
        for (int i = 0; i < 8; i++) {
            int chunk = t + 512 * i;
            const float4* p4 = (const float4*)(ri + 8 * chunk);
            float4 a = p4[0], c = p4[1];
            a.x *= KSCALE; a.y *= KSCALE; a.z *= KSCALE; a.w *= KSCALE;
            c.x *= KSCALE; c.y *= KSCALE; c.z *= KSCALE; c.w *= KSCALE;
            float sel = (cam < 4) ? ((cam < 2) ? (cam == 0 ? a.x : a.y)
                                               : (cam == 2 ? a.z : a.w))
                                  : ((cam < 6) ? (cam == 4 ? c.x : c.y)
                                               : (cam == 6 ? c.z : c.w));
            vcam[i] = sel;
            if (chunk != pseudo) {
                m = fmaxf(m, fmaxf(fmaxf(a.x, a.y), fmaxf(a.z, a.w)));
                m = fmaxf(m, fmaxf(fmaxf(c.x, c.y), fmaxf(c.z, c.w)));
            }
        }
        tmax[t] = m;
        float mi = vcam[0];
#pragma unroll
        for (int i = 1; i < 8; i++) mi = fmaxf(mi, vcam[i]);
        float Mi = blockMaxF(mi, s16, t);

        warp0_pivot(tmax, t, BGK, &sh_pk, &sh_gm);
        float M = sh_gm;
#pragma unroll
        for (int k = 0; k < 8; k++) M = fmaxf(M, sposv[k]);
        float pf = unfkey(sh_pk);

#pragma unroll
        for (int i = 0; i < 8; i++) {
            int chunk = t + 512 * i;
            if (chunk == pseudo) continue;
            const float4* p4 = (const float4*)(ri + 8 * chunk);
            float4 a = p4[0], c = p4[1];
            float vv[8] = {KSCALE*a.x, KSCALE*a.y, KSCALE*a.z, KSCALE*a.w,
                           KSCALE*c.x, KSCALE*c.y, KSCALE*c.z, KSCALE*c.w};
#pragma unroll
            for (int j = 0; j < 8; j++) {
                if (vv[j] > pf) {
                    unsigned k = atomicAdd(&sh_cnt, 1u);
                    if (k < (unsigned)CAP) candv[k] = vv[j];
                }
            }
        }
        __syncthreads();
        if (sh_cnt > (unsigned)CAP) {
            unsigned pk = sh_pk, pkhi = fkey(sh_gm);
            int cnt = (int)sh_cnt;
#pragma unroll 1
            while (cnt > CAP && pkhi - pk > 1u) {
                unsigned mid = pk + ((pkhi - pk) >> 1);
                float pm = unfkey(mid);
                int c2 = 0;
                for (int i = 0; i < 8; i++) {
                    int chunk = t + 512 * i;
                    if (chunk == pseudo) continue;
                    const float4* p4 = (const float4*)(ri + 8 * chunk);
                    float4 a = p4[0], c = p4[1];
                    c2 += (KSCALE*a.x > pm) + (KSCALE*a.y > pm) + (KSCALE*a.z > pm) + (KSCALE*a.w > pm)
                        + (KSCALE*c.x > pm) + (KSCALE*c.y > pm) + (KSCALE*c.z > pm) + (KSCALE*c.w > pm);
                }
                int t2 = blockSumI(c2, si16, t);
                if (t2 >= BGK) { pk = mid; cnt = t2; }
                else pkhi = mid;
            }
            pf = unfkey(pk);
            __syncthreads();
            if (t == 0) sh_cnt = 0;
            __syncthreads();
            for (int i = 0; i < 8; i++) {
                int chunk = t + 512 * i;
                if (chunk == pseudo) continue;
                const float4* p4 = (const float4*)(ri + 8 * chunk);
                float4 a = p4[0], c = p4[1];
                float vv[8] = {KSCALE*a.x, KSCALE*a.y, KSCALE*a.z, KSCALE*a.w,
                               KSCALE*c.x, KSCALE*c.y, KSCALE*c.z, KSCALE*c.w};
                for (int j = 0; j < 8; j++) {
                    if (vv[j] > pf) {
                        unsigned k = atomicAdd(&sh_cnt, 1u);
                        if (k < (unsigned)CAP) candv[k] = vv[j];
                    }
                }
            }
            __syncthreads();
        }
        int nc = (int)min(sh_cnt, (unsigned)CAP);

        float seC = 0.f;
        for (int i = t; i < nc; i += 512) {
            float x = candv[i];
            int r = 0;
            for (int j = 0; j < nc; j++) {
                float w2 = candv[j];
                r += (w2 > x) || (w2 == x && j < i);
            }
            if (r < BGK) seC += __expf(x - M);
        }
        if (t < 8) seC += __expf(sposv[t] - M);
        float sumC = blockSumF(seC, s16, t);

        float seI = 0.f;
#pragma unroll
        for (int i = 0; i < 8; i++) seI += __expf(vcam[i] - Mi);
        float sumI = blockSumF(seI, s16, t);

        if (t == 0) {
            float psum = 0.f;
            for (int k = 0; k < 8; k++) psum += sposv[k];
            g_loss[b]      = Mi + logf(sumI) - sposv[cam];
            g_loss[BN + b] = M  + logf(sumC) - psum * 0.125f;
        }
    } else {
        // ================= lossB: online on sims =================
        const int b = blockIdx.x;
        const float* rsm = g_sims  + (size_t)b * PN;
        const float* rsc = g_score + (size_t)b * PN;

        if (t == 0) { sh_cnt = 0; sh_nf = 3; }

        float bv[8]; int bi[8];
#pragma unroll
        for (int j = 0; j < 8; j++) { bv[j] = NEG_INF; bi[j] = 0x7fffffff; }
        float m = NEG_INF;
#pragma unroll
        for (int i = 0; i < 8; i++) {
            int chunk = t + 512 * i;
            const float4* p4 = (const float4*)(rsm + 8 * chunk);
            float4 a = p4[0], c = p4[1];
            float vv[8] = {a.x, a.y, a.z, a.w, c.x, c.y, c.z, c.w};
#pragma unroll
            for (int j = 0; j < 8; j++) {
                float x = vv[j];
                if (x > bv[j]) { bv[j] = x; bi[j] = 8 * chunk + j; }
                m = fmaxf(m, x);
            }
        }
        tmax[t] = m;

#pragma unroll
        for (int j = 0; j < 8; j++) {
            float x = bv[j]; int idx = bi[j];
            for (int o = 16; o > 0; o >>= 1) {
                float ov = __shfl_down_sync(0xffffffffu, x, o);
                int   oi = __shfl_down_sync(0xffffffffu, idx, o);
                if (ov > x || (ov == x && oi < idx)) { x = ov; idx = oi; }
            }
            if (lane == 0) { s_cv[j][wid] = x; s_ci[j][wid] = idx; }
        }
        __syncthreads();
        if (t == 0) {
            float cv[8]; int ci[8];
            for (int c = 0; c < 8; c++) {
                float bvv = NEG_INF; int bii = 0x7fffffff;
                for (int w2 = 0; w2 < 16; w2++) {
                    float x = s_cv[c][w2]; int idx = s_ci[c][w2];
                    if (x > bvv || (x == bvv && idx < bii)) { bvv = x; bii = idx; }
                }
                cv[c] = bvv; ci[c] = bii;
            }
            bool used[8] = {false,false,false,false,false,false,false,false};
            for (int k = 0; k < PKK; k++) {
                int bc = -1; float bvv = NEG_INF;
                for (int c = 0; c < 8; c++)
                    if (!used[c] && cv[c] > bvv) { bvv = cv[c]; bc = c; }
                used[bc] = true;
                chos[k] = ci[bc];
            }
            fin[0] = chos[0]; fin[1] = chos[1]; fin[2] = chos[2];
        }
        __syncthreads();
        int c0 = chos[0], c1 = chos[1], c2 = chos[2];

        warp0_pivot(tmax, t, BGK + PKK, &sh_pk, &sh_gm);
        float pf = unfkey(sh_pk);

#pragma unroll
        for (int i = 0; i < 8; i++) {
            int chunk = t + 512 * i;
            const float4* p4 = (const float4*)(rsm + 8 * chunk);
            float4 a = p4[0], c = p4[1];
            float vv[8] = {a.x, a.y, a.z, a.w, c.x, c.y, c.z, c.w};
#pragma unroll
            for (int j = 0; j < 8; j++) {
                int p = 8 * chunk + j;
                if (vv[j] > pf && p != c0 && p != c1 && p != c2) {
                    unsigned k = atomicAdd(&sh_cnt, 1u);
                    if (k < (unsigned)CAP) { candv[k] = vv[j]; candi[k] = p; }
                }
            }
        }
        __syncthreads();
        if (sh_cnt > (unsigned)CAP) {
            unsigned pk = sh_pk, pkhi = fkey(sh_gm);
            int cnt = (int)sh_cnt;
#pragma unroll 1
            while (cnt > CAP && pkhi - pk > 1u) {
                unsigned mid = pk + ((pkhi - pk) >> 1);
                float pm = unfkey(mid);
                int cacc = 0;
                for (int i = 0; i < 8; i++) {
                    int chunk = t + 512 * i;
                    const float4* p4 = (const float4*)(rsm + 8 * chunk);
                    float4 a = p4[0], c = p4[1];
                    float vv[8] = {a.x, a.y, a.z, a.w, c.x, c.y, c.z, c.w};
                    for (int j = 0; j < 8; j++) {
                        int p = 8 * chunk + j;
                        cacc += (vv[j] > pm && p != c0 && p != c1 && p != c2);
                    }
                }
                int t2 = blockSumI(cacc, si16, t);
                if (t2 >= BGK) { pk = mid; cnt = t2; }
                else pkhi = mid;
            }
            pf = unfkey(pk);
            __syncthreads();
            if (t == 0) sh_cnt = 0;
            __syncthreads();
            for (int i = 0; i < 8; i++) {
                int chunk = t + 512 * i;
                const float4* p4 = (const float4*)(rsm + 8 * chunk);
                float4 a = p4[0], c = p4[1];
                float vv[8] = {a.x, a.y, a.z, a.w, c.x, c.y, c.z, c.w};
                for (int j = 0; j < 8; j++) {
                    int p = 8 * chunk + j;
                    if (vv[j] > pf && p != c0 && p != c1 && p != c2) {
                        unsigned k = atomicAdd(&sh_cnt, 1u);
                        if (k < (unsigned)CAP) { candv[k] = vv[j]; candi[k] = p; }
                    }
                }
            }
            __syncthreads();
        }
        int nc = (int)min(sh_cnt, (unsigned)CAP);

        for (int i = t; i < nc; i += 512) {
            float x = candv[i]; int pi = candi[i];
            int r = 0;
            for (int j = 0; j < nc; j++) {
                float w2 = candv[j];
                r += (w2 > x) || (w2 == x && candi[j] < pi);
            }
            if (r < BGK) {
                unsigned k = atomicAdd(&sh_nf, 1u);
                if (k < 64u) fin[k] = pi;
            }
        }
        __syncthreads();
        int nf = (int)min(sh_nf, 64u);   // 53

        float val = (t < nf) ? KSCALE * rsc[fin[t]] : NEG_INF;
        float mo = blockMaxF(val, s16, t);
        float e  = (t < nf) ? __expf(val - mo) : 0.f;
        float se = blockSumF(e, s16, t);
        if (t == 0) {
            float csum = KSCALE * rsc[c0] + KSCALE * rsc[c1] + KSCALE * rsc[c2];
            g_loss[2 * BN + b] = mo + logf(se) - csum * (1.0f / 3.0f);
        }
    }
}

// ---------------- final reduction (warp per camera) ----------------
__global__ void k_final(const int* __restrict__ cams, float* __restrict__ out) {
    __shared__ float sv[256];
    __shared__ int   sc[256];
    __shared__ float s8[8];
    int t = threadIdx.x;
    int w = t >> 5, l = t & 31;
    sv[t] = g_loss[t] + g_loss[BN + t] + g_loss[2 * BN + t];
    sc[t] = cams[t];
    __syncthreads();
    {
        float acc = 0.f; int n = 0;
        for (int b = l; b < BN; b += 32) {
            if (sc[b] == w) { acc += sv[b]; n++; }
        }
        for (int o = 16; o > 0; o >>= 1) {
            acc += __shfl_xor_sync(0xffffffffu, acc, o);
            n   += __shfl_xor_sync(0xffffffffu, n, o);
        }
        if (l == 0) s8[w] = (n > 0) ? acc / (float)n : 0.f;
    }
    __syncthreads();
    if (t == 0) {
        float tot = 0.f;
        for (int c = 0; c < 8; c++) tot += s8[c];
        out[0] = tot;
    }
}

// ---------------- launch ----------------
extern "C" void kernel_launch(void* const* d_in, const int* in_sizes, int n_in,
                              void* d_out, int out_size) {
    const float* features        = (const float*)d_in[0];
    const int*   targets         = (const int*)d_in[1];
    const int*   cams            = (const int*)d_in[2];
    const float* global_memory   = (const float*)d_in[4];
    const int*   all_proxy_label = (const int*)d_in[6];
    float* out = (float*)d_out;

    cudaFuncSetAttribute(k_gemm_mma, cudaFuncAttributeMaxDynamicSharedMemorySize, SMEM_GEMM);

    k_prep<<<1024 + BN, 256>>>(features, targets, all_proxy_label, global_memory);
    dim3 gg(PN / 128, 2, 2);
    k_gemm_mma<<<gg, 256, SMEM_GEMM>>>();
    k_loss<<<2 * BN, 512>>>(cams);
    k_final<<<1, 256>>>(cams, out);
}

// round 13
// speedup vs baseline: 1.2780x; 1.0015x over previous
#include <cuda_runtime.h>
#include <cuda_bf16.h>
#include <math.h>
#include <stdint.h>

#define BN   256
#define PN   32768
#define DN   256
#define CN   8
#define KSCALE 20.0f
#define BGK  50
#define PKK  3
#define BALW 0.15f
#define CAP  768

#define NEG_INF (__int_as_float(0xff800000))

// ---------------- scratch ----------------
__device__ int   g_pseudo[BN];
__device__ __nv_bfloat16 g_Ahi[2 * BN * DN];   // rows 0..255 features, 256..511 blended
__device__ __nv_bfloat16 g_Alo[2 * BN * DN];
__device__ __nv_bfloat16 g_Bhi[(size_t)PN * DN];
__device__ __nv_bfloat16 g_Blo[(size_t)PN * DN];
__device__ float g_score[(size_t)BN * PN];
__device__ float g_sims [(size_t)BN * PN];
__device__ float g_loss[3 * BN];
__device__ unsigned g_done;                    // loss-block completion counter

// ---------------- PTX helpers ----------------
__device__ __forceinline__ uint32_t smem_u32(const void* p) {
    uint32_t a;
    asm("{ .reg .u64 t; cvta.to.shared.u64 t, %1; cvt.u32.u64 %0, t; }" : "=r"(a) : "l"(p));
    return a;
}
// 64B-row swizzle
#define SW64(off) ((off) ^ (((off) >> 3) & 0x30))
__device__ __forceinline__ void cp16(uint32_t dst, const void* src) {
    asm volatile("cp.async.cg.shared.global [%0], [%1], 16;" :: "r"(dst), "l"(src));
}
__device__ __forceinline__ void cp_commit() { asm volatile("cp.async.commit_group;"); }
template <int N>
__device__ __forceinline__ void cp_wait() { asm volatile("cp.async.wait_group %0;" :: "n"(N)); }

__device__ __forceinline__ void ldsm_x4(uint32_t addr, uint32_t& r0, uint32_t& r1,
                                        uint32_t& r2, uint32_t& r3) {
    asm volatile("ldmatrix.sync.aligned.m8n8.x4.shared.b16 {%0,%1,%2,%3}, [%4];"
        : "=r"(r0), "=r"(r1), "=r"(r2), "=r"(r3) : "r"(addr));
}
__device__ __forceinline__ void mma_bf16(float& c0, float& c1, float& c2, float& c3,
                                         uint32_t a0, uint32_t a1, uint32_t a2, uint32_t a3,
                                         uint32_t b0, uint32_t b1) {
    asm volatile("mma.sync.aligned.m16n8k16.row.col.f32.bf16.bf16.f32 "
        "{%0,%1,%2,%3}, {%4,%5,%6,%7}, {%8,%9}, {%0,%1,%2,%3};"
        : "+f"(c0), "+f"(c1), "+f"(c2), "+f"(c3)
        : "r"(a0), "r"(a1), "r"(a2), "r"(a3), "r"(b0), "r"(b1));
}

// ---------------- selection helpers ----------------
__device__ __forceinline__ unsigned fkey(float v) {
    unsigned u = __float_as_uint(v);
    return (u & 0x80000000u) ? ~u : (u | 0x80000000u);
}
__device__ __forceinline__ float unfkey(unsigned k) {
    unsigned u = (k & 0x80000000u) ? (k ^ 0x80000000u) : ~k;
    return __uint_as_float(u);
}
__device__ __forceinline__ float blockMaxF(float x, float* s16, int t) {
    int lane = t & 31, wid = t >> 5;
    for (int o = 16; o > 0; o >>= 1) x = fmaxf(x, __shfl_xor_sync(0xffffffffu, x, o));
    __syncthreads();
    if (lane == 0) s16[wid] = x;
    __syncthreads();
    if (t == 0) { float y = s16[0]; for (int w = 1; w < 16; w++) y = fmaxf(y, s16[w]); s16[0] = y; }
    __syncthreads();
    return s16[0];
}
__device__ __forceinline__ float blockSumF(float x, float* s16, int t) {
    int lane = t & 31, wid = t >> 5;
    for (int o = 16; o > 0; o >>= 1) x += __shfl_xor_sync(0xffffffffu, x, o);
    __syncthreads();
    if (lane == 0) s16[wid] = x;
    __syncthreads();
    if (t == 0) { float y = 0.f; for (int w = 0; w < 16; w++) y += s16[w]; s16[0] = y; }
    __syncthreads();
    return s16[0];
}
__device__ __forceinline__ int blockSumI(int x, int* s16, int t) {
    int lane = t & 31, wid = t >> 5;
    for (int o = 16; o > 0; o >>= 1) x += __shfl_xor_sync(0xffffffffu, x, o);
    __syncthreads();
    if (lane == 0) s16[wid] = x;
    __syncthreads();
    if (t == 0) { int y = 0; for (int w = 0; w < 16; w++) y += s16[w]; s16[0] = y; }
    __syncthreads();
    return s16[0];
}

// ---------------- K1: merged prep ----------------
__global__ __launch_bounds__(256) void k_prep(const float* __restrict__ features,
                                              const int* __restrict__ targets,
                                              const int* __restrict__ all_proxy_label,
                                              const float* __restrict__ mem) {
    int blk = blockIdx.x;
    int t = threadIdx.x;
    if (blk < 1024) {
        size_t base = (size_t)blk * 8192;
#pragma unroll
        for (int i = 0; i < 8; i++) {
            size_t off = base + (size_t)i * 1024 + t * 4;
            float4 f = *(const float4*)(mem + off);
            __nv_bfloat162 h01 = __floats2bfloat162_rn(f.x, f.y);
            __nv_bfloat162 h23 = __floats2bfloat162_rn(f.z, f.w);
            float lx = f.x - __bfloat162float(__low2bfloat16(h01));
            float ly = f.y - __bfloat162float(__high2bfloat16(h01));
            float lz = f.z - __bfloat162float(__low2bfloat16(h23));
            float lw = f.w - __bfloat162float(__high2bfloat16(h23));
            __nv_bfloat162 l01 = __floats2bfloat162_rn(lx, ly);
            __nv_bfloat162 l23 = __floats2bfloat162_rn(lz, lw);
            ((__nv_bfloat162*)(g_Bhi + off))[0] = h01;
            ((__nv_bfloat162*)(g_Bhi + off))[1] = h23;
            ((__nv_bfloat162*)(g_Blo + off))[0] = l01;
            ((__nv_bfloat162*)(g_Blo + off))[1] = l23;
        }
    } else {
        int b = blk - 1024;
        int tgt = targets[b];
        int prx = all_proxy_label[tgt];
        if (t == 0) g_pseudo[b] = prx / CN;
        if (blk == 1024 && t == 1) g_done = 0;   // reset fused-final counter
        float f = features[b * DN + t];
        __nv_bfloat16 fh = __float2bfloat16_rn(f);
        g_Ahi[b * DN + t] = fh;
        g_Alo[b * DN + t] = __float2bfloat16_rn(f - __bfloat162float(fh));
        float m = mem[(size_t)prx * DN + t];
        float bl = BALW * f + (1.0f - BALW) * m;
        __nv_bfloat16 bh = __float2bfloat16_rn(bl);
        g_Ahi[(BN + b) * DN + t] = bh;
        g_Alo[(BN + b) * DN + t] = __float2bfloat16_rn(bl - __bfloat162float(bh));
    }
}

// ---------------- K2: mma.sync bf16 3-term GEMM (R12, proven) --------------
#define KCH 32
#define STAGE_SZ 32768
#define SMEM_GEMM (3 * STAGE_SZ)

__global__ __launch_bounds__(256, 2) void k_gemm_mma() {
    extern __shared__ char smem[];
    const uint32_t sb = smem_u32(smem);
    const int t = threadIdx.x;
    const int lane = t & 31, w = t >> 5;
    const int warp_m = w >> 2, warp_n = w & 3;
    const int n0 = blockIdx.x * 128;
    const int m0 = blockIdx.y * 128;
    const int z  = blockIdx.z;
    const int arow_base = (z ? BN : 0) + m0;

    float acc[4][4][4];
#pragma unroll
    for (int i = 0; i < 4; i++)
#pragma unroll
        for (int j = 0; j < 4; j++)
#pragma unroll
            for (int q = 0; q < 4; q++) acc[i][j][q] = 0.f;

    const int cprow = t >> 2;
    const int cpu   = t & 3;

#define ISSUE(c, s)                                                                    \
    {                                                                                  \
        int k0 = (c) * KCH;                                                            \
        uint32_t st = sb + (s) * STAGE_SZ;                                             \
        _Pragma("unroll")                                                              \
        for (int j = 0; j < 2; j++) {                                                  \
            int row = cprow + 64 * j;                                                  \
            uint32_t d = SW64((uint32_t)(row * 64 + cpu * 16));                        \
            cp16(st + d,         g_Ahi + (size_t)(arow_base + row) * DN + k0 + cpu * 8); \
            cp16(st + 8192 + d,  g_Alo + (size_t)(arow_base + row) * DN + k0 + cpu * 8); \
            cp16(st + 16384 + d, g_Bhi + (size_t)(n0 + row) * DN + k0 + cpu * 8);      \
            cp16(st + 24576 + d, g_Blo + (size_t)(n0 + row) * DN + k0 + cpu * 8);      \
        }                                                                              \
        cp_commit();                                                                   \
    }

#define COMPUTE(s)                                                                     \
    {                                                                                  \
        uint32_t stAh = sb + (s) * STAGE_SZ;                                           \
        uint32_t stAl = stAh + 8192;                                                   \
        uint32_t stBh = stAh + 16384;                                                  \
        uint32_t stBl = stAh + 24576;                                                  \
        const int arow = warp_m * 64 + (lane & 15);                                    \
        const int acolb = (lane >> 4) << 4;                                            \
        const int brow = warp_n * 32 + (lane & 7) + ((lane >> 4) << 3);                \
        const int bcolb = ((lane >> 3) & 1) << 4;                                      \
        _Pragma("unroll")                                                              \
        for (int ks = 0; ks < 2; ks++) {                                               \
            uint32_t bh[4][2], bl[4][2];                                               \
            _Pragma("unroll")                                                          \
            for (int h = 0; h < 2; h++) {                                              \
                uint32_t off = SW64((uint32_t)((brow + h * 16) * 64 + ks * 32 + bcolb)); \
                uint32_t r0, r1, r2, r3;                                               \
                ldsm_x4(stBh + off, r0, r1, r2, r3);                                   \
                bh[h*2][0] = r0; bh[h*2][1] = r1; bh[h*2+1][0] = r2; bh[h*2+1][1] = r3;\
                ldsm_x4(stBl + off, r0, r1, r2, r3);                                   \
                bl[h*2][0] = r0; bl[h*2][1] = r1; bl[h*2+1][0] = r2; bl[h*2+1][1] = r3;\
            }                                                                          \
            _Pragma("unroll")                                                          \
            for (int mf = 0; mf < 4; mf++) {                                           \
                uint32_t ah0, ah1, ah2, ah3, al0, al1, al2, al3;                       \
                uint32_t off = SW64((uint32_t)((arow + mf * 16) * 64 + ks * 32 + acolb)); \
                ldsm_x4(stAh + off, ah0, ah1, ah2, ah3);                               \
                ldsm_x4(stAl + off, al0, al1, al2, al3);                               \
                _Pragma("unroll")                                                      \
                for (int nf = 0; nf < 4; nf++) {                                       \
                    mma_bf16(acc[mf][nf][0], acc[mf][nf][1], acc[mf][nf][2], acc[mf][nf][3], \
                             ah0, ah1, ah2, ah3, bh[nf][0], bh[nf][1]);                \
                    mma_bf16(acc[mf][nf][0], acc[mf][nf][1], acc[mf][nf][2], acc[mf][nf][3], \
                             ah0, ah1, ah2, ah3, bl[nf][0], bl[nf][1]);                \
                    mma_bf16(acc[mf][nf][0], acc[mf][nf][1], acc[mf][nf][2], acc[mf][nf][3], \
                             al0, al1, al2, al3, bh[nf][0], bh[nf][1]);                \
                }                                                                      \
            }                                                                          \
        }                                                                              \
    }

    ISSUE(0, 0); ISSUE(1, 1); ISSUE(2, 2);

    cp_wait<2>(); __syncthreads(); COMPUTE(0); __syncthreads(); ISSUE(3, 0);
    cp_wait<2>(); __syncthreads(); COMPUTE(1); __syncthreads(); ISSUE(4, 1);
    cp_wait<2>(); __syncthreads(); COMPUTE(2); __syncthreads(); ISSUE(5, 2);
    cp_wait<2>(); __syncthreads(); COMPUTE(0); __syncthreads(); ISSUE(6, 0);
    cp_wait<2>(); __syncthreads(); COMPUTE(1); __syncthreads(); ISSUE(7, 1);
    cp_wait<2>(); __syncthreads(); COMPUTE(2);
    cp_wait<1>(); __syncthreads(); COMPUTE(0);
    cp_wait<0>(); __syncthreads(); COMPUTE(1);

    float* outp = (z == 0) ? g_score : g_sims;
    const int gr = lane >> 2;
    const int gc = (lane & 3) * 2;
#pragma unroll
    for (int mf = 0; mf < 4; mf++) {
#pragma unroll
        for (int nf = 0; nf < 4; nf++) {
            int r0 = m0 + warp_m * 64 + mf * 16 + gr;
            int col = n0 + warp_n * 32 + nf * 8 + gc;
            float2 v0 = make_float2(acc[mf][nf][0], acc[mf][nf][1]);
            float2 v1 = make_float2(acc[mf][nf][2], acc[mf][nf][3]);
            *(float2*)(outp + (size_t)r0 * PN + col)       = v0;
            *(float2*)(outp + (size_t)(r0 + 8) * PN + col) = v1;
        }
    }
}

// warp0-only: exact kth-largest of 512 shared values via key bisection.
__device__ __forceinline__ void warp0_pivot(const float* tmax, int t, int kth,
                                            unsigned* sh_pk, float* sh_gm) {
    if (t < 32) {
        float m16[16];
#pragma unroll
        for (int k = 0; k < 16; k++) m16[k] = tmax[t + 32 * k];
        float gm = m16[0];
#pragma unroll
        for (int k = 1; k < 16; k++) gm = fmaxf(gm, m16[k]);
        for (int o = 16; o > 0; o >>= 1) gm = fmaxf(gm, __shfl_xor_sync(0xffffffffu, gm, o));
        unsigned klo = 0u, khi = fkey(gm);
#pragma unroll 1
        for (int it = 0; it < 32; it++) {
            if (khi - klo <= 1u) break;
            unsigned mid = klo + ((khi - klo) >> 1);
            float pm = unfkey(mid);
            int c = 0;
#pragma unroll
            for (int k = 0; k < 16; k++) c += (m16[k] > pm);
            for (int o = 16; o > 0; o >>= 1) c += __shfl_xor_sync(0xffffffffu, c, o);
            if (c >= kth) klo = mid; else khi = mid;
        }
        if (t == 0) { *sh_pk = klo; *sh_gm = gm; }
    }
    __syncthreads();
}

// ---------------- merged loss kernel + fused final reduction ---------------
__global__ __launch_bounds__(512, 2) void k_loss(const int* __restrict__ cams,
                                                 float* __restrict__ out) {
    __shared__ float s16[16];
    __shared__ int   si16[16];
    __shared__ float tmax[512];
    __shared__ float candv[CAP];
    __shared__ int   candi[CAP];
    __shared__ float sposv[8];
    __shared__ float s_cv[8][16];
    __shared__ int   s_ci[8][16];
    __shared__ int   chos[3];
    __shared__ int   fin[64];
    __shared__ unsigned sh_pk;
    __shared__ float sh_gm;
    __shared__ unsigned sh_cnt, sh_nf;
    __shared__ unsigned sh_rank;

    const int t = threadIdx.x;
    const int lane = t & 31, wid = t >> 5;

    if (blockIdx.x >= BN) {
        // ================= lossA: intra + cross on score =================
        const int b = blockIdx.x - BN;
        const float* ri = g_score + (size_t)b * PN;
        const int pseudo = g_pseudo[b];
        const int cam = cams[b];

        if (t == 0) sh_cnt = 0;
        if (t < 8) sposv[t] = KSCALE * ri[pseudo * 8 + t];

        float vcam[8];
        float m = NEG_INF;
#pragma unroll
        for (int i = 0; i < 8; i++) {
            int chunk = t + 512 * i;
            const float4* p4 = (const float4*)(ri + 8 * chunk);
            float4 a = p4[0], c = p4[1];
            a.x *= KSCALE; a.y *= KSCALE; a.z *= KSCALE; a.w *= KSCALE;
            c.x *= KSCALE; c.y *= KSCALE; c.z *= KSCALE; c.w *= KSCALE;
            float sel = (cam < 4) ? ((cam < 2) ? (cam == 0 ? a.x : a.y)
                                               : (cam == 2 ? a.z : a.w))
                                  : ((cam < 6) ? (cam == 4 ? c.x : c.y)
                                               : (cam == 6 ? c.z : c.w));
            vcam[i] = sel;
            if (chunk != pseudo) {
                m = fmaxf(m, fmaxf(fmaxf(a.x, a.y), fmaxf(a.z, a.w)));
                m = fmaxf(m, fmaxf(fmaxf(c.x, c.y), fmaxf(c.z, c.w)));
            }
        }
        tmax[t] = m;
        float mi = vcam[0];
#pragma unroll
        for (int i = 1; i < 8; i++) mi = fmaxf(mi, vcam[i]);
        float Mi = blockMaxF(mi, s16, t);

        warp0_pivot(tmax, t, BGK, &sh_pk, &sh_gm);
        float M = sh_gm;
#pragma unroll
        for (int k = 0; k < 8; k++) M = fmaxf(M, sposv[k]);
        float pf = unfkey(sh_pk);

#pragma unroll
        for (int i = 0; i < 8; i++) {
            int chunk = t + 512 * i;
            if (chunk == pseudo) continue;
            const float4* p4 = (const float4*)(ri + 8 * chunk);
            float4 a = p4[0], c = p4[1];
            float vv[8] = {KSCALE*a.x, KSCALE*a.y, KSCALE*a.z, KSCALE*a.w,
                           KSCALE*c.x, KSCALE*c.y, KSCALE*c.z, KSCALE*c.w};
#pragma unroll
            for (int j = 0; j < 8; j++) {
                if (vv[j] > pf) {
                    unsigned k = atomicAdd(&sh_cnt, 1u);
                    if (k < (unsigned)CAP) candv[k] = vv[j];
                }
            }
        }
        __syncthreads();
        if (sh_cnt > (unsigned)CAP) {
            unsigned pk = sh_pk, pkhi = fkey(sh_gm);
            int cnt = (int)sh_cnt;
#pragma unroll 1
            while (cnt > CAP && pkhi - pk > 1u) {
                unsigned mid = pk + ((pkhi - pk) >> 1);
                float pm = unfkey(mid);
                int c2 = 0;
                for (int i = 0; i < 8; i++) {
                    int chunk = t + 512 * i;
                    if (chunk == pseudo) continue;
                    const float4* p4 = (const float4*)(ri + 8 * chunk);
                    float4 a = p4[0], c = p4[1];
                    c2 += (KSCALE*a.x > pm) + (KSCALE*a.y > pm) + (KSCALE*a.z > pm) + (KSCALE*a.w > pm)
                        + (KSCALE*c.x > pm) + (KSCALE*c.y > pm) + (KSCALE*c.z > pm) + (KSCALE*c.w > pm);
                }
                int t2 = blockSumI(c2, si16, t);
                if (t2 >= BGK) { pk = mid; cnt = t2; }
                else pkhi = mid;
            }
            pf = unfkey(pk);
            __syncthreads();
            if (t == 0) sh_cnt = 0;
            __syncthreads();
            for (int i = 0; i < 8; i++) {
                int chunk = t + 512 * i;
                if (chunk == pseudo) continue;
                const float4* p4 = (const float4*)(ri + 8 * chunk);
                float4 a = p4[0], c = p4[1];
                float vv[8] = {KSCALE*a.x, KSCALE*a.y, KSCALE*a.z, KSCALE*a.w,
                               KSCALE*c.x, KSCALE*c.y, KSCALE*c.z, KSCALE*c.w};
                for (int j = 0; j < 8; j++) {
                    if (vv[j] > pf) {
                        unsigned k = atomicAdd(&sh_cnt, 1u);
                        if (k < (unsigned)CAP) candv[k] = vv[j];
                    }
                }
            }
            __syncthreads();
        }
        int nc = (int)min(sh_cnt, (unsigned)CAP);

        float seC = 0.f;
        for (int i = t; i < nc; i += 512) {
            float x = candv[i];
            int r = 0;
            for (int j = 0; j < nc; j++) {
                float w2 = candv[j];
                r += (w2 > x) || (w2 == x && j < i);
            }
            if (r < BGK) seC += __expf(x - M);
        }
        if (t < 8) seC += __expf(sposv[t] - M);
        float sumC = blockSumF(seC, s16, t);

        float seI = 0.f;
#pragma unroll
        for (int i = 0; i < 8; i++) seI += __expf(vcam[i] - Mi);
        float sumI = blockSumF(seI, s16, t);

        if (t == 0) {
            float psum = 0.f;
            for (int k = 0; k < 8; k++) psum += sposv[k];
            g_loss[b]      = Mi + logf(sumI) - sposv[cam];
            g_loss[BN + b] = M  + logf(sumC) - psum * 0.125f;
        }
    } else {
        // ================= lossB: online on sims =================
        const int b = blockIdx.x;
        const float* rsm = g_sims  + (size_t)b * PN;
        const float* rsc = g_score + (size_t)b * PN;

        if (t == 0) { sh_cnt = 0; sh_nf = 3; }

        float bv[8]; int bi[8];
#pragma unroll
        for (int j = 0; j < 8; j++) { bv[j] = NEG_INF; bi[j] = 0x7fffffff; }
        float m = NEG_INF;
#pragma unroll
        for (int i = 0; i < 8; i++) {
            int chunk = t + 512 * i;
            const float4* p4 = (const float4*)(rsm + 8 * chunk);
            float4 a = p4[0], c = p4[1];
            float vv[8] = {a.x, a.y, a.z, a.w, c.x, c.y, c.z, c.w};
#pragma unroll
            for (int j = 0; j < 8; j++) {
                float x = vv[j];
                if (x > bv[j]) { bv[j] = x; bi[j] = 8 * chunk + j; }
                m = fmaxf(m, x);
            }
        }
        tmax[t] = m;

#pragma unroll
        for (int j = 0; j < 8; j++) {
            float x = bv[j]; int idx = bi[j];
            for (int o = 16; o > 0; o >>= 1) {
                float ov = __shfl_down_sync(0xffffffffu, x, o);
                int   oi = __shfl_down_sync(0xffffffffu, idx, o);
                if (ov > x || (ov == x && oi < idx)) { x = ov; idx = oi; }
            }
            if (lane == 0) { s_cv[j][wid] = x; s_ci[j][wid] = idx; }
        }
        __syncthreads();
        if (t == 0) {
            float cv[8]; int ci[8];
            for (int c = 0; c < 8; c++) {
                float bvv = NEG_INF; int bii = 0x7fffffff;
                for (int w2 = 0; w2 < 16; w2++) {
                    float x = s_cv[c][w2]; int idx = s_ci[c][w2];
                    if (x > bvv || (x == bvv && idx < bii)) { bvv = x; bii = idx; }
                }
                cv[c] = bvv; ci[c] = bii;
            }
            bool used[8] = {false,false,false,false,false,false,false,false};
            for (int k = 0; k < PKK; k++) {
                int bc = -1; float bvv = NEG_INF;
                for (int c = 0; c < 8; c++)
                    if (!used[c] && cv[c] > bvv) { bvv = cv[c]; bc = c; }
                used[bc] = true;
                chos[k] = ci[bc];
            }
            fin[0] = chos[0]; fin[1] = chos[1]; fin[2] = chos[2];
        }
        __syncthreads();
        int c0 = chos[0], c1 = chos[1], c2 = chos[2];

        warp0_pivot(tmax, t, BGK + PKK, &sh_pk, &sh_gm);
        float pf = unfkey(sh_pk);

#pragma unroll
        for (int i = 0; i < 8; i++) {
            int chunk = t + 512 * i;
            const float4* p4 = (const float4*)(rsm + 8 * chunk);
            float4 a = p4[0], c = p4[1];
            float vv[8] = {a.x, a.y, a.z, a.w, c.x, c.y, c.z, c.w};
#pragma unroll
            for (int j = 0; j < 8; j++) {
                int p = 8 * chunk + j;
                if (vv[j] > pf && p != c0 && p != c1 && p != c2) {
                    unsigned k = atomicAdd(&sh_cnt, 1u);
                    if (k < (unsigned)CAP) { candv[k] = vv[j]; candi[k] = p; }
                }
            }
        }
        __syncthreads();
        if (sh_cnt > (unsigned)CAP) {
            unsigned pk = sh_pk, pkhi = fkey(sh_gm);
            int cnt = (int)sh_cnt;
#pragma unroll 1
            while (cnt > CAP && pkhi - pk > 1u) {
                unsigned mid = pk + ((pkhi - pk) >> 1);
                float pm = unfkey(mid);
                int cacc = 0;
                for (int i = 0; i < 8; i++) {
                    int chunk = t + 512 * i;
                    const float4* p4 = (const float4*)(rsm + 8 * chunk);
                    float4 a = p4[0], c = p4[1];
                    float vv[8] = {a.x, a.y, a.z, a.w, c.x, c.y, c.z, c.w};
                    for (int j = 0; j < 8; j++) {
                        int p = 8 * chunk + j;
                        cacc += (vv[j] > pm && p != c0 && p != c1 && p != c2);
                    }
                }
                int t2 = blockSumI(cacc, si16, t);
                if (t2 >= BGK) { pk = mid; cnt = t2; }
                else pkhi = mid;
            }
            pf = unfkey(pk);
            __syncthreads();
            if (t == 0) sh_cnt = 0;
            __syncthreads();
            for (int i = 0; i < 8; i++) {
                int chunk = t + 512 * i;
                const float4* p4 = (const float4*)(rsm + 8 * chunk);
                float4 a = p4[0], c = p4[1];
                float vv[8] = {a.x, a.y, a.z, a.w, c.x, c.y, c.z, c.w};
                for (int j = 0; j < 8; j++) {
                    int p = 8 * chunk + j;
                    if (vv[j] > pf && p != c0 && p != c1 && p != c2) {
                        unsigned k = atomicAdd(&sh_cnt, 1u);
                        if (k < (unsigned)CAP) { candv[k] = vv[j]; candi[k] = p; }
                    }
                }
            }
            __syncthreads();
        }
        int nc = (int)min(sh_cnt, (unsigned)CAP);

        for (int i = t; i < nc; i += 512) {
            float x = candv[i]; int pi = candi[i];
            int r = 0;
            for (int j = 0; j < nc; j++) {
                float w2 = candv[j];
                r += (w2 > x) || (w2 == x && candi[j] < pi);
            }
            if (r < BGK) {
                unsigned k = atomicAdd(&sh_nf, 1u);
                if (k < 64u) fin[k] = pi;
            }
        }
        __syncthreads();
        int nf = (int)min(sh_nf, 64u);   // 53

        float val = (t < nf) ? KSCALE * rsc[fin[t]] : NEG_INF;
        float mo = blockMaxF(val, s16, t);
        float e  = (t < nf) ? __expf(val - mo) : 0.f;
        float se = blockSumF(e, s16, t);
        if (t == 0) {
            float csum = KSCALE * rsc[c0] + KSCALE * rsc[c1] + KSCALE * rsc[c2];
            g_loss[2 * BN + b] = mo + logf(se) - csum * (1.0f / 3.0f);
        }
    }

    // ============ fused final reduction (last block to finish) ============
    __syncthreads();
    if (t == 0) {
        __threadfence();
        sh_rank = atomicAdd(&g_done, 1u);
    }
    __syncthreads();
    if (sh_rank == 2u * BN - 1u) {
        __threadfence();
        if (t < 256) {
            tmax[t]  = g_loss[t] + g_loss[BN + t] + g_loss[2 * BN + t];
            si16[0]  = 0;   // dummy
        }
        // reuse candi[0..255] for cams
        if (t < 256) candi[t] = cams[t];
        __syncthreads();
        if (t < 256) {
            int w2 = t >> 5, l2 = t & 31;
            float acc = 0.f; int n = 0;
            for (int b2 = l2; b2 < BN; b2 += 32) {
                if (candi[b2] == w2) { acc += tmax[b2]; n++; }
            }
            for (int o = 16; o > 0; o >>= 1) {
                acc += __shfl_xor_sync(0xffffffffu, acc, o);
                n   += __shfl_xor_sync(0xffffffffu, n, o);
            }
            if (l2 == 0) s_cv[0][w2] = (n > 0) ? acc / (float)n : 0.f;
        }
        __syncthreads();
        if (t == 0) {
            float tot = 0.f;
            for (int c = 0; c < 8; c++) tot += s_cv[0][c];
            out[0] = tot;
        }
    }
}

// ---------------- launch ----------------
extern "C" void kernel_launch(void* const* d_in, const int* in_sizes, int n_in,
                              void* d_out, int out_size) {
    const float* features        = (const float*)d_in[0];
    const int*   targets         = (const int*)d_in[1];
    const int*   cams            = (const int*)d_in[2];
    const float* global_memory   = (const float*)d_in[4];
    const int*   all_proxy_label = (const int*)d_in[6];
    float* out = (float*)d_out;

    cudaFuncSetAttribute(k_gemm_mma, cudaFuncAttributeMaxDynamicSharedMemorySize, SMEM_GEMM);

    k_prep<<<1024 + BN, 256>>>(features, targets, all_proxy_label, global_memory);
    dim3 gg(PN / 128, 2, 2);
    k_gemm_mma<<<gg, 256, SMEM_GEMM>>>();
    k_loss<<<2 * BN, 512>>>(cams, out);
}

// round 15
// speedup vs baseline: 1.2793x; 1.0010x over previous
#include <cuda_runtime.h>
#include <cuda_bf16.h>
#include <math.h>
#include <stdint.h>

#define BN   256
#define PN   32768
#define DN   256
#define CN   8
#define KSCALE 20.0f
#define BGK  50
#define PKK  3
#define BALW 0.15f
#define CAP  768

#define NEG_INF (__int_as_float(0xff800000))

// ---------------- scratch ----------------
__device__ int   g_pseudo[BN];
__device__ __nv_bfloat16 g_Ahi[2 * BN * DN];   // rows 0..255 features, 256..511 blended
__device__ __nv_bfloat16 g_Alo[2 * BN * DN];
__device__ __nv_bfloat16 g_Bhi[(size_t)PN * DN];
__device__ __nv_bfloat16 g_Blo[(size_t)PN * DN];
__device__ float g_score[(size_t)BN * PN];
__device__ float g_sims [(size_t)BN * PN];
__device__ float g_loss[3 * BN];
__device__ unsigned g_done;

// ---------------- PTX helpers ----------------
__device__ __forceinline__ uint32_t smem_u32(const void* p) {
    uint32_t a;
    asm("{ .reg .u64 t; cvta.to.shared.u64 t, %1; cvt.u32.u64 %0, t; }" : "=r"(a) : "l"(p));
    return a;
}
#define SW64(off) ((off) ^ (((off) >> 3) & 0x30))
__device__ __forceinline__ void cp16(uint32_t dst, const void* src) {
    asm volatile("cp.async.cg.shared.global [%0], [%1], 16;" :: "r"(dst), "l"(src));
}
__device__ __forceinline__ void cp_commit() { asm volatile("cp.async.commit_group;"); }
template <int N>
__device__ __forceinline__ void cp_wait() { asm volatile("cp.async.wait_group %0;" :: "n"(N)); }

__device__ __forceinline__ void ldsm_x4(uint32_t addr, uint32_t& r0, uint32_t& r1,
                                        uint32_t& r2, uint32_t& r3) {
    asm volatile("ldmatrix.sync.aligned.m8n8.x4.shared.b16 {%0,%1,%2,%3}, [%4];"
        : "=r"(r0), "=r"(r1), "=r"(r2), "=r"(r3) : "r"(addr));
}
__device__ __forceinline__ void mma_bf16(float& c0, float& c1, float& c2, float& c3,
                                         uint32_t a0, uint32_t a1, uint32_t a2, uint32_t a3,
                                         uint32_t b0, uint32_t b1) {
    asm volatile("mma.sync.aligned.m16n8k16.row.col.f32.bf16.bf16.f32 "
        "{%0,%1,%2,%3}, {%4,%5,%6,%7}, {%8,%9}, {%0,%1,%2,%3};"
        : "+f"(c0), "+f"(c1), "+f"(c2), "+f"(c3)
        : "r"(a0), "r"(a1), "r"(a2), "r"(a3), "r"(b0), "r"(b1));
}
__device__ __forceinline__ unsigned bf2_as_u32(__nv_bfloat162 h) {
    return *(const unsigned*)&h;
}

// ---------------- selection helpers ----------------
__device__ __forceinline__ unsigned fkey(float v) {
    unsigned u = __float_as_uint(v);
    return (u & 0x80000000u) ? ~u : (u | 0x80000000u);
}
__device__ __forceinline__ float unfkey(unsigned k) {
    unsigned u = (k & 0x80000000u) ? (k ^ 0x80000000u) : ~k;
    return __uint_as_float(u);
}
__device__ __forceinline__ float blockMaxF(float x, float* s16, int t) {
    int lane = t & 31, wid = t >> 5;
    for (int o = 16; o > 0; o >>= 1) x = fmaxf(x, __shfl_xor_sync(0xffffffffu, x, o));
    __syncthreads();
    if (lane == 0) s16[wid] = x;
    __syncthreads();
    if (t == 0) { float y = s16[0]; for (int w = 1; w < 16; w++) y = fmaxf(y, s16[w]); s16[0] = y; }
    __syncthreads();
    return s16[0];
}
__device__ __forceinline__ float blockSumF(float x, float* s16, int t) {
    int lane = t & 31, wid = t >> 5;
    for (int o = 16; o > 0; o >>= 1) x += __shfl_xor_sync(0xffffffffu, x, o);
    __syncthreads();
    if (lane == 0) s16[wid] = x;
    __syncthreads();
    if (t == 0) { float y = 0.f; for (int w = 0; w < 16; w++) y += s16[w]; s16[0] = y; }
    __syncthreads();
    return s16[0];
}
__device__ __forceinline__ int blockSumI(int x, int* s16, int t) {
    int lane = t & 31, wid = t >> 5;
    for (int o = 16; o > 0; o >>= 1) x += __shfl_xor_sync(0xffffffffu, x, o);
    __syncthreads();
    if (lane == 0) s16[wid] = x;
    __syncthreads();
    if (t == 0) { int y = 0; for (int w = 0; w < 16; w++) y += s16[w]; s16[0] = y; }
    __syncthreads();
    return s16[0];
}

// ---------------- K1: merged prep (vectorized B conversion) ----------------
__global__ __launch_bounds__(256) void k_prep(const float* __restrict__ features,
                                              const int* __restrict__ targets,
                                              const int* __restrict__ all_proxy_label,
                                              const float* __restrict__ mem) {
    int blk = blockIdx.x;
    int t = threadIdx.x;
    if (blk < 1024) {
        // B conversion: each thread handles 8 consecutive floats x 4 iterations.
        size_t base = (size_t)blk * 8192;
#pragma unroll
        for (int i = 0; i < 4; i++) {
            size_t off = base + (size_t)i * 2048 + t * 8;
            float4 f0 = *(const float4*)(mem + off);
            float4 f1 = *(const float4*)(mem + off + 4);
            __nv_bfloat162 h0 = __floats2bfloat162_rn(f0.x, f0.y);
            __nv_bfloat162 h1 = __floats2bfloat162_rn(f0.z, f0.w);
            __nv_bfloat162 h2 = __floats2bfloat162_rn(f1.x, f1.y);
            __nv_bfloat162 h3 = __floats2bfloat162_rn(f1.z, f1.w);
            __nv_bfloat162 l0 = __floats2bfloat162_rn(f0.x - __bfloat162float(__low2bfloat16(h0)),
                                                      f0.y - __bfloat162float(__high2bfloat16(h0)));
            __nv_bfloat162 l1 = __floats2bfloat162_rn(f0.z - __bfloat162float(__low2bfloat16(h1)),
                                                      f0.w - __bfloat162float(__high2bfloat16(h1)));
            __nv_bfloat162 l2 = __floats2bfloat162_rn(f1.x - __bfloat162float(__low2bfloat16(h2)),
                                                      f1.y - __bfloat162float(__high2bfloat16(h2)));
            __nv_bfloat162 l3 = __floats2bfloat162_rn(f1.z - __bfloat162float(__low2bfloat16(h3)),
                                                      f1.w - __bfloat162float(__high2bfloat16(h3)));
            uint4 hv, lv;
            hv.x = bf2_as_u32(h0); hv.y = bf2_as_u32(h1);
            hv.z = bf2_as_u32(h2); hv.w = bf2_as_u32(h3);
            lv.x = bf2_as_u32(l0); lv.y = bf2_as_u32(l1);
            lv.z = bf2_as_u32(l2); lv.w = bf2_as_u32(l3);
            *(uint4*)(g_Bhi + off) = hv;
            *(uint4*)(g_Blo + off) = lv;
        }
    } else {
        int b = blk - 1024;
        int tgt = targets[b];
        int prx = all_proxy_label[tgt];
        if (t == 0) g_pseudo[b] = prx / CN;
        if (blk == 1024 && t == 1) g_done = 0;
        float f = features[b * DN + t];
        __nv_bfloat16 fh = __float2bfloat16_rn(f);
        g_Ahi[b * DN + t] = fh;
        g_Alo[b * DN + t] = __float2bfloat16_rn(f - __bfloat162float(fh));
        float m = mem[(size_t)prx * DN + t];
        float bl = BALW * f + (1.0f - BALW) * m;
        __nv_bfloat16 bh = __float2bfloat16_rn(bl);
        g_Ahi[(BN + b) * DN + t] = bh;
        g_Alo[(BN + b) * DN + t] = __float2bfloat16_rn(bl - __bfloat162float(bh));
    }
}

// ---------------- K2: mma.sync bf16 3-term GEMM (R12, proven) --------------
#define KCH 32
#define STAGE_SZ 32768
#define SMEM_GEMM (3 * STAGE_SZ)

__global__ __launch_bounds__(256, 2) void k_gemm_mma() {
    extern __shared__ char smem[];
    const uint32_t sb = smem_u32(smem);
    const int t = threadIdx.x;
    const int lane = t & 31, w = t >> 5;
    const int warp_m = w >> 2, warp_n = w & 3;
    const int n0 = blockIdx.x * 128;
    const int m0 = blockIdx.y * 128;
    const int z  = blockIdx.z;
    const int arow_base = (z ? BN : 0) + m0;

    float acc[4][4][4];
#pragma unroll
    for (int i = 0; i < 4; i++)
#pragma unroll
        for (int j = 0; j < 4; j++)
#pragma unroll
            for (int q = 0; q < 4; q++) acc[i][j][q] = 0.f;

    const int cprow = t >> 2;
    const int cpu   = t & 3;

#define ISSUE(c, s)                                                                    \
    {                                                                                  \
        int k0 = (c) * KCH;                                                            \
        uint32_t st = sb + (s) * STAGE_SZ;                                             \
        _Pragma("unroll")                                                              \
        for (int j = 0; j < 2; j++) {                                                  \
            int row = cprow + 64 * j;                                                  \
            uint32_t d = SW64((uint32_t)(row * 64 + cpu * 16));                        \
            cp16(st + d,         g_Ahi + (size_t)(arow_base + row) * DN + k0 + cpu * 8); \
            cp16(st + 8192 + d,  g_Alo + (size_t)(arow_base + row) * DN + k0 + cpu * 8); \
            cp16(st + 16384 + d, g_Bhi + (size_t)(n0 + row) * DN + k0 + cpu * 8);      \
            cp16(st + 24576 + d, g_Blo + (size_t)(n0 + row) * DN + k0 + cpu * 8);      \
        }                                                                              \
        cp_commit();                                                                   \
    }

#define COMPUTE(s)                                                                     \
    {                                                                                  \
        uint32_t stAh = sb + (s) * STAGE_SZ;                                           \
        uint32_t stAl = stAh + 8192;                                                   \
        uint32_t stBh = stAh + 16384;                                                  \
        uint32_t stBl = stAh + 24576;                                                  \
        const int arow = warp_m * 64 + (lane & 15);                                    \
        const int acolb = (lane >> 4) << 4;                                            \
        const int brow = warp_n * 32 + (lane & 7) + ((lane >> 4) << 3);                \
        const int bcolb = ((lane >> 3) & 1) << 4;                                      \
        _Pragma("unroll")                                                              \
        for (int ks = 0; ks < 2; ks++) {                                               \
            uint32_t bh[4][2], bl[4][2];                                               \
            _Pragma("unroll")                                                          \
            for (int h = 0; h < 2; h++) {                                              \
                uint32_t off = SW64((uint32_t)((brow + h * 16) * 64 + ks * 32 + bcolb)); \
                uint32_t r0, r1, r2, r3;                                               \
                ldsm_x4(stBh + off, r0, r1, r2, r3);                                   \
                bh[h*2][0] = r0; bh[h*2][1] = r1; bh[h*2+1][0] = r2; bh[h*2+1][1] = r3;\
                ldsm_x4(stBl + off, r0, r1, r2, r3);                                   \
                bl[h*2][0] = r0; bl[h*2][1] = r1; bl[h*2+1][0] = r2; bl[h*2+1][1] = r3;\
            }                                                                          \
            _Pragma("unroll")                                                          \
            for (int mf = 0; mf < 4; mf++) {                                           \
                uint32_t ah0, ah1, ah2, ah3, al0, al1, al2, al3;                       \
                uint32_t off = SW64((uint32_t)((arow + mf * 16) * 64 + ks * 32 + acolb)); \
                ldsm_x4(stAh + off, ah0, ah1, ah2, ah3);                               \
                ldsm_x4(stAl + off, al0, al1, al2, al3);                               \
                _Pragma("unroll")                                                      \
                for (int nf = 0; nf < 4; nf++) {                                       \
                    mma_bf16(acc[mf][nf][0], acc[mf][nf][1], acc[mf][nf][2], acc[mf][nf][3], \
                             ah0, ah1, ah2, ah3, bh[nf][0], bh[nf][1]);                \
                    mma_bf16(acc[mf][nf][0], acc[mf][nf][1], acc[mf][nf][2], acc[mf][nf][3], \
                             ah0, ah1, ah2, ah3, bl[nf][0], bl[nf][1]);                \
                    mma_bf16(acc[mf][nf][0], acc[mf][nf][1], acc[mf][nf][2], acc[mf][nf][3], \
                             al0, al1, al2, al3, bh[nf][0], bh[nf][1]);                \
                }                                                                      \
            }                                                                          \
        }                                                                              \
    }

    ISSUE(0, 0); ISSUE(1, 1); ISSUE(2, 2);

    cp_wait<2>(); __syncthreads(); COMPUTE(0); __syncthreads(); ISSUE(3, 0);
    cp_wait<2>(); __syncthreads(); COMPUTE(1); __syncthreads(); ISSUE(4, 1);
    cp_wait<2>(); __syncthreads(); COMPUTE(2); __syncthreads(); ISSUE(5, 2);
    cp_wait<2>(); __syncthreads(); COMPUTE(0); __syncthreads(); ISSUE(6, 0);
    cp_wait<2>(); __syncthreads(); COMPUTE(1); __syncthreads(); ISSUE(7, 1);
    cp_wait<2>(); __syncthreads(); COMPUTE(2);
    cp_wait<1>(); __syncthreads(); COMPUTE(0);
    cp_wait<0>(); __syncthreads(); COMPUTE(1);

    float* outp = (z == 0) ? g_score : g_sims;
    const int gr = lane >> 2;
    const int gc = (lane & 3) * 2;
#pragma unroll
    for (int mf = 0; mf < 4; mf++) {
#pragma unroll
        for (int nf = 0; nf < 4; nf++) {
            int r0 = m0 + warp_m * 64 + mf * 16 + gr;
            int col = n0 + warp_n * 32 + nf * 8 + gc;
            float2 v0 = make_float2(acc[mf][nf][0], acc[mf][nf][1]);
            float2 v1 = make_float2(acc[mf][nf][2], acc[mf][nf][3]);
            *(float2*)(outp + (size_t)r0 * PN + col)       = v0;
            *(float2*)(outp + (size_t)(r0 + 8) * PN + col) = v1;
        }
    }
}

// warp0-only: exact kth-largest of 512 shared values via key bisection.
__device__ __forceinline__ void warp0_pivot(const float* tmax, int t, int kth,
                                            unsigned* sh_pk, float* sh_gm) {
    if (t < 32) {
        float m16[16];
#pragma unroll
        for (int k = 0; k < 16; k++) m16[k] = tmax[t + 32 * k];
        float gm = m16[0];
#pragma unroll
        for (int k = 1; k < 16; k++) gm = fmaxf(gm, m16[k]);
        for (int o = 16; o > 0; o >>= 1) gm = fmaxf(gm, __shfl_xor_sync(0xffffffffu, gm, o));
        unsigned klo = 0u, khi = fkey(gm);
#pragma unroll 1
        for (int it = 0; it < 32; it++) {
            if (khi - klo <= 1u) break;
            unsigned mid = klo + ((khi - klo) >> 1);
            float pm = unfkey(mid);
            int c = 0;
#pragma unroll
            for (int k = 0; k < 16; k++) c += (m16[k] > pm);
            for (int o = 16; o > 0; o >>= 1) c += __shfl_xor_sync(0xffffffffu, c, o);
            if (c >= kth) klo = mid; else khi = mid;
        }
        if (t == 0) { *sh_pk = klo; *sh_gm = gm; }
    }
    __syncthreads();
}

// ---------------- merged loss kernel + fused final reduction ---------------
__global__ __launch_bounds__(512, 2) void k_loss(const int* __restrict__ cams,
                                                 float* __restrict__ out) {
    __shared__ float s16[16];
    __shared__ int   si16[16];
    __shared__ float tmax[512];
    __shared__ float candv[CAP];
    __shared__ int   candi[CAP];
    __shared__ float sposv[8];
    __shared__ float s_cv[8][16];
    __shared__ int   s_ci[8][16];
    __shared__ int   chos[3];
    __shared__ int   fin[64];
    __shared__ unsigned sh_pk;
    __shared__ float sh_gm;
    __shared__ unsigned sh_cnt, sh_nf;
    __shared__ unsigned sh_rank;

    const int t = threadIdx.x;
    const int lane = t & 31, wid = t >> 5;

    if (blockIdx.x >= BN) {
        // ================= lossA: intra + cross on score =================
        const int b = blockIdx.x - BN;
        const float* ri = g_score + (size_t)b * PN;
        const int pseudo = g_pseudo[b];
        const int cam = cams[b];

        if (t == 0) sh_cnt = 0;
        if (t < 8) sposv[t] = KSCALE * ri[pseudo * 8 + t];

        float vcam[8];
        float m = NEG_INF;
#pragma unroll
        for (int i = 0; i < 8; i++) {
            int chunk = t + 512 * i;
            const float4* p4 = (const float4*)(ri + 8 * chunk);
            float4 a = p4[0], c = p4[1];
            a.x *= KSCALE; a.y *= KSCALE; a.z *= KSCALE; a.w *= KSCALE;
            c.x *= KSCALE; c.y *= KSCALE; c.z *= KSCALE; c.w *= KSCALE;
            float sel = (cam < 4) ? ((cam < 2) ? (cam == 0 ? a.x : a.y)
                                               : (cam == 2 ? a.z : a.w))
                                  : ((cam < 6) ? (cam == 4 ? c.x : c.y)
                                               : (cam == 6 ? c.z : c.w));
            vcam[i] = sel;
            if (chunk != pseudo) {
                m = fmaxf(m, fmaxf(fmaxf(a.x, a.y), fmaxf(a.z, a.w)));
                m = fmaxf(m, fmaxf(fmaxf(c.x, c.y), fmaxf(c.z, c.w)));
            }
        }
        tmax[t] = m;
        float mi = vcam[0];
#pragma unroll
        for (int i = 1; i < 8; i++) mi = fmaxf(mi, vcam[i]);
        float Mi = blockMaxF(mi, s16, t);

        warp0_pivot(tmax, t, BGK, &sh_pk, &sh_gm);
        float M = sh_gm;
#pragma unroll
        for (int k = 0; k < 8; k++) M = fmaxf(M, sposv[k]);
        float pf = unfkey(sh_pk);

#pragma unroll
        for (int i = 0; i < 8; i++) {
            int chunk = t + 512 * i;
            if (chunk == pseudo) continue;
            const float4* p4 = (const float4*)(ri + 8 * chunk);
            float4 a = p4[0], c = p4[1];
            float vv[8] = {KSCALE*a.x, KSCALE*a.y, KSCALE*a.z, KSCALE*a.w,
                           KSCALE*c.x, KSCALE*c.y, KSCALE*c.z, KSCALE*c.w};
#pragma unroll
            for (int j = 0; j < 8; j++) {
                if (vv[j] > pf) {
                    unsigned k = atomicAdd(&sh_cnt, 1u);
                    if (k < (unsigned)CAP) candv[k] = vv[j];
                }
            }
        }
        __syncthreads();
        if (sh_cnt > (unsigned)CAP) {
            unsigned pk = sh_pk, pkhi = fkey(sh_gm);
            int cnt = (int)sh_cnt;
#pragma unroll 1
            while (cnt > CAP && pkhi - pk > 1u) {
                unsigned mid = pk + ((pkhi - pk) >> 1);
                float pm = unfkey(mid);
                int c2 = 0;
                for (int i = 0; i < 8; i++) {
                    int chunk = t + 512 * i;
                    if (chunk == pseudo) continue;
                    const float4* p4 = (const float4*)(ri + 8 * chunk);
                    float4 a = p4[0], c = p4[1];
                    c2 += (KSCALE*a.x > pm) + (KSCALE*a.y > pm) + (KSCALE*a.z > pm) + (KSCALE*a.w > pm)
                        + (KSCALE*c.x > pm) + (KSCALE*c.y > pm) + (KSCALE*c.z > pm) + (KSCALE*c.w > pm);
                }
                int t2 = blockSumI(c2, si16, t);
                if (t2 >= BGK) { pk = mid; cnt = t2; }
                else pkhi = mid;
            }
            pf = unfkey(pk);
            __syncthreads();
            if (t == 0) sh_cnt = 0;
            __syncthreads();
            for (int i = 0; i < 8; i++) {
                int chunk = t + 512 * i;
                if (chunk == pseudo) continue;
                const float4* p4 = (const float4*)(ri + 8 * chunk);
                float4 a = p4[0], c = p4[1];
                float vv[8] = {KSCALE*a.x, KSCALE*a.y, KSCALE*a.z, KSCALE*a.w,
                               KSCALE*c.x, KSCALE*c.y, KSCALE*c.z, KSCALE*c.w};
                for (int j = 0; j < 8; j++) {
                    if (vv[j] > pf) {
                        unsigned k = atomicAdd(&sh_cnt, 1u);
                        if (k < (unsigned)CAP) candv[k] = vv[j];
                    }
                }
            }
            __syncthreads();
        }
        int nc = (int)min(sh_cnt, (unsigned)CAP);

        float seC = 0.f;
        for (int i = t; i < nc; i += 512) {
            float x = candv[i];
            int r = 0;
            for (int j = 0; j < nc; j++) {
                float w2 = candv[j];
                r += (w2 > x) || (w2 == x && j < i);
            }
            if (r < BGK) seC += __expf(x - M);
        }
        if (t < 8) seC += __expf(sposv[t] - M);
        float sumC = blockSumF(seC, s16, t);

        float seI = 0.f;
#pragma unroll
        for (int i = 0; i < 8; i++) seI += __expf(vcam[i] - Mi);
        float sumI = blockSumF(seI, s16, t);

        if (t == 0) {
            float psum = 0.f;
            for (int k = 0; k < 8; k++) psum += sposv[k];
            g_loss[b]      = Mi + logf(sumI) - sposv[cam];
            g_loss[BN + b] = M  + logf(sumC) - psum * 0.125f;
        }
    } else {
        // ================= lossB: online on sims =================
        const int b = blockIdx.x;
        const float* rsm = g_sims  + (size_t)b * PN;
        const float* rsc = g_score + (size_t)b * PN;

        if (t == 0) { sh_cnt = 0; sh_nf = 3; }

        float bv[8]; int bi[8];
#pragma unroll
        for (int j = 0; j < 8; j++) { bv[j] = NEG_INF; bi[j] = 0x7fffffff; }
        float m = NEG_INF;
#pragma unroll
        for (int i = 0; i < 8; i++) {
            int chunk = t + 512 * i;
            const float4* p4 = (const float4*)(rsm + 8 * chunk);
            float4 a = p4[0], c = p4[1];
            float vv[8] = {a.x, a.y, a.z, a.w, c.x, c.y, c.z, c.w};
#pragma unroll
            for (int j = 0; j < 8; j++) {
                float x = vv[j];
                if (x > bv[j]) { bv[j] = x; bi[j] = 8 * chunk + j; }
                m = fmaxf(m, x);
            }
        }
        tmax[t] = m;

#pragma unroll
        for (int j = 0; j < 8; j++) {
            float x = bv[j]; int idx = bi[j];
            for (int o = 16; o > 0; o >>= 1) {
                float ov = __shfl_down_sync(0xffffffffu, x, o);
                int   oi = __shfl_down_sync(0xffffffffu, idx, o);
                if (ov > x || (ov == x && oi < idx)) { x = ov; idx = oi; }
            }
            if (lane == 0) { s_cv[j][wid] = x; s_ci[j][wid] = idx; }
        }
        __syncthreads();
        if (t == 0) {
            float cv[8]; int ci[8];
            for (int c = 0; c < 8; c++) {
                float bvv = NEG_INF; int bii = 0x7fffffff;
                for (int w2 = 0; w2 < 16; w2++) {
                    float x = s_cv[c][w2]; int idx = s_ci[c][w2];
                    if (x > bvv || (x == bvv && idx < bii)) { bvv = x; bii = idx; }
                }
                cv[c] = bvv; ci[c] = bii;
            }
            bool used[8] = {false,false,false,false,false,false,false,false};
            for (int k = 0; k < PKK; k++) {
                int bc = -1; float bvv = NEG_INF;
                for (int c = 0; c < 8; c++)
                    if (!used[c] && cv[c] > bvv) { bvv = cv[c]; bc = c; }
                used[bc] = true;
                chos[k] = ci[bc];
            }
            fin[0] = chos[0]; fin[1] = chos[1]; fin[2] = chos[2];
        }
        __syncthreads();
        int c0 = chos[0], c1 = chos[1], c2 = chos[2];

        warp0_pivot(tmax, t, BGK + PKK, &sh_pk, &sh_gm);
        float pf = unfkey(sh_pk);

#pragma unroll
        for (int i = 0; i < 8; i++) {
            int chunk = t + 512 * i;
            const float4* p4 = (const float4*)(rsm + 8 * chunk);
            float4 a = p4[0], c = p4[1];
            float vv[8] = {a.x, a.y, a.z, a.w, c.x, c.y, c.z, c.w};
#pragma unroll
            for (int j = 0; j < 8; j++) {
                int p = 8 * chunk + j;
                if (vv[j] > pf && p != c0 && p != c1 && p != c2) {
                    unsigned k = atomicAdd(&sh_cnt, 1u);
                    if (k < (unsigned)CAP) { candv[k] = vv[j]; candi[k] = p; }
                }
            }
        }
        __syncthreads();
        if (sh_cnt > (unsigned)CAP) {
            unsigned pk = sh_pk, pkhi = fkey(sh_gm);
            int cnt = (int)sh_cnt;
#pragma unroll 1
            while (cnt > CAP && pkhi - pk > 1u) {
                unsigned mid = pk + ((pkhi - pk) >> 1);
                float pm = unfkey(mid);
                int cacc = 0;
                for (int i = 0; i < 8; i++) {
                    int chunk = t + 512 * i;
                    const float4* p4 = (const float4*)(rsm + 8 * chunk);
                    float4 a = p4[0], c = p4[1];
                    float vv[8] = {a.x, a.y, a.z, a.w, c.x, c.y, c.z, c.w};
                    for (int j = 0; j < 8; j++) {
                        int p = 8 * chunk + j;
                        cacc += (vv[j] > pm && p != c0 && p != c1 && p != c2);
                    }
                }
                int t2 = blockSumI(cacc, si16, t);
                if (t2 >= BGK) { pk = mid; cnt = t2; }
                else pkhi = mid;
            }
            pf = unfkey(pk);
            __syncthreads();
            if (t == 0) sh_cnt = 0;
            __syncthreads();
            for (int i = 0; i < 8; i++) {
                int chunk = t + 512 * i;
                const float4* p4 = (const float4*)(rsm + 8 * chunk);
                float4 a = p4[0], c = p4[1];
                float vv[8] = {a.x, a.y, a.z, a.w, c.x, c.y, c.z, c.w};
                for (int j = 0; j < 8; j++) {
                    int p = 8 * chunk + j;
                    if (vv[j] > pf && p != c0 && p != c1 && p != c2) {
                        unsigned k = atomicAdd(&sh_cnt, 1u);
                        if (k < (unsigned)CAP) { candv[k] = vv[j]; candi[k] = p; }
                    }
                }
            }
            __syncthreads();
        }
        int nc = (int)min(sh_cnt, (unsigned)CAP);

        for (int i = t; i < nc; i += 512) {
            float x = candv[i]; int pi = candi[i];
            int r = 0;
            for (int j = 0; j < nc; j++) {
                float w2 = candv[j];
                r += (w2 > x) || (w2 == x && candi[j] < pi);
            }
            if (r < BGK) {
                unsigned k = atomicAdd(&sh_nf, 1u);
                if (k < 64u) fin[k] = pi;
            }
        }
        __syncthreads();
        int nf = (int)min(sh_nf, 64u);   // 53

        float val = (t < nf) ? KSCALE * rsc[fin[t]] : NEG_INF;
        float mo = blockMaxF(val, s16, t);
        float e  = (t < nf) ? __expf(val - mo) : 0.f;
        float se = blockSumF(e, s16, t);
        if (t == 0) {
            float csum = KSCALE * rsc[c0] + KSCALE * rsc[c1] + KSCALE * rsc[c2];
            g_loss[2 * BN + b] = mo + logf(se) - csum * (1.0f / 3.0f);
        }
    }

    // ============ fused final reduction (last block to finish) ============
    __syncthreads();
    if (t == 0) {
        __threadfence();
        sh_rank = atomicAdd(&g_done, 1u);
    }
    __syncthreads();
    if (sh_rank == 2u * BN - 1u) {
        __threadfence();
        if (t < 256) {
            tmax[t]  = g_loss[t] + g_loss[BN + t] + g_loss[2 * BN + t];
            candi[t] = cams[t];
        }
        __syncthreads();
        if (t < 256) {
            int w2 = t >> 5, l2 = t & 31;
            float acc = 0.f; int n = 0;
            for (int b2 = l2; b2 < BN; b2 += 32) {
                if (candi[b2] == w2) { acc += tmax[b2]; n++; }
            }
            for (int o = 16; o > 0; o >>= 1) {
                acc += __shfl_xor_sync(0xffffffffu, acc, o);
                n   += __shfl_xor_sync(0xffffffffu, n, o);
            }
            if (l2 == 0) s_cv[0][w2] = (n > 0) ? acc / (float)n : 0.f;
        }
        __syncthreads();
        if (t == 0) {
            float tot = 0.f;
            for (int c = 0; c < 8; c++) tot += s_cv[0][c];
            out[0] = tot;
        }
    }
}

// ---------------- launch ----------------
extern "C" void kernel_launch(void* const* d_in, const int* in_sizes, int n_in,
                              void* d_out, int out_size) {
    const float* features        = (const float*)d_in[0];
    const int*   targets         = (const int*)d_in[1];
    const int*   cams            = (const int*)d_in[2];
    const float* global_memory   = (const float*)d_in[4];
    const int*   all_proxy_label = (const int*)d_in[6];
    float* out = (float*)d_out;

    cudaFuncSetAttribute(k_gemm_mma, cudaFuncAttributeMaxDynamicSharedMemorySize, SMEM_GEMM);

    k_prep<<<1024 + BN, 256>>>(features, targets, all_proxy_label, global_memory);
    dim3 gg(PN / 128, 2, 2);
    k_gemm_mma<<<gg, 256, SMEM_GEMM>>>();
    k_loss<<<2 * BN, 512>>>(cams, out);
}

// round 16
// speedup vs baseline: 1.2986x; 1.0151x over previous
#include <cuda_runtime.h>
#include <cuda_bf16.h>
#include <math.h>
#include <stdint.h>

#define BN   256
#define PN   32768
#define DN   256
#define CN   8
#define KSCALE 20.0f
#define BGK  50
#define PKK  3
#define BALW 0.15f
#define CAP  768

#define NEG_INF (__int_as_float(0xff800000))

// ---------------- scratch ----------------
__device__ int   g_pseudo[BN];
__device__ __nv_bfloat16 g_Ahi[2 * BN * DN];
__device__ __nv_bfloat16 g_Alo[2 * BN * DN];
__device__ __nv_bfloat16 g_Bhi[(size_t)PN * DN];
__device__ __nv_bfloat16 g_Blo[(size_t)PN * DN];
__device__ float g_score[(size_t)BN * PN];
__device__ float g_sims [(size_t)BN * PN];
__device__ float g_loss[3 * BN];
__device__ unsigned g_done;

// ---------------- PTX helpers ----------------
__device__ __forceinline__ uint32_t smem_u32(const void* p) {
    uint32_t a;
    asm("{ .reg .u64 t; cvta.to.shared.u64 t, %1; cvt.u32.u64 %0, t; }" : "=r"(a) : "l"(p));
    return a;
}
#define SW64(off) ((off) ^ (((off) >> 3) & 0x30))
__device__ __forceinline__ void cp16(uint32_t dst, const void* src) {
    asm volatile("cp.async.cg.shared.global [%0], [%1], 16;" :: "r"(dst), "l"(src));
}
__device__ __forceinline__ void cp_commit() { asm volatile("cp.async.commit_group;"); }
template <int N>
__device__ __forceinline__ void cp_wait() { asm volatile("cp.async.wait_group %0;" :: "n"(N)); }

__device__ __forceinline__ void ldsm_x4(uint32_t addr, uint32_t& r0, uint32_t& r1,
                                        uint32_t& r2, uint32_t& r3) {
    asm volatile("ldmatrix.sync.aligned.m8n8.x4.shared.b16 {%0,%1,%2,%3}, [%4];"
        : "=r"(r0), "=r"(r1), "=r"(r2), "=r"(r3) : "r"(addr));
}
__device__ __forceinline__ void mma_bf16(float& c0, float& c1, float& c2, float& c3,
                                         uint32_t a0, uint32_t a1, uint32_t a2, uint32_t a3,
                                         uint32_t b0, uint32_t b1) {
    asm volatile("mma.sync.aligned.m16n8k16.row.col.f32.bf16.bf16.f32 "
        "{%0,%1,%2,%3}, {%4,%5,%6,%7}, {%8,%9}, {%0,%1,%2,%3};"
        : "+f"(c0), "+f"(c1), "+f"(c2), "+f"(c3)
        : "r"(a0), "r"(a1), "r"(a2), "r"(a3), "r"(b0), "r"(b1));
}
__device__ __forceinline__ unsigned bf2_as_u32(__nv_bfloat162 h) {
    return *(const unsigned*)&h;
}

// ---------------- selection helpers ----------------
__device__ __forceinline__ unsigned fkey(float v) {
    unsigned u = __float_as_uint(v);
    return (u & 0x80000000u) ? ~u : (u | 0x80000000u);
}
__device__ __forceinline__ float unfkey(unsigned k) {
    unsigned u = (k & 0x80000000u) ? (k ^ 0x80000000u) : ~k;
    return __uint_as_float(u);
}
__device__ __forceinline__ float blockMaxF(float x, float* s16, int t) {
    int lane = t & 31, wid = t >> 5;
    for (int o = 16; o > 0; o >>= 1) x = fmaxf(x, __shfl_xor_sync(0xffffffffu, x, o));
    __syncthreads();
    if (lane == 0) s16[wid] = x;
    __syncthreads();
    if (t == 0) { float y = s16[0]; for (int w = 1; w < 16; w++) y = fmaxf(y, s16[w]); s16[0] = y; }
    __syncthreads();
    return s16[0];
}
__device__ __forceinline__ float blockSumF(float x, float* s16, int t) {
    int lane = t & 31, wid = t >> 5;
    for (int o = 16; o > 0; o >>= 1) x += __shfl_xor_sync(0xffffffffu, x, o);
    __syncthreads();
    if (lane == 0) s16[wid] = x;
    __syncthreads();
    if (t == 0) { float y = 0.f; for (int w = 0; w < 16; w++) y += s16[w]; s16[0] = y; }
    __syncthreads();
    return s16[0];
}
__device__ __forceinline__ int blockSumI(int x, int* s16, int t) {
    int lane = t & 31, wid = t >> 5;
    for (int o = 16; o > 0; o >>= 1) x += __shfl_xor_sync(0xffffffffu, x, o);
    __syncthreads();
    if (lane == 0) s16[wid] = x;
    __syncthreads();
    if (t == 0) { int y = 0; for (int w = 0; w < 16; w++) y += s16[w]; s16[0] = y; }
    __syncthreads();
    return s16[0];
}

// ---------------- K1: merged prep (vectorized B conversion) ----------------
__global__ __launch_bounds__(256) void k_prep(const float* __restrict__ features,
                                              const int* __restrict__ targets,
                                              const int* __restrict__ all_proxy_label,
                                              const float* __restrict__ mem) {
    int blk = blockIdx.x;
    int t = threadIdx.x;
    if (blk < 1024) {
        size_t base = (size_t)blk * 8192;
#pragma unroll
        for (int i = 0; i < 4; i++) {
            size_t off = base + (size_t)i * 2048 + t * 8;
            float4 f0 = *(const float4*)(mem + off);
            float4 f1 = *(const float4*)(mem + off + 4);
            __nv_bfloat162 h0 = __floats2bfloat162_rn(f0.x, f0.y);
            __nv_bfloat162 h1 = __floats2bfloat162_rn(f0.z, f0.w);
            __nv_bfloat162 h2 = __floats2bfloat162_rn(f1.x, f1.y);
            __nv_bfloat162 h3 = __floats2bfloat162_rn(f1.z, f1.w);
            __nv_bfloat162 l0 = __floats2bfloat162_rn(f0.x - __bfloat162float(__low2bfloat16(h0)),
                                                      f0.y - __bfloat162float(__high2bfloat16(h0)));
            __nv_bfloat162 l1 = __floats2bfloat162_rn(f0.z - __bfloat162float(__low2bfloat16(h1)),
                                                      f0.w - __bfloat162float(__high2bfloat16(h1)));
            __nv_bfloat162 l2 = __floats2bfloat162_rn(f1.x - __bfloat162float(__low2bfloat16(h2)),
                                                      f1.y - __bfloat162float(__high2bfloat16(h2)));
            __nv_bfloat162 l3 = __floats2bfloat162_rn(f1.z - __bfloat162float(__low2bfloat16(h3)),
                                                      f1.w - __bfloat162float(__high2bfloat16(h3)));
            uint4 hv, lv;
            hv.x = bf2_as_u32(h0); hv.y = bf2_as_u32(h1);
            hv.z = bf2_as_u32(h2); hv.w = bf2_as_u32(h3);
            lv.x = bf2_as_u32(l0); lv.y = bf2_as_u32(l1);
            lv.z = bf2_as_u32(l2); lv.w = bf2_as_u32(l3);
            *(uint4*)(g_Bhi + off) = hv;
            *(uint4*)(g_Blo + off) = lv;
        }
    } else {
        int b = blk - 1024;
        int tgt = targets[b];
        int prx = all_proxy_label[tgt];
        if (t == 0) g_pseudo[b] = prx / CN;
        if (blk == 1024 && t == 1) g_done = 0;
        float f = features[b * DN + t];
        __nv_bfloat16 fh = __float2bfloat16_rn(f);
        g_Ahi[b * DN + t] = fh;
        g_Alo[b * DN + t] = __float2bfloat16_rn(f - __bfloat162float(fh));
        float m = mem[(size_t)prx * DN + t];
        float bl = BALW * f + (1.0f - BALW) * m;
        __nv_bfloat16 bh = __float2bfloat16_rn(bl);
        g_Ahi[(BN + b) * DN + t] = bh;
        g_Alo[(BN + b) * DN + t] = __float2bfloat16_rn(bl - __bfloat162float(bh));
    }
}

// ---------------- K2: mma.sync bf16 3-term GEMM (R12, proven) --------------
#define KCH 32
#define STAGE_SZ 32768
#define SMEM_GEMM (3 * STAGE_SZ)

__global__ __launch_bounds__(256, 2) void k_gemm_mma() {
    extern __shared__ char smem[];
    const uint32_t sb = smem_u32(smem);
    const int t = threadIdx.x;
    const int lane = t & 31, w = t >> 5;
    const int warp_m = w >> 2, warp_n = w & 3;
    const int n0 = blockIdx.x * 128;
    const int m0 = blockIdx.y * 128;
    const int z  = blockIdx.z;
    const int arow_base = (z ? BN : 0) + m0;

    float acc[4][4][4];
#pragma unroll
    for (int i = 0; i < 4; i++)
#pragma unroll
        for (int j = 0; j < 4; j++)
#pragma unroll
            for (int q = 0; q < 4; q++) acc[i][j][q] = 0.f;

    const int cprow = t >> 2;
    const int cpu   = t & 3;

#define ISSUE(c, s)                                                                    \
    {                                                                                  \
        int k0 = (c) * KCH;                                                            \
        uint32_t st = sb + (s) * STAGE_SZ;                                             \
        _Pragma("unroll")                                                              \
        for (int j = 0; j < 2; j++) {                                                  \
            int row = cprow + 64 * j;                                                  \
            uint32_t d = SW64((uint32_t)(row * 64 + cpu * 16));                        \
            cp16(st + d,         g_Ahi + (size_t)(arow_base + row) * DN + k0 + cpu * 8); \
            cp16(st + 8192 + d,  g_Alo + (size_t)(arow_base + row) * DN + k0 + cpu * 8); \
            cp16(st + 16384 + d, g_Bhi + (size_t)(n0 + row) * DN + k0 + cpu * 8);      \
            cp16(st + 24576 + d, g_Blo + (size_t)(n0 + row) * DN + k0 + cpu * 8);      \
        }                                                                              \
        cp_commit();                                                                   \
    }

#define COMPUTE(s)                                                                     \
    {                                                                                  \
        uint32_t stAh = sb + (s) * STAGE_SZ;                                           \
        uint32_t stAl = stAh + 8192;                                                   \
        uint32_t stBh = stAh + 16384;                                                  \
        uint32_t stBl = stAh + 24576;                                                  \
        const int arow = warp_m * 64 + (lane & 15);                                    \
        const int acolb = (lane >> 4) << 4;                                            \
        const int brow = warp_n * 32 + (lane & 7) + ((lane >> 4) << 3);                \
        const int bcolb = ((lane >> 3) & 1) << 4;                                      \
        _Pragma("unroll")                                                              \
        for (int ks = 0; ks < 2; ks++) {                                               \
            uint32_t bh[4][2], bl[4][2];                                               \
            _Pragma("unroll")                                                          \
            for (int h = 0; h < 2; h++) {                                              \
                uint32_t off = SW64((uint32_t)((brow + h * 16) * 64 + ks * 32 + bcolb)); \
                uint32_t r0, r1, r2, r3;                                               \
                ldsm_x4(stBh + off, r0, r1, r2, r3);                                   \
                bh[h*2][0] = r0; bh[h*2][1] = r1; bh[h*2+1][0] = r2; bh[h*2+1][1] = r3;\
                ldsm_x4(stBl + off, r0, r1, r2, r3);                                   \
                bl[h*2][0] = r0; bl[h*2][1] = r1; bl[h*2+1][0] = r2; bl[h*2+1][1] = r3;\
            }                                                                          \
            _Pragma("unroll")                                                          \
            for (int mf = 0; mf < 4; mf++) {                                           \
                uint32_t ah0, ah1, ah2, ah3, al0, al1, al2, al3;                       \
                uint32_t off = SW64((uint32_t)((arow + mf * 16) * 64 + ks * 32 + acolb)); \
                ldsm_x4(stAh + off, ah0, ah1, ah2, ah3);                               \
                ldsm_x4(stAl + off, al0, al1, al2, al3);                               \
                _Pragma("unroll")                                                      \
                for (int nf = 0; nf < 4; nf++) {                                       \
                    mma_bf16(acc[mf][nf][0], acc[mf][nf][1], acc[mf][nf][2], acc[mf][nf][3], \
                             ah0, ah1, ah2, ah3, bh[nf][0], bh[nf][1]);                \
                    mma_bf16(acc[mf][nf][0], acc[mf][nf][1], acc[mf][nf][2], acc[mf][nf][3], \
                             ah0, ah1, ah2, ah3, bl[nf][0], bl[nf][1]);                \
                    mma_bf16(acc[mf][nf][0], acc[mf][nf][1], acc[mf][nf][2], acc[mf][nf][3], \
                             al0, al1, al2, al3, bh[nf][0], bh[nf][1]);                \
                }                                                                      \
            }                                                                          \
        }                                                                              \
    }

    ISSUE(0, 0); ISSUE(1, 1); ISSUE(2, 2);

    cp_wait<2>(); __syncthreads(); COMPUTE(0); __syncthreads(); ISSUE(3, 0);
    cp_wait<2>(); __syncthreads(); COMPUTE(1); __syncthreads(); ISSUE(4, 1);
    cp_wait<2>(); __syncthreads(); COMPUTE(2); __syncthreads(); ISSUE(5, 2);
    cp_wait<2>(); __syncthreads(); COMPUTE(0); __syncthreads(); ISSUE(6, 0);
    cp_wait<2>(); __syncthreads(); COMPUTE(1); __syncthreads(); ISSUE(7, 1);
    cp_wait<2>(); __syncthreads(); COMPUTE(2);
    cp_wait<1>(); __syncthreads(); COMPUTE(0);
    cp_wait<0>(); __syncthreads(); COMPUTE(1);

    float* outp = (z == 0) ? g_score : g_sims;
    const int gr = lane >> 2;
    const int gc = (lane & 3) * 2;
#pragma unroll
    for (int mf = 0; mf < 4; mf++) {
#pragma unroll
        for (int nf = 0; nf < 4; nf++) {
            int r0 = m0 + warp_m * 64 + mf * 16 + gr;
            int col = n0 + warp_n * 32 + nf * 8 + gc;
            float2 v0 = make_float2(acc[mf][nf][0], acc[mf][nf][1]);
            float2 v1 = make_float2(acc[mf][nf][2], acc[mf][nf][3]);
            *(float2*)(outp + (size_t)r0 * PN + col)       = v0;
            *(float2*)(outp + (size_t)(r0 + 8) * PN + col) = v1;
        }
    }
}

// warp0-only: exact kth-largest of 512 shared values via key bisection.
__device__ __forceinline__ void warp0_pivot(const float* tmax, int t, int kth,
                                            unsigned* sh_pk, float* sh_gm) {
    if (t < 32) {
        float m16[16];
#pragma unroll
        for (int k = 0; k < 16; k++) m16[k] = tmax[t + 32 * k];
        float gm = m16[0];
#pragma unroll
        for (int k = 1; k < 16; k++) gm = fmaxf(gm, m16[k]);
        for (int o = 16; o > 0; o >>= 1) gm = fmaxf(gm, __shfl_xor_sync(0xffffffffu, gm, o));
        unsigned klo = 0u, khi = fkey(gm);
#pragma unroll 1
        for (int it = 0; it < 32; it++) {
            if (khi - klo <= 1u) break;
            unsigned mid = klo + ((khi - klo) >> 1);
            float pm = unfkey(mid);
            int c = 0;
#pragma unroll
            for (int k = 0; k < 16; k++) c += (m16[k] > pm);
            for (int o = 16; o > 0; o >>= 1) c += __shfl_xor_sync(0xffffffffu, c, o);
            if (c >= kth) klo = mid; else khi = mid;
        }
        if (t == 0) { *sh_pk = klo; *sh_gm = gm; }
    }
    __syncthreads();
}

// ---------------- merged loss kernel + fused final reduction ---------------
__global__ __launch_bounds__(512, 2) void k_loss(const int* __restrict__ cams,
                                                 float* __restrict__ out) {
    __shared__ float s16[16];
    __shared__ int   si16[16];
    __shared__ float tmax[512];
    __shared__ float candv[CAP];
    __shared__ int   candi[CAP];
    __shared__ float sposv[8];
    __shared__ float s_cv[8][16];
    __shared__ int   s_ci[8][16];
    __shared__ int   chos[3];
    __shared__ int   fin[64];
    __shared__ unsigned sh_pk;
    __shared__ float sh_gm;
    __shared__ unsigned sh_cnt, sh_nf;
    __shared__ unsigned sh_rank;

    const int t = threadIdx.x;
    const int lane = t & 31, wid = t >> 5;

    if (blockIdx.x >= BN) {
        // ================= lossA: intra + cross on score =================
        const int b = blockIdx.x - BN;
        const float* ri = g_score + (size_t)b * PN;
        const int pseudo = g_pseudo[b];
        const int cam = cams[b];

        if (t == 0) sh_cnt = 0;
        if (t < 8) sposv[t] = KSCALE * ri[pseudo * 8 + t];

        float vcam[8];
        float m = NEG_INF;
#pragma unroll
        for (int i = 0; i < 8; i++) {
            int chunk = t + 512 * i;
            const float4* p4 = (const float4*)(ri + 8 * chunk);
            float4 a = p4[0], c = p4[1];
            a.x *= KSCALE; a.y *= KSCALE; a.z *= KSCALE; a.w *= KSCALE;
            c.x *= KSCALE; c.y *= KSCALE; c.z *= KSCALE; c.w *= KSCALE;
            float sel = (cam < 4) ? ((cam < 2) ? (cam == 0 ? a.x : a.y)
                                               : (cam == 2 ? a.z : a.w))
                                  : ((cam < 6) ? (cam == 4 ? c.x : c.y)
                                               : (cam == 6 ? c.z : c.w));
            vcam[i] = sel;
            if (chunk != pseudo) {
                m = fmaxf(m, fmaxf(fmaxf(a.x, a.y), fmaxf(a.z, a.w)));
                m = fmaxf(m, fmaxf(fmaxf(c.x, c.y), fmaxf(c.z, c.w)));
            }
        }
        tmax[t] = m;
        float mi = vcam[0];
#pragma unroll
        for (int i = 1; i < 8; i++) mi = fmaxf(mi, vcam[i]);
        float Mi = blockMaxF(mi, s16, t);

        warp0_pivot(tmax, t, BGK, &sh_pk, &sh_gm);
        float M = sh_gm;
#pragma unroll
        for (int k = 0; k < 8; k++) M = fmaxf(M, sposv[k]);
        float pf = unfkey(sh_pk);

        // pass 2: only threads whose max can contain candidates
        if (m > pf) {
#pragma unroll
            for (int i = 0; i < 8; i++) {
                int chunk = t + 512 * i;
                if (chunk == pseudo) continue;
                const float4* p4 = (const float4*)(ri + 8 * chunk);
                float4 a = p4[0], c = p4[1];
                float vv[8] = {KSCALE*a.x, KSCALE*a.y, KSCALE*a.z, KSCALE*a.w,
                               KSCALE*c.x, KSCALE*c.y, KSCALE*c.z, KSCALE*c.w};
#pragma unroll
                for (int j = 0; j < 8; j++) {
                    if (vv[j] > pf) {
                        unsigned k = atomicAdd(&sh_cnt, 1u);
                        if (k < (unsigned)CAP) candv[k] = vv[j];
                    }
                }
            }
        }
        __syncthreads();
        if (sh_cnt > (unsigned)CAP) {
            unsigned pk = sh_pk, pkhi = fkey(sh_gm);
            int cnt = (int)sh_cnt;
#pragma unroll 1
            while (cnt > CAP && pkhi - pk > 1u) {
                unsigned mid = pk + ((pkhi - pk) >> 1);
                float pm = unfkey(mid);
                int c2 = 0;
                if (m > pm) {
                    for (int i = 0; i < 8; i++) {
                        int chunk = t + 512 * i;
                        if (chunk == pseudo) continue;
                        const float4* p4 = (const float4*)(ri + 8 * chunk);
                        float4 a = p4[0], c = p4[1];
                        c2 += (KSCALE*a.x > pm) + (KSCALE*a.y > pm) + (KSCALE*a.z > pm) + (KSCALE*a.w > pm)
                            + (KSCALE*c.x > pm) + (KSCALE*c.y > pm) + (KSCALE*c.z > pm) + (KSCALE*c.w > pm);
                    }
                }
                int t2 = blockSumI(c2, si16, t);
                if (t2 >= BGK) { pk = mid; cnt = t2; }
                else pkhi = mid;
            }
            pf = unfkey(pk);
            __syncthreads();
            if (t == 0) sh_cnt = 0;
            __syncthreads();
            if (m > pf) {
                for (int i = 0; i < 8; i++) {
                    int chunk = t + 512 * i;
                    if (chunk == pseudo) continue;
                    const float4* p4 = (const float4*)(ri + 8 * chunk);
                    float4 a = p4[0], c = p4[1];
                    float vv[8] = {KSCALE*a.x, KSCALE*a.y, KSCALE*a.z, KSCALE*a.w,
                                   KSCALE*c.x, KSCALE*c.y, KSCALE*c.z, KSCALE*c.w};
                    for (int j = 0; j < 8; j++) {
                        if (vv[j] > pf) {
                            unsigned k = atomicAdd(&sh_cnt, 1u);
                            if (k < (unsigned)CAP) candv[k] = vv[j];
                        }
                    }
                }
            }
            __syncthreads();
        }
        int nc = (int)min(sh_cnt, (unsigned)CAP);

        float seC = 0.f;
        for (int i = t; i < nc; i += 512) {
            float x = candv[i];
            int r = 0;
            for (int j = 0; j < nc; j++) {
                float w2 = candv[j];
                r += (w2 > x) || (w2 == x && j < i);
            }
            if (r < BGK) seC += __expf(x - M);
        }
        if (t < 8) seC += __expf(sposv[t] - M);
        float sumC = blockSumF(seC, s16, t);

        float seI = 0.f;
#pragma unroll
        for (int i = 0; i < 8; i++) seI += __expf(vcam[i] - Mi);
        float sumI = blockSumF(seI, s16, t);

        if (t == 0) {
            float psum = 0.f;
            for (int k = 0; k < 8; k++) psum += sposv[k];
            g_loss[b]      = Mi + logf(sumI) - sposv[cam];
            g_loss[BN + b] = M  + logf(sumC) - psum * 0.125f;
        }
    } else {
        // ================= lossB: online on sims =================
        const int b = blockIdx.x;
        const float* rsm = g_sims  + (size_t)b * PN;
        const float* rsc = g_score + (size_t)b * PN;

        if (t == 0) { sh_cnt = 0; sh_nf = 3; }

        float bv[8]; int bi[8];
#pragma unroll
        for (int j = 0; j < 8; j++) { bv[j] = NEG_INF; bi[j] = 0x7fffffff; }
        float m = NEG_INF;
#pragma unroll
        for (int i = 0; i < 8; i++) {
            int chunk = t + 512 * i;
            const float4* p4 = (const float4*)(rsm + 8 * chunk);
            float4 a = p4[0], c = p4[1];
            float vv[8] = {a.x, a.y, a.z, a.w, c.x, c.y, c.z, c.w};
#pragma unroll
            for (int j = 0; j < 8; j++) {
                float x = vv[j];
                if (x > bv[j]) { bv[j] = x; bi[j] = 8 * chunk + j; }
                m = fmaxf(m, x);
            }
        }
        tmax[t] = m;

#pragma unroll
        for (int j = 0; j < 8; j++) {
            float x = bv[j]; int idx = bi[j];
            for (int o = 16; o > 0; o >>= 1) {
                float ov = __shfl_down_sync(0xffffffffu, x, o);
                int   oi = __shfl_down_sync(0xffffffffu, idx, o);
                if (ov > x || (ov == x && oi < idx)) { x = ov; idx = oi; }
            }
            if (lane == 0) { s_cv[j][wid] = x; s_ci[j][wid] = idx; }
        }
        __syncthreads();
        if (t == 0) {
            float cv[8]; int ci[8];
            for (int c = 0; c < 8; c++) {
                float bvv = NEG_INF; int bii = 0x7fffffff;
                for (int w2 = 0; w2 < 16; w2++) {
                    float x = s_cv[c][w2]; int idx = s_ci[c][w2];
                    if (x > bvv || (x == bvv && idx < bii)) { bvv = x; bii = idx; }
                }
                cv[c] = bvv; ci[c] = bii;
            }
            bool used[8] = {false,false,false,false,false,false,false,false};
            for (int k = 0; k < PKK; k++) {
                int bc = -1; float bvv = NEG_INF;
                for (int c = 0; c < 8; c++)
                    if (!used[c] && cv[c] > bvv) { bvv = cv[c]; bc = c; }
                used[bc] = true;
                chos[k] = ci[bc];
            }
            fin[0] = chos[0]; fin[1] = chos[1]; fin[2] = chos[2];
        }
        __syncthreads();
        int c0 = chos[0], c1 = chos[1], c2 = chos[2];

        warp0_pivot(tmax, t, BGK + PKK, &sh_pk, &sh_gm);
        float pf = unfkey(sh_pk);

        // pass 2: only threads whose max can contain candidates
        if (m > pf) {
#pragma unroll
            for (int i = 0; i < 8; i++) {
                int chunk = t + 512 * i;
                const float4* p4 = (const float4*)(rsm + 8 * chunk);
                float4 a = p4[0], c = p4[1];
                float vv[8] = {a.x, a.y, a.z, a.w, c.x, c.y, c.z, c.w};
#pragma unroll
                for (int j = 0; j < 8; j++) {
                    int p = 8 * chunk + j;
                    if (vv[j] > pf && p != c0 && p != c1 && p != c2) {
                        unsigned k = atomicAdd(&sh_cnt, 1u);
                        if (k < (unsigned)CAP) { candv[k] = vv[j]; candi[k] = p; }
                    }
                }
            }
        }
        __syncthreads();
        if (sh_cnt > (unsigned)CAP) {
            unsigned pk = sh_pk, pkhi = fkey(sh_gm);
            int cnt = (int)sh_cnt;
#pragma unroll 1
            while (cnt > CAP && pkhi - pk > 1u) {
                unsigned mid = pk + ((pkhi - pk) >> 1);
                float pm = unfkey(mid);
                int cacc = 0;
                if (m > pm) {
                    for (int i = 0; i < 8; i++) {
                        int chunk = t + 512 * i;
                        const float4* p4 = (const float4*)(rsm + 8 * chunk);
                        float4 a = p4[0], c = p4[1];
                        float vv[8] = {a.x, a.y, a.z, a.w, c.x, c.y, c.z, c.w};
                        for (int j = 0; j < 8; j++) {
                            int p = 8 * chunk + j;
                            cacc += (vv[j] > pm && p != c0 && p != c1 && p != c2);
                        }
                    }
                }
                int t2 = blockSumI(cacc, si16, t);
                if (t2 >= BGK) { pk = mid; cnt = t2; }
                else pkhi = mid;
            }
            pf = unfkey(pk);
            __syncthreads();
            if (t == 0) sh_cnt = 0;
            __syncthreads();
            if (m > pf) {
                for (int i = 0; i < 8; i++) {
                    int chunk = t + 512 * i;
                    const float4* p4 = (const float4*)(rsm + 8 * chunk);
                    float4 a = p4[0], c = p4[1];
                    float vv[8] = {a.x, a.y, a.z, a.w, c.x, c.y, c.z, c.w};
                    for (int j = 0; j < 8; j++) {
                        int p = 8 * chunk + j;
                        if (vv[j] > pf && p != c0 && p != c1 && p != c2) {
                            unsigned k = atomicAdd(&sh_cnt, 1u);
                            if (k < (unsigned)CAP) { candv[k] = vv[j]; candi[k] = p; }
                        }
                    }
                }
            }
            __syncthreads();
        }
        int nc = (int)min(sh_cnt, (unsigned)CAP);

        for (int i = t; i < nc; i += 512) {
            float x = candv[i]; int pi = candi[i];
            int r = 0;
            for (int j = 0; j < nc; j++) {
                float w2 = candv[j];
                r += (w2 > x) || (w2 == x && candi[j] < pi);
            }
            if (r < BGK) {
                unsigned k = atomicAdd(&sh_nf, 1u);
                if (k < 64u) fin[k] = pi;
            }
        }
        __syncthreads();
        int nf = (int)min(sh_nf, 64u);   // 53

        float val = (t < nf) ? KSCALE * rsc[fin[t]] : NEG_INF;
        float mo = blockMaxF(val, s16, t);
        float e  = (t < nf) ? __expf(val - mo) : 0.f;
        float se = blockSumF(e, s16, t);
        if (t == 0) {
            float csum = KSCALE * rsc[c0] + KSCALE * rsc[c1] + KSCALE * rsc[c2];
            g_loss[2 * BN + b] = mo + logf(se) - csum * (1.0f / 3.0f);
        }
    }

    // ============ fused final reduction (last block to finish) ============
    __syncthreads();
    if (t == 0) {
        __threadfence();
        sh_rank = atomicAdd(&g_done, 1u);
    }
    __syncthreads();
    if (sh_rank == 2u * BN - 1u) {
        __threadfence();
        if (t < 256) {
            tmax[t]  = g_loss[t] + g_loss[BN + t] + g_loss[2 * BN + t];
            candi[t] = cams[t];
        }
        __syncthreads();
        if (t < 256) {
            int w2 = t >> 5, l2 = t & 31;
            float acc = 0.f; int n = 0;
            for (int b2 = l2; b2 < BN; b2 += 32) {
                if (candi[b2] == w2) { acc += tmax[b2]; n++; }
            }
            for (int o = 16; o > 0; o >>= 1) {
                acc += __shfl_xor_sync(0xffffffffu, acc, o);
                n   += __shfl_xor_sync(0xffffffffu, n, o);
            }
            if (l2 == 0) s_cv[0][w2] = (n > 0) ? acc / (float)n : 0.f;
        }
        __syncthreads();
        if (t == 0) {
            float tot = 0.f;
            for (int c = 0; c < 8; c++) tot += s_cv[0][c];
            out[0] = tot;
        }
    }
}

// ---------------- launch ----------------
extern "C" void kernel_launch(void* const* d_in, const int* in_sizes, int n_in,
                              void* d_out, int out_size) {
    const float* features        = (const float*)d_in[0];
    const int*   targets         = (const int*)d_in[1];
    const int*   cams            = (const int*)d_in[2];
    const float* global_memory   = (const float*)d_in[4];
    const int*   all_proxy_label = (const int*)d_in[6];
    float* out = (float*)d_out;

    cudaFuncSetAttribute(k_gemm_mma, cudaFuncAttributeMaxDynamicSharedMemorySize, SMEM_GEMM);

    k_prep<<<1024 + BN, 256>>>(features, targets, all_proxy_label, global_memory);
    dim3 gg(PN / 128, 2, 2);
    k_gemm_mma<<<gg, 256, SMEM_GEMM>>>();
    k_loss<<<2 * BN, 512>>>(cams, out);
}

// round 17
// speedup vs baseline: 1.3435x; 1.0346x over previous
#include <cuda_runtime.h>
#include <cuda_bf16.h>
#include <math.h>
#include <stdint.h>

#define BN   256
#define PN   32768
#define DN   256
#define CN   8
#define KSCALE 20.0f
#define BGK  50
#define PKK  3
#define BALW 0.15f
#define CAP  768

#define NEG_INF (__int_as_float(0xff800000))

// ---------------- scratch ----------------
__device__ int   g_pseudo[BN];
__device__ __nv_bfloat16 g_Ahi[2 * BN * DN];
__device__ __nv_bfloat16 g_Alo[2 * BN * DN];
__device__ __nv_bfloat16 g_Bhi[(size_t)PN * DN];
__device__ __nv_bfloat16 g_Blo[(size_t)PN * DN];
__device__ float g_score[(size_t)BN * PN];
__device__ float g_sims [(size_t)BN * PN];
__device__ float g_loss[3 * BN];
__device__ unsigned g_done;

// ---------------- PTX helpers ----------------
__device__ __forceinline__ uint32_t smem_u32(const void* p) {
    uint32_t a;
    asm("{ .reg .u64 t; cvta.to.shared.u64 t, %1; cvt.u32.u64 %0, t; }" : "=r"(a) : "l"(p));
    return a;
}
#define SW64(off) ((off) ^ (((off) >> 3) & 0x30))
__device__ __forceinline__ void cp16(uint32_t dst, const void* src) {
    asm volatile("cp.async.cg.shared.global [%0], [%1], 16;" :: "r"(dst), "l"(src));
}
__device__ __forceinline__ void cp_commit() { asm volatile("cp.async.commit_group;"); }
template <int N>
__device__ __forceinline__ void cp_wait() { asm volatile("cp.async.wait_group %0;" :: "n"(N)); }

__device__ __forceinline__ void ldsm_x4(uint32_t addr, uint32_t& r0, uint32_t& r1,
                                        uint32_t& r2, uint32_t& r3) {
    asm volatile("ldmatrix.sync.aligned.m8n8.x4.shared.b16 {%0,%1,%2,%3}, [%4];"
        : "=r"(r0), "=r"(r1), "=r"(r2), "=r"(r3) : "r"(addr));
}
__device__ __forceinline__ void mma_bf16(float& c0, float& c1, float& c2, float& c3,
                                         uint32_t a0, uint32_t a1, uint32_t a2, uint32_t a3,
                                         uint32_t b0, uint32_t b1) {
    asm volatile("mma.sync.aligned.m16n8k16.row.col.f32.bf16.bf16.f32 "
        "{%0,%1,%2,%3}, {%4,%5,%6,%7}, {%8,%9}, {%0,%1,%2,%3};"
        : "+f"(c0), "+f"(c1), "+f"(c2), "+f"(c3)
        : "r"(a0), "r"(a1), "r"(a2), "r"(a3), "r"(b0), "r"(b1));
}
__device__ __forceinline__ unsigned bf2_as_u32(__nv_bfloat162 h) {
    return *(const unsigned*)&h;
}

// ---------------- selection helpers ----------------
__device__ __forceinline__ unsigned fkey(float v) {
    unsigned u = __float_as_uint(v);
    return (u & 0x80000000u) ? ~u : (u | 0x80000000u);
}
__device__ __forceinline__ float unfkey(unsigned k) {
    unsigned u = (k & 0x80000000u) ? (k ^ 0x80000000u) : ~k;
    return __uint_as_float(u);
}
__device__ __forceinline__ float blockMaxF(float x, float* s16, int t) {
    int lane = t & 31, wid = t >> 5;
    for (int o = 16; o > 0; o >>= 1) x = fmaxf(x, __shfl_xor_sync(0xffffffffu, x, o));
    __syncthreads();
    if (lane == 0) s16[wid] = x;
    __syncthreads();
    if (t == 0) { float y = s16[0]; for (int w = 1; w < 16; w++) y = fmaxf(y, s16[w]); s16[0] = y; }
    __syncthreads();
    return s16[0];
}
__device__ __forceinline__ float blockSumF(float x, float* s16, int t) {
    int lane = t & 31, wid = t >> 5;
    for (int o = 16; o > 0; o >>= 1) x += __shfl_xor_sync(0xffffffffu, x, o);
    __syncthreads();
    if (lane == 0) s16[wid] = x;
    __syncthreads();
    if (t == 0) { float y = 0.f; for (int w = 0; w < 16; w++) y += s16[w]; s16[0] = y; }
    __syncthreads();
    return s16[0];
}
__device__ __forceinline__ int blockSumI(int x, int* s16, int t) {
    int lane = t & 31, wid = t >> 5;
    for (int o = 16; o > 0; o >>= 1) x += __shfl_xor_sync(0xffffffffu, x, o);
    __syncthreads();
    if (lane == 0) s16[wid] = x;
    __syncthreads();
    if (t == 0) { int y = 0; for (int w = 0; w < 16; w++) y += s16[w]; s16[0] = y; }
    __syncthreads();
    return s16[0];
}

// ---------------- K1: merged prep (vectorized B conversion) ----------------
__global__ __launch_bounds__(256) void k_prep(const float* __restrict__ features,
                                              const int* __restrict__ targets,
                                              const int* __restrict__ all_proxy_label,
                                              const float* __restrict__ mem) {
    int blk = blockIdx.x;
    int t = threadIdx.x;
    if (blk < 1024) {
        size_t base = (size_t)blk * 8192;
#pragma unroll
        for (int i = 0; i < 4; i++) {
            size_t off = base + (size_t)i * 2048 + t * 8;
            float4 f0 = *(const float4*)(mem + off);
            float4 f1 = *(const float4*)(mem + off + 4);
            __nv_bfloat162 h0 = __floats2bfloat162_rn(f0.x, f0.y);
            __nv_bfloat162 h1 = __floats2bfloat162_rn(f0.z, f0.w);
            __nv_bfloat162 h2 = __floats2bfloat162_rn(f1.x, f1.y);
            __nv_bfloat162 h3 = __floats2bfloat162_rn(f1.z, f1.w);
            __nv_bfloat162 l0 = __floats2bfloat162_rn(f0.x - __bfloat162float(__low2bfloat16(h0)),
                                                      f0.y - __bfloat162float(__high2bfloat16(h0)));
            __nv_bfloat162 l1 = __floats2bfloat162_rn(f0.z - __bfloat162float(__low2bfloat16(h1)),
                                                      f0.w - __bfloat162float(__high2bfloat16(h1)));
            __nv_bfloat162 l2 = __floats2bfloat162_rn(f1.x - __bfloat162float(__low2bfloat16(h2)),
                                                      f1.y - __bfloat162float(__high2bfloat16(h2)));
            __nv_bfloat162 l3 = __floats2bfloat162_rn(f1.z - __bfloat162float(__low2bfloat16(h3)),
                                                      f1.w - __bfloat162float(__high2bfloat16(h3)));
            uint4 hv, lv;
            hv.x = bf2_as_u32(h0); hv.y = bf2_as_u32(h1);
            hv.z = bf2_as_u32(h2); hv.w = bf2_as_u32(h3);
            lv.x = bf2_as_u32(l0); lv.y = bf2_as_u32(l1);
            lv.z = bf2_as_u32(l2); lv.w = bf2_as_u32(l3);
            *(uint4*)(g_Bhi + off) = hv;
            *(uint4*)(g_Blo + off) = lv;
        }
    } else {
        int b = blk - 1024;
        int tgt = targets[b];
        int prx = all_proxy_label[tgt];
        if (t == 0) g_pseudo[b] = prx / CN;
        if (blk == 1024 && t == 1) g_done = 0;
        float f = features[b * DN + t];
        __nv_bfloat16 fh = __float2bfloat16_rn(f);
        g_Ahi[b * DN + t] = fh;
        g_Alo[b * DN + t] = __float2bfloat16_rn(f - __bfloat162float(fh));
        float m = mem[(size_t)prx * DN + t];
        float bl = BALW * f + (1.0f - BALW) * m;
        __nv_bfloat16 bh = __float2bfloat16_rn(bl);
        g_Ahi[(BN + b) * DN + t] = bh;
        g_Alo[(BN + b) * DN + t] = __float2bfloat16_rn(bl - __bfloat162float(bh));
    }
}

// ---------------- K2: mma.sync bf16 3-term GEMM (R12, proven) --------------
#define KCH 32
#define STAGE_SZ 32768
#define SMEM_GEMM (3 * STAGE_SZ)

__global__ __launch_bounds__(256, 2) void k_gemm_mma() {
    extern __shared__ char smem[];
    const uint32_t sb = smem_u32(smem);
    const int t = threadIdx.x;
    const int lane = t & 31, w = t >> 5;
    const int warp_m = w >> 2, warp_n = w & 3;
    const int n0 = blockIdx.x * 128;
    const int m0 = blockIdx.y * 128;
    const int z  = blockIdx.z;
    const int arow_base = (z ? BN : 0) + m0;

    float acc[4][4][4];
#pragma unroll
    for (int i = 0; i < 4; i++)
#pragma unroll
        for (int j = 0; j < 4; j++)
#pragma unroll
            for (int q = 0; q < 4; q++) acc[i][j][q] = 0.f;

    const int cprow = t >> 2;
    const int cpu   = t & 3;

#define ISSUE(c, s)                                                                    \
    {                                                                                  \
        int k0 = (c) * KCH;                                                            \
        uint32_t st = sb + (s) * STAGE_SZ;                                             \
        _Pragma("unroll")                                                              \
        for (int j = 0; j < 2; j++) {                                                  \
            int row = cprow + 64 * j;                                                  \
            uint32_t d = SW64((uint32_t)(row * 64 + cpu * 16));                        \
            cp16(st + d,         g_Ahi + (size_t)(arow_base + row) * DN + k0 + cpu * 8); \
            cp16(st + 8192 + d,  g_Alo + (size_t)(arow_base + row) * DN + k0 + cpu * 8); \
            cp16(st + 16384 + d, g_Bhi + (size_t)(n0 + row) * DN + k0 + cpu * 8);      \
            cp16(st + 24576 + d, g_Blo + (size_t)(n0 + row) * DN + k0 + cpu * 8);      \
        }                                                                              \
        cp_commit();                                                                   \
    }

#define COMPUTE(s)                                                                     \
    {                                                                                  \
        uint32_t stAh = sb + (s) * STAGE_SZ;                                           \
        uint32_t stAl = stAh + 8192;                                                   \
        uint32_t stBh = stAh + 16384;                                                  \
        uint32_t stBl = stAh + 24576;                                                  \
        const int arow = warp_m * 64 + (lane & 15);                                    \
        const int acolb = (lane >> 4) << 4;                                            \
        const int brow = warp_n * 32 + (lane & 7) + ((lane >> 4) << 3);                \
        const int bcolb = ((lane >> 3) & 1) << 4;                                      \
        _Pragma("unroll")                                                              \
        for (int ks = 0; ks < 2; ks++) {                                               \
            uint32_t bh[4][2], bl[4][2];                                               \
            _Pragma("unroll")                                                          \
            for (int h = 0; h < 2; h++) {                                              \
                uint32_t off = SW64((uint32_t)((brow + h * 16) * 64 + ks * 32 + bcolb)); \
                uint32_t r0, r1, r2, r3;                                               \
                ldsm_x4(stBh + off, r0, r1, r2, r3);                                   \
                bh[h*2][0] = r0; bh[h*2][1] = r1; bh[h*2+1][0] = r2; bh[h*2+1][1] = r3;\
                ldsm_x4(stBl + off, r0, r1, r2, r3);                                   \
                bl[h*2][0] = r0; bl[h*2][1] = r1; bl[h*2+1][0] = r2; bl[h*2+1][1] = r3;\
            }                                                                          \
            _Pragma("unroll")                                                          \
            for (int mf = 0; mf < 4; mf++) {                                           \
                uint32_t ah0, ah1, ah2, ah3, al0, al1, al2, al3;                       \
                uint32_t off = SW64((uint32_t)((arow + mf * 16) * 64 + ks * 32 + acolb)); \
                ldsm_x4(stAh + off, ah0, ah1, ah2, ah3);                               \
                ldsm_x4(stAl + off, al0, al1, al2, al3);                               \
                _Pragma("unroll")                                                      \
                for (int nf = 0; nf < 4; nf++) {                                       \
                    mma_bf16(acc[mf][nf][0], acc[mf][nf][1], acc[mf][nf][2], acc[mf][nf][3], \
                             ah0, ah1, ah2, ah3, bh[nf][0], bh[nf][1]);                \
                    mma_bf16(acc[mf][nf][0], acc[mf][nf][1], acc[mf][nf][2], acc[mf][nf][3], \
                             ah0, ah1, ah2, ah3, bl[nf][0], bl[nf][1]);                \
                    mma_bf16(acc[mf][nf][0], acc[mf][nf][1], acc[mf][nf][2], acc[mf][nf][3], \
                             al0, al1, al2, al3, bh[nf][0], bh[nf][1]);                \
                }                                                                      \
            }                                                                          \
        }                                                                              \
    }

    ISSUE(0, 0); ISSUE(1, 1); ISSUE(2, 2);

    cp_wait<2>(); __syncthreads(); COMPUTE(0); __syncthreads(); ISSUE(3, 0);
    cp_wait<2>(); __syncthreads(); COMPUTE(1); __syncthreads(); ISSUE(4, 1);
    cp_wait<2>(); __syncthreads(); COMPUTE(2); __syncthreads(); ISSUE(5, 2);
    cp_wait<2>(); __syncthreads(); COMPUTE(0); __syncthreads(); ISSUE(6, 0);
    cp_wait<2>(); __syncthreads(); COMPUTE(1); __syncthreads(); ISSUE(7, 1);
    cp_wait<2>(); __syncthreads(); COMPUTE(2);
    cp_wait<1>(); __syncthreads(); COMPUTE(0);
    cp_wait<0>(); __syncthreads(); COMPUTE(1);

    float* outp = (z == 0) ? g_score : g_sims;
    const int gr = lane >> 2;
    const int gc = (lane & 3) * 2;
#pragma unroll
    for (int mf = 0; mf < 4; mf++) {
#pragma unroll
        for (int nf = 0; nf < 4; nf++) {
            int r0 = m0 + warp_m * 64 + mf * 16 + gr;
            int col = n0 + warp_n * 32 + nf * 8 + gc;
            float2 v0 = make_float2(acc[mf][nf][0], acc[mf][nf][1]);
            float2 v1 = make_float2(acc[mf][nf][2], acc[mf][nf][3]);
            *(float2*)(outp + (size_t)r0 * PN + col)       = v0;
            *(float2*)(outp + (size_t)(r0 + 8) * PN + col) = v1;
        }
    }
}

// warp0-only: exact kth-largest of 512 shared values via key bisection.
__device__ __forceinline__ void warp0_pivot(const float* tmax, int t, int kth,
                                            unsigned* sh_pk, float* sh_gm) {
    if (t < 32) {
        float m16[16];
#pragma unroll
        for (int k = 0; k < 16; k++) m16[k] = tmax[t + 32 * k];
        float gm = m16[0];
#pragma unroll
        for (int k = 1; k < 16; k++) gm = fmaxf(gm, m16[k]);
        for (int o = 16; o > 0; o >>= 1) gm = fmaxf(gm, __shfl_xor_sync(0xffffffffu, gm, o));
        unsigned klo = 0u, khi = fkey(gm);
#pragma unroll 1
        for (int it = 0; it < 32; it++) {
            if (khi - klo <= 1u) break;
            unsigned mid = klo + ((khi - klo) >> 1);
            float pm = unfkey(mid);
            int c = 0;
#pragma unroll
            for (int k = 0; k < 16; k++) c += (m16[k] > pm);
            for (int o = 16; o > 0; o >>= 1) c += __shfl_xor_sync(0xffffffffu, c, o);
            if (c >= kth) klo = mid; else khi = mid;
        }
        if (t == 0) { *sh_pk = klo; *sh_gm = gm; }
    }
    __syncthreads();
}

// ---------------- merged loss kernel + fused final reduction ---------------
__global__ __launch_bounds__(512, 3) void k_loss(const int* __restrict__ cams,
                                                 float* __restrict__ out) {
    __shared__ float s16[16];
    __shared__ int   si16[16];
    __shared__ float tmax[512];
    __shared__ float candv[CAP];
    __shared__ int   candi[CAP];
    __shared__ float sposv[8];
    __shared__ float s_cv[8][16];
    __shared__ int   s_ci[8][16];
    __shared__ int   chos[3];
    __shared__ int   fin[64];
    __shared__ unsigned sh_pk;
    __shared__ float sh_gm;
    __shared__ unsigned sh_cnt, sh_nf;
    __shared__ unsigned sh_rank;

    const int t = threadIdx.x;
    const int lane = t & 31, wid = t >> 5;

    if (blockIdx.x >= BN) {
        // ================= lossA: intra + cross on score =================
        const int b = blockIdx.x - BN;
        const float* ri = g_score + (size_t)b * PN;
        const int pseudo = g_pseudo[b];
        const int cam = cams[b];

        if (t == 0) sh_cnt = 0;
        if (t < 8) sposv[t] = KSCALE * ri[pseudo * 8 + t];

        float vcam[8];
        float m = NEG_INF;
#pragma unroll
        for (int i = 0; i < 8; i++) {
            int chunk = t + 512 * i;
            const float4* p4 = (const float4*)(ri + 8 * chunk);
            float4 a = p4[0], c = p4[1];
            a.x *= KSCALE; a.y *= KSCALE; a.z *= KSCALE; a.w *= KSCALE;
            c.x *= KSCALE; c.y *= KSCALE; c.z *= KSCALE; c.w *= KSCALE;
            float sel = (cam < 4) ? ((cam < 2) ? (cam == 0 ? a.x : a.y)
                                               : (cam == 2 ? a.z : a.w))
                                  : ((cam < 6) ? (cam == 4 ? c.x : c.y)
                                               : (cam == 6 ? c.z : c.w));
            vcam[i] = sel;
            if (chunk != pseudo) {
                m = fmaxf(m, fmaxf(fmaxf(a.x, a.y), fmaxf(a.z, a.w)));
                m = fmaxf(m, fmaxf(fmaxf(c.x, c.y), fmaxf(c.z, c.w)));
            }
        }
        tmax[t] = m;
        float mi = vcam[0];
#pragma unroll
        for (int i = 1; i < 8; i++) mi = fmaxf(mi, vcam[i]);
        float Mi = blockMaxF(mi, s16, t);

        warp0_pivot(tmax, t, BGK, &sh_pk, &sh_gm);
        float M = sh_gm;
#pragma unroll
        for (int k = 0; k < 8; k++) M = fmaxf(M, sposv[k]);
        float pf = unfkey(sh_pk);

        if (m > pf) {
#pragma unroll
            for (int i = 0; i < 8; i++) {
                int chunk = t + 512 * i;
                if (chunk == pseudo) continue;
                const float4* p4 = (const float4*)(ri + 8 * chunk);
                float4 a = p4[0], c = p4[1];
                float vv[8] = {KSCALE*a.x, KSCALE*a.y, KSCALE*a.z, KSCALE*a.w,
                               KSCALE*c.x, KSCALE*c.y, KSCALE*c.z, KSCALE*c.w};
#pragma unroll
                for (int j = 0; j < 8; j++) {
                    if (vv[j] > pf) {
                        unsigned k = atomicAdd(&sh_cnt, 1u);
                        if (k < (unsigned)CAP) candv[k] = vv[j];
                    }
                }
            }
        }
        __syncthreads();
        if (sh_cnt > (unsigned)CAP) {
            unsigned pk = sh_pk, pkhi = fkey(sh_gm);
            int cnt = (int)sh_cnt;
#pragma unroll 1
            while (cnt > CAP && pkhi - pk > 1u) {
                unsigned mid = pk + ((pkhi - pk) >> 1);
                float pm = unfkey(mid);
                int c2 = 0;
                if (m > pm) {
                    for (int i = 0; i < 8; i++) {
                        int chunk = t + 512 * i;
                        if (chunk == pseudo) continue;
                        const float4* p4 = (const float4*)(ri + 8 * chunk);
                        float4 a = p4[0], c = p4[1];
                        c2 += (KSCALE*a.x > pm) + (KSCALE*a.y > pm) + (KSCALE*a.z > pm) + (KSCALE*a.w > pm)
                            + (KSCALE*c.x > pm) + (KSCALE*c.y > pm) + (KSCALE*c.z > pm) + (KSCALE*c.w > pm);
                    }
                }
                int t2 = blockSumI(c2, si16, t);
                if (t2 >= BGK) { pk = mid; cnt = t2; }
                else pkhi = mid;
            }
            pf = unfkey(pk);
            __syncthreads();
            if (t == 0) sh_cnt = 0;
            __syncthreads();
            if (m > pf) {
                for (int i = 0; i < 8; i++) {
                    int chunk = t + 512 * i;
                    if (chunk == pseudo) continue;
                    const float4* p4 = (const float4*)(ri + 8 * chunk);
                    float4 a = p4[0], c = p4[1];
                    float vv[8] = {KSCALE*a.x, KSCALE*a.y, KSCALE*a.z, KSCALE*a.w,
                                   KSCALE*c.x, KSCALE*c.y, KSCALE*c.z, KSCALE*c.w};
                    for (int j = 0; j < 8; j++) {
                        if (vv[j] > pf) {
                            unsigned k = atomicAdd(&sh_cnt, 1u);
                            if (k < (unsigned)CAP) candv[k] = vv[j];
                        }
                    }
                }
            }
            __syncthreads();
        }
        int nc = (int)min(sh_cnt, (unsigned)CAP);

        float seC = 0.f;
        for (int i = t; i < nc; i += 512) {
            float x = candv[i];
            int r = 0;
            for (int j = 0; j < nc; j++) {
                float w2 = candv[j];
                r += (w2 > x) || (w2 == x && j < i);
            }
            if (r < BGK) seC += __expf(x - M);
        }
        if (t < 8) seC += __expf(sposv[t] - M);
        float sumC = blockSumF(seC, s16, t);

        float seI = 0.f;
#pragma unroll
        for (int i = 0; i < 8; i++) seI += __expf(vcam[i] - Mi);
        float sumI = blockSumF(seI, s16, t);

        if (t == 0) {
            float psum = 0.f;
            for (int k = 0; k < 8; k++) psum += sposv[k];
            g_loss[b]      = Mi + logf(sumI) - sposv[cam];
            g_loss[BN + b] = M  + logf(sumC) - psum * 0.125f;
        }
    } else {
        // ================= lossB: online on sims =================
        const int b = blockIdx.x;
        const float* rsm = g_sims  + (size_t)b * PN;
        const float* rsc = g_score + (size_t)b * PN;

        if (t == 0) { sh_cnt = 0; sh_nf = 3; }

        float bv[8]; int bi[8];
#pragma unroll
        for (int j = 0; j < 8; j++) { bv[j] = NEG_INF; bi[j] = 0x7fffffff; }
        float m = NEG_INF;
#pragma unroll
        for (int i = 0; i < 8; i++) {
            int chunk = t + 512 * i;
            const float4* p4 = (const float4*)(rsm + 8 * chunk);
            float4 a = p4[0], c = p4[1];
            float vv[8] = {a.x, a.y, a.z, a.w, c.x, c.y, c.z, c.w};
#pragma unroll
            for (int j = 0; j < 8; j++) {
                float x = vv[j];
                if (x > bv[j]) { bv[j] = x; bi[j] = 8 * chunk + j; }
                m = fmaxf(m, x);
            }
        }
        tmax[t] = m;

#pragma unroll
        for (int j = 0; j < 8; j++) {
            float x = bv[j]; int idx = bi[j];
            for (int o = 16; o > 0; o >>= 1) {
                float ov = __shfl_down_sync(0xffffffffu, x, o);
                int   oi = __shfl_down_sync(0xffffffffu, idx, o);
                if (ov > x || (ov == x && oi < idx)) { x = ov; idx = oi; }
            }
            if (lane == 0) { s_cv[j][wid] = x; s_ci[j][wid] = idx; }
        }
        __syncthreads();
        if (t == 0) {
            float cv[8]; int ci[8];
            for (int c = 0; c < 8; c++) {
                float bvv = NEG_INF; int bii = 0x7fffffff;
                for (int w2 = 0; w2 < 16; w2++) {
                    float x = s_cv[c][w2]; int idx = s_ci[c][w2];
                    if (x > bvv || (x == bvv && idx < bii)) { bvv = x; bii = idx; }
                }
                cv[c] = bvv; ci[c] = bii;
            }
            bool used[8] = {false,false,false,false,false,false,false,false};
            for (int k = 0; k < PKK; k++) {
                int bc = -1; float bvv = NEG_INF;
                for (int c = 0; c < 8; c++)
                    if (!used[c] && cv[c] > bvv) { bvv = cv[c]; bc = c; }
                used[bc] = true;
                chos[k] = ci[bc];
            }
            fin[0] = chos[0]; fin[1] = chos[1]; fin[2] = chos[2];
        }
        __syncthreads();
        int c0 = chos[0], c1 = chos[1], c2 = chos[2];

        warp0_pivot(tmax, t, BGK + PKK, &sh_pk, &sh_gm);
        float pf = unfkey(sh_pk);

        if (m > pf) {
#pragma unroll
            for (int i = 0; i < 8; i++) {
                int chunk = t + 512 * i;
                const float4* p4 = (const float4*)(rsm + 8 * chunk);
                float4 a = p4[0], c = p4[1];
                float vv[8] = {a.x, a.y, a.z, a.w, c.x, c.y, c.z, c.w};
#pragma unroll
                for (int j = 0; j < 8; j++) {
                    int p = 8 * chunk + j;
                    if (vv[j] > pf && p != c0 && p != c1 && p != c2) {
                        unsigned k = atomicAdd(&sh_cnt, 1u);
                        if (k < (unsigned)CAP) { candv[k] = vv[j]; candi[k] = p; }
                    }
                }
            }
        }
        __syncthreads();
        if (sh_cnt > (unsigned)CAP) {
            unsigned pk = sh_pk, pkhi = fkey(sh_gm);
            int cnt = (int)sh_cnt;
#pragma unroll 1
            while (cnt > CAP && pkhi - pk > 1u) {
                unsigned mid = pk + ((pkhi - pk) >> 1);
                float pm = unfkey(mid);
                int cacc = 0;
                if (m > pm) {
                    for (int i = 0; i < 8; i++) {
                        int chunk = t + 512 * i;
                        const float4* p4 = (const float4*)(rsm + 8 * chunk);
                        float4 a = p4[0], c = p4[1];
                        float vv[8] = {a.x, a.y, a.z, a.w, c.x, c.y, c.z, c.w};
                        for (int j = 0; j < 8; j++) {
                            int p = 8 * chunk + j;
                            cacc += (vv[j] > pm && p != c0 && p != c1 && p != c2);
                        }
                    }
                }
                int t2 = blockSumI(cacc, si16, t);
                if (t2 >= BGK) { pk = mid; cnt = t2; }
                else pkhi = mid;
            }
            pf = unfkey(pk);
            __syncthreads();
            if (t == 0) sh_cnt = 0;
            __syncthreads();
            if (m > pf) {
                for (int i = 0; i < 8; i++) {
                    int chunk = t + 512 * i;
                    const float4* p4 = (const float4*)(rsm + 8 * chunk);
                    float4 a = p4[0], c = p4[1];
                    float vv[8] = {a.x, a.y, a.z, a.w, c.x, c.y, c.z, c.w};
                    for (int j = 0; j < 8; j++) {
                        int p = 8 * chunk + j;
                        if (vv[j] > pf && p != c0 && p != c1 && p != c2) {
                            unsigned k = atomicAdd(&sh_cnt, 1u);
                            if (k < (unsigned)CAP) { candv[k] = vv[j]; candi[k] = p; }
                        }
                    }
                }
            }
            __syncthreads();
        }
        int nc = (int)min(sh_cnt, (unsigned)CAP);

        for (int i = t; i < nc; i += 512) {
            float x = candv[i]; int pi = candi[i];
            int r = 0;
            for (int j = 0; j < nc; j++) {
                float w2 = candv[j];
                r += (w2 > x) || (w2 == x && candi[j] < pi);
            }
            if (r < BGK) {
                unsigned k = atomicAdd(&sh_nf, 1u);
                if (k < 64u) fin[k] = pi;
            }
        }
        __syncthreads();
        int nf = (int)min(sh_nf, 64u);   // 53

        float val = (t < nf) ? KSCALE * rsc[fin[t]] : NEG_INF;
        float mo = blockMaxF(val, s16, t);
        float e  = (t < nf) ? __expf(val - mo) : 0.f;
        float se = blockSumF(e, s16, t);
        if (t == 0) {
            float csum = KSCALE * rsc[c0] + KSCALE * rsc[c1] + KSCALE * rsc[c2];
            g_loss[2 * BN + b] = mo + logf(se) - csum * (1.0f / 3.0f);
        }
    }

    // ============ fused final reduction (last block to finish) ============
    __syncthreads();
    if (t == 0) {
        __threadfence();
        sh_rank = atomicAdd(&g_done, 1u);
    }
    __syncthreads();
    if (sh_rank == 2u * BN - 1u) {
        __threadfence();
        if (t < 256) {
            tmax[t]  = g_loss[t] + g_loss[BN + t] + g_loss[2 * BN + t];
            candi[t] = cams[t];
        }
        __syncthreads();
        if (t < 256) {
            int w2 = t >> 5, l2 = t & 31;
            float acc = 0.f; int n = 0;
            for (int b2 = l2; b2 < BN; b2 += 32) {
                if (candi[b2] == w2) { acc += tmax[b2]; n++; }
            }
            for (int o = 16; o > 0; o >>= 1) {
                acc += __shfl_xor_sync(0xffffffffu, acc, o);
                n   += __shfl_xor_sync(0xffffffffu, n, o);
            }
            if (l2 == 0) s_cv[0][w2] = (n > 0) ? acc / (float)n : 0.f;
        }
        __syncthreads();
        if (t == 0) {
            float tot = 0.f;
            for (int c = 0; c < 8; c++) tot += s_cv[0][c];
            out[0] = tot;
        }
    }
}

// ---------------- launch ----------------
extern "C" void kernel_launch(void* const* d_in, const int* in_sizes, int n_in,
                              void* d_out, int out_size) {
    const float* features        = (const float*)d_in[0];
    const int*   targets         = (const int*)d_in[1];
    const int*   cams            = (const int*)d_in[2];
    const float* global_memory   = (const float*)d_in[4];
    const int*   all_proxy_label = (const int*)d_in[6];
    float* out = (float*)d_out;

    cudaFuncSetAttribute(k_gemm_mma, cudaFuncAttributeMaxDynamicSharedMemorySize, SMEM_GEMM);

    k_prep<<<1024 + BN, 256>>>(features, targets, all_proxy_label, global_memory);
    dim3 gg(PN / 128, 2, 2);
    k_gemm_mma<<<gg, 256, SMEM_GEMM>>>();
    k_loss<<<2 * BN, 512>>>(cams, out);
}